// round 8
// baseline (speedup 1.0000x reference)
#include <cuda_runtime.h>
#include <cuda_fp16.h>

#define B_  16
#define Q_  1000
#define N_  16
#define C_  256
#define H_  100
#define W_  100
#define HW_ 10000
#define NH_ 8
#define D_  32
#define TQ  4          // queries per fused block
#define MP  20         // queries per proj block
#define MB  8          // queries per out block
#define AP2 264        // A_sm row pitch in halves

// ---- fused kernel smem offsets (bytes) ----
#define OFF_A    0
#define SZ_A     (TQ*N_*AP2*2)          // 33792 half A[64][264]
#define OFF_T    (OFF_A + SZ_A)         // 33792 half t[4][8][256]
#define SZ_T     (TQ*NH_*C_*2)          // 16384
#define OFF_PS   (OFF_T + SZ_T)         // 50176 float ps[4][512]
#define SZ_PS    (4*512*4)              // 8192
#define OFF_SC   (OFF_PS + SZ_PS)       // 58368 float sc[4][8][16]
#define SZ_SC    (TQ*NH_*N_*4)          // 2048
#define OFF_AT   (OFF_SC + SZ_SC)       // 60416 float at[4][16][8]
#define SZ_AT    (TQ*N_*NH_*4)          // 2048
#define OFF_U    (OFF_AT + SZ_AT)       // 62464 float u[32]
#define SZ_U     (TQ*NH_*4)             // 128
#define OFF_WT   (OFF_U + SZ_U)         // 62592 float4 wt[64]
#define SZ_WT    (TQ*N_*16)             // 1024
#define OFF_OY   (OFF_WT + SZ_WT)       // 63616 int2 oy[64]
#define SZ_OY    (TQ*N_*8)              // 512
#define OFF_OX   (OFF_OY + SZ_OY)       // 64128 ushort2 ox[64]
#define SZ_OX    (TQ*N_*4)              // 256
#define SMEM_BYTES (OFF_OX + SZ_OX)     // 64384 -> 3 blocks/SM

#define PROJ_SMEM (MP*C_*4*2)           // 40960
#define OUT_SMEM  (MB*NH_*128*8)        // 65536 (float2 m rows)

// device scratch
__device__ __half g_xt[B_ * HW_ * C_];               // channels-last fp16 x
__device__ float2 g_wqP[(C_/2) * C_];                // wq k-pair packed [k2][c]
__device__ float2 g_wvP[(C_/2) * C_];                // wv k-pair packed [k2][c]
__device__ __half g_t[(size_t)B_ * Q_ * NH_ * C_];   // t[b,q,h,k] fp16
__device__ float2 g_m2[(size_t)B_ * Q_ * NH_ * (C_/2)]; // m[b,q,h,k2] packed fp32
__device__ float  g_u[(size_t)B_ * Q_ * NH_];        // u[b,q,h]

// ---- f32x2 helpers ----
__device__ __forceinline__ void fma2(unsigned long long &d,
                                     unsigned long long a, unsigned long long b) {
    asm volatile("fma.rn.f32x2 %0, %1, %2, %0;" : "+l"(d) : "l"(a), "l"(b));
}
__device__ __forceinline__ void lds_v2b64(unsigned int addr,
                                          unsigned long long &a, unsigned long long &b) {
    asm volatile("ld.shared.v2.u64 {%0, %1}, [%2];" : "=l"(a), "=l"(b) : "r"(addr));
}

// ---------------------------------------------------------------------------
// Prologue A: pack wq, wv into k-pair float2 layout [k2][c]
// ---------------------------------------------------------------------------
__global__ void pack_w_kernel(const float* __restrict__ wq,
                              const float* __restrict__ wv) {
    int k2 = blockIdx.x;          // 0..127
    int c  = threadIdx.x;         // 0..255
    float2 a, b;
    a.x = wq[(size_t)c * C_ + 2 * k2];
    a.y = wq[(size_t)c * C_ + 2 * k2 + 1];
    b.x = wv[(size_t)c * C_ + 2 * k2];
    b.y = wv[(size_t)c * C_ + 2 * k2 + 1];
    g_wqP[k2 * C_ + c] = a;
    g_wvP[k2 * C_ + c] = b;
}

// ---------------------------------------------------------------------------
// Prologue B: transpose x [B,C,HW] -> g_xt [B,HW,C] (fp16)
// ---------------------------------------------------------------------------
__global__ void transpose_x_kernel(const float* __restrict__ x) {
    __shared__ float tile[32][33];
    int b  = blockIdx.z;
    int p0 = blockIdx.x * 32;   // HW
    int c0 = blockIdx.y * 32;   // C
    int tx = threadIdx.x, ty = threadIdx.y;   // 32x8
    #pragma unroll
    for (int dy = 0; dy < 32; dy += 8) {
        int c = c0 + ty + dy;
        int p = p0 + tx;
        float v = 0.f;
        if (p < HW_) v = x[(size_t)(b * C_ + c) * HW_ + p];
        tile[ty + dy][tx] = v;
    }
    __syncthreads();
    #pragma unroll
    for (int dy = 0; dy < 32; dy += 8) {
        int p = p0 + ty + dy;
        int c = c0 + tx;
        if (p < HW_)
            g_xt[(size_t)(b * HW_ + p) * C_ + c] = __float2half_rn(tile[tx][ty + dy]);
    }
}

// ---------------------------------------------------------------------------
// Kernel P: projections. 512 threads, MP=20 queries.
// qp phase: k-packed f32x2 (R5-proven pattern). t/u phases scalar fp32.
// ---------------------------------------------------------------------------
__global__ __launch_bounds__(512, 2)
void proj_kernel(const float* __restrict__ q,  const float* __restrict__ bq,
                 const float* __restrict__ wk, const float* __restrict__ bk) {
    extern __shared__ float psm[];
    float* qb = psm;                 // [MP][256]
    float* qp = psm + MP * C_;       // [MP][256]

    const int tid = threadIdx.x;
    const int b   = blockIdx.y;
    const int q0  = blockIdx.x * MP;
    const int lc  = tid & 255;       // channel / k lane
    const int ig  = tid >> 8;        // i-group: 0 or 1
    const int i0  = ig * (MP / 2);   // 10 queries per group

    for (int idx = tid; idx < MP * C_; idx += 512)
        qb[idx] = q[(size_t)(b * Q_ + q0 + idx / C_) * C_ + (idx % C_)];
    __syncthreads();

    unsigned int qb_s = (unsigned int)__cvta_generic_to_shared(qb);

    // ---- qp phase: (c, i-group); k-packed f32x2; 2 FFMA2 per v2 LDS ----
    {
        unsigned long long acc2[MP / 2];
        #pragma unroll
        for (int i = 0; i < MP / 2; i++) acc2[i] = 0ull;
        const unsigned long long* wp = (const unsigned long long*)g_wqP;
        #pragma unroll 2
        for (int k4 = 0; k4 < C_ / 4; k4++) {
            unsigned long long w01 = __ldg(wp + (size_t)(2 * k4) * C_ + lc);
            unsigned long long w23 = __ldg(wp + (size_t)(2 * k4 + 1) * C_ + lc);
            #pragma unroll
            for (int i = 0; i < MP / 2; i++) {
                unsigned long long q01, q23;
                lds_v2b64(qb_s + ((i0 + i) * C_ + k4 * 4) * 4, q01, q23);
                fma2(acc2[i], q01, w01);
                fma2(acc2[i], q23, w23);
            }
        }
        float bb = __ldg(bq + lc);
        #pragma unroll
        for (int i = 0; i < MP / 2; i++) {
            float lo = __uint_as_float((unsigned)acc2[i]);
            float hi = __uint_as_float((unsigned)(acc2[i] >> 32));
            qp[(i0 + i) * C_ + lc] = lo + hi + bb;
        }
    }
    __syncthreads();

    // ---- t phase: (k, i-group); coalesced wk; fp16 out ----
    {
        for (int h = 0; h < NH_; h++) {
            float acc[MP / 2];
            #pragma unroll
            for (int i = 0; i < MP / 2; i++) acc[i] = 0.f;
            #pragma unroll 2
            for (int d4 = 0; d4 < D_ / 4; d4++) {
                const float* wp = wk + (size_t)(h * D_ + d4 * 4) * C_ + lc;
                float w0 = __ldg(wp);
                float w1 = __ldg(wp + C_);
                float w2 = __ldg(wp + 2 * C_);
                float w3 = __ldg(wp + 3 * C_);
                #pragma unroll
                for (int i = 0; i < MP / 2; i++) {
                    float4 qv = *(const float4*)(qp + (i0 + i) * C_ + h * D_ + d4 * 4);
                    acc[i] += qv.x * w0 + qv.y * w1 + qv.z * w2 + qv.w * w3;
                }
            }
            #pragma unroll
            for (int i = 0; i < MP / 2; i++)
                g_t[((size_t)(b * Q_ + q0 + i0 + i) * NH_ + h) * C_ + lc] =
                    __float2half_rn(acc[i]);
        }
    }

    // ---- u phase ----
    if (tid < MP * NH_) {
        int i = tid / NH_, h = tid % NH_;
        float s = 0.f;
        #pragma unroll
        for (int dd = 0; dd < D_; dd++)
            s += qp[i * C_ + h * D_ + dd] * __ldg(bk + h * D_ + dd);
        g_u[(size_t)(b * Q_ + q0 + i) * NH_ + h] = s;
    }
}

// ---------------------------------------------------------------------------
// Kernel F: gather + scores + softmax + m (packed fp32 to global).
// TQ=4, 512 thr, 3 blocks/SM.
// ---------------------------------------------------------------------------
__global__ __launch_bounds__(512, 3)
void deform_attn_kernel(const float* __restrict__ ref) {
    extern __shared__ char smc[];
    __half*  A_sm  = (__half*)(smc + OFF_A);
    __half*  t_sm  = (__half*)(smc + OFF_T);
    float*   ps_sm = (float*)(smc + OFF_PS);
    float*   sc_sm = (float*)(smc + OFF_SC);
    float*   at_sm = (float*)(smc + OFF_AT);
    float*   u_sm  = (float*)(smc + OFF_U);
    float4*  wt_sm = (float4*)(smc + OFF_WT);
    int2*    oy_sm = (int2*)(smc + OFF_OY);
    ushort2* ox_sm = (ushort2*)(smc + OFF_OX);

    const int tid = threadIdx.x;
    const int b   = blockIdx.y;
    const int gq0 = blockIdx.x * TQ;

    // ---- phase 0: ref precompute (64 thr) + t/u load ----
    if (tid < TQ * N_) {
        int i  = tid >> 4, j = tid & 15;
        int rr = (gq0 + i) * N_ + j;
        int n  = rr / Q_;
        int qq = rr - n * Q_;
        float2 g = __ldg((const float2*)(ref + (size_t)((b * Q_ + qq) * N_ + n) * 2));
        float gx = ((g.x + 1.0f) * (float)W_ - 1.0f) * 0.5f;
        float gy = ((g.y + 1.0f) * (float)H_ - 1.0f) * 0.5f;
        float x0f = floorf(gx), y0f = floorf(gy);
        float fx = gx - x0f, fy = gy - y0f;
        int x0 = (int)x0f, y0 = (int)y0f;
        int x1 = x0 + 1,   y1 = y0 + 1;
        bool vx0 = (x0 >= 0) & (x0 < W_);
        bool vx1 = (x1 >= 0) & (x1 < W_);
        bool vy0 = (y0 >= 0) & (y0 < H_);
        bool vy1 = (y1 >= 0) & (y1 < H_);
        float4 w;
        w.x = (vx0 && vy0) ? (1.f - fx) * (1.f - fy) : 0.f;
        w.y = (vx1 && vy0) ? fx * (1.f - fy)         : 0.f;
        w.z = (vx0 && vy1) ? (1.f - fx) * fy         : 0.f;
        w.w = (vx1 && vy1) ? fx * fy                 : 0.f;
        int x0c = min(max(x0, 0), W_ - 1);
        int x1c = min(max(x1, 0), W_ - 1);
        int y0c = min(max(y0, 0), H_ - 1);
        int y1c = min(max(y1, 0), H_ - 1);
        wt_sm[tid] = w;
        oy_sm[tid] = make_int2(y0c * W_ * C_, y1c * W_ * C_);
        ox_sm[tid] = make_ushort2((unsigned short)(x0c * C_),
                                  (unsigned short)(x1c * C_));
    }
    {
        const uint4* ts = (const uint4*)(g_t + (size_t)(b * Q_ + gq0) * NH_ * C_);
        uint4* td = (uint4*)t_sm;
        td[tid] = __ldg(ts + tid);
        td[tid + 512] = __ldg(ts + tid + 512);
    }
    if (tid < TQ * NH_)
        u_sm[tid] = __ldg(g_u + (size_t)(b * Q_ + gq0) * NH_ + tid);
    __syncthreads();

    // ---- gather: thread owns k-pair; 16 rows each ----
    {
        const int k2 = tid & 127;
        const int rg = tid >> 7;
        const __half* xb = g_xt + (size_t)b * HW_ * C_;
        #pragma unroll 4
        for (int row = rg; row < TQ * N_; row += 4) {
            float4  w  = wt_sm[row];
            int2    oy = oy_sm[row];
            ushort2 ox = ox_sm[row];
            float2 v00 = __half22float2(__ldg((const __half2*)(xb + oy.x + ox.x) + k2));
            float2 v01 = __half22float2(__ldg((const __half2*)(xb + oy.x + ox.y) + k2));
            float2 v10 = __half22float2(__ldg((const __half2*)(xb + oy.y + ox.x) + k2));
            float2 v11 = __half22float2(__ldg((const __half2*)(xb + oy.y + ox.y) + k2));
            float rx = w.x * v00.x + w.y * v01.x + w.z * v10.x + w.w * v11.x;
            float ry = w.x * v00.y + w.y * v01.y + w.z * v10.y + w.w * v11.y;
            *(__half2*)(A_sm + row * AP2 + 2 * k2) = __floats2half2_rn(rx, ry);
        }
    }
    __syncthreads();

    // ---- scores: 2x2 tile, 4-way k-split. tid = (kh, i, jp, hp) ----
    {
        const int kh = tid >> 7;            // k quarter (64 k's)
        const int r  = tid & 127;
        const int i  = r >> 5;
        const int jp = (r >> 2) & 7;        // j = 2jp, 2jp+1
        const int hp = r & 3;               // h = 2hp, 2hp+1
        const uint4* a0 = (const uint4*)(A_sm + (i * N_ + 2 * jp) * AP2) + kh * 8;
        const uint4* a1 = (const uint4*)(A_sm + (i * N_ + 2 * jp + 1) * AP2) + kh * 8;
        const uint4* t0 = (const uint4*)(t_sm + (i * NH_ + 2 * hp) * C_) + kh * 8;
        const uint4* t1 = (const uint4*)(t_sm + (i * NH_ + 2 * hp + 1) * C_) + kh * 8;
        float acc00 = 0.f, acc01 = 0.f, acc10 = 0.f, acc11 = 0.f;
        #pragma unroll
        for (int c8 = 0; c8 < 8; c8++) {
            uint4 av0 = a0[c8], av1 = a1[c8], tv0 = t0[c8], tv1 = t1[c8];
            const __half2* ah0 = (const __half2*)&av0;
            const __half2* ah1 = (const __half2*)&av1;
            const __half2* th0 = (const __half2*)&tv0;
            const __half2* th1 = (const __half2*)&tv1;
            #pragma unroll
            for (int p = 0; p < 4; p++) {
                float2 f0 = __half22float2(ah0[p]);
                float2 f1 = __half22float2(ah1[p]);
                float2 g0 = __half22float2(th0[p]);
                float2 g1 = __half22float2(th1[p]);
                acc00 += f0.x * g0.x + f0.y * g0.y;
                acc01 += f0.x * g1.x + f0.y * g1.y;
                acc10 += f1.x * g0.x + f1.y * g0.y;
                acc11 += f1.x * g1.x + f1.y * g1.y;
            }
        }
        float* ps = ps_sm + kh * 512 + i * 128;
        ps[(2 * jp) * 8 + 2 * hp]         = acc00;
        ps[(2 * jp) * 8 + 2 * hp + 1]     = acc01;
        ps[(2 * jp + 1) * 8 + 2 * hp]     = acc10;
        ps[(2 * jp + 1) * 8 + 2 * hp + 1] = acc11;
    }
    __syncthreads();

    // ---- reduce partials -> sc ----
    {
        const int i = tid >> 7;
        const int j = (tid >> 3) & 15;
        const int h = tid & 7;
        const int idx = i * 128 + j * 8 + h;
        float s = ps_sm[idx] + ps_sm[512 + idx] + ps_sm[1024 + idx] + ps_sm[1536 + idx];
        const float scale = 0.17677669529663687f; // 1/sqrt(32)
        sc_sm[(i * NH_ + h) * N_ + j] = (s + u_sm[i * NH_ + h]) * scale;
    }
    __syncthreads();

    // ---- softmax over j per (i,h): 32 threads; attn transposed fp32 ----
    if (tid < TQ * NH_) {
        int i = tid >> 3, h = tid & 7;
        float s[N_];
        float mx = -1e30f;
        #pragma unroll
        for (int j = 0; j < N_; j++) {
            s[j] = sc_sm[(i * NH_ + h) * N_ + j];
            mx = fmaxf(mx, s[j]);
        }
        float sum = 0.f;
        #pragma unroll
        for (int j = 0; j < N_; j++) { s[j] = expf(s[j] - mx); sum += s[j]; }
        float inv = 1.f / sum;
        #pragma unroll
        for (int j = 0; j < N_; j++)
            at_sm[(i * N_ + j) * NH_ + h] = s[j] * inv;
    }
    __syncthreads();

    // ---- m[i][h][k] = sum_j attn*A : thread owns (k-pair, i); packed fp32 out ----
    {
        const int k2 = tid & 127;
        const int i  = tid >> 7;
        float accx[NH_], accy[NH_];
        #pragma unroll
        for (int h = 0; h < NH_; h++) { accx[h] = 0.f; accy[h] = 0.f; }
        #pragma unroll
        for (int j = 0; j < N_; j++) {
            float2 a = __half22float2(*(const __half2*)(A_sm + (i * N_ + j) * AP2 + 2 * k2));
            float4 p0 = *(const float4*)(at_sm + (i * N_ + j) * NH_);
            float4 p1 = *(const float4*)(at_sm + (i * N_ + j) * NH_ + 4);
            accx[0] += a.x * p0.x; accy[0] += a.y * p0.x;
            accx[1] += a.x * p0.y; accy[1] += a.y * p0.y;
            accx[2] += a.x * p0.z; accy[2] += a.y * p0.z;
            accx[3] += a.x * p0.w; accy[3] += a.y * p0.w;
            accx[4] += a.x * p1.x; accy[4] += a.y * p1.x;
            accx[5] += a.x * p1.y; accy[5] += a.y * p1.y;
            accx[6] += a.x * p1.z; accy[6] += a.y * p1.z;
            accx[7] += a.x * p1.w; accy[7] += a.y * p1.w;
        }
        float2* mb = g_m2 + (size_t)(b * Q_ + gq0 + i) * NH_ * (C_ / 2);
        #pragma unroll
        for (int h = 0; h < NH_; h++)
            mb[h * (C_ / 2) + k2] = make_float2(accx[h], accy[h]);
    }
}

// ---------------------------------------------------------------------------
// Kernel O: out[r][c] = sum_k m[r][h(c)][k] * wv[c][k] + bv[c].
// k-packed f32x2. MB=8 queries/block, 512 threads, 2 blocks/SM.
// ---------------------------------------------------------------------------
__global__ __launch_bounds__(512, 2)
void out_kernel(const float* __restrict__ bv, float* __restrict__ out) {
    extern __shared__ char osm[];
    float2* m_sm = (float2*)osm;     // [MB][8][128] k-pairs

    const int tid = threadIdx.x;
    const int r0  = blockIdx.x * MB;

    // load m: MB*8*128 float2 = 4096 uint4
    {
        const uint4* ms = (const uint4*)(g_m2 + (size_t)r0 * NH_ * (C_ / 2));
        uint4* md = (uint4*)m_sm;
        #pragma unroll
        for (int rep = 0; rep < 8; rep++)
            md[tid + rep * 512] = __ldg(ms + tid + rep * 512);
    }
    __syncthreads();

    const int c  = tid & 255;
    const int ig = tid >> 8;            // 2 groups of 4 queries
    const int h  = c >> 5;
    unsigned int m_s = (unsigned int)__cvta_generic_to_shared(m_sm);

    unsigned long long acc2[MB / 2];
    #pragma unroll
    for (int ii = 0; ii < MB / 2; ii++) acc2[ii] = 0ull;

    const unsigned long long* wp = (const unsigned long long*)g_wvP;
    #pragma unroll 2
    for (int k2 = 0; k2 < C_ / 2; k2 += 2) {
        unsigned long long w0 = __ldg(wp + (size_t)k2 * C_ + c);
        unsigned long long w1 = __ldg(wp + (size_t)(k2 + 1) * C_ + c);
        #pragma unroll
        for (int ii = 0; ii < MB / 2; ii++) {
            int i = ig * (MB / 2) + ii;
            unsigned long long m0, m1;
            lds_v2b64(m_s + ((i * NH_ + h) * (C_ / 2) + k2) * 8, m0, m1);
            fma2(acc2[ii], m0, w0);
            fma2(acc2[ii], m1, w1);
        }
    }
    float bb = __ldg(bv + c);
    #pragma unroll
    for (int ii = 0; ii < MB / 2; ii++) {
        int i = ig * (MB / 2) + ii;
        float lo = __uint_as_float((unsigned)acc2[ii]);
        float hi = __uint_as_float((unsigned)(acc2[ii] >> 32));
        out[(size_t)(r0 + i) * C_ + c] = lo + hi + bb;
    }
}

// ---------------------------------------------------------------------------
extern "C" void kernel_launch(void* const* d_in, const int* in_sizes, int n_in,
                              void* d_out, int out_size) {
    const float* x   = (const float*)d_in[0];
    const float* q   = (const float*)d_in[1];
    const float* ref = (const float*)d_in[2];
    const float* wq  = (const float*)d_in[3];
    const float* bq  = (const float*)d_in[4];
    const float* wk  = (const float*)d_in[5];
    const float* bk  = (const float*)d_in[6];
    const float* wv  = (const float*)d_in[7];
    const float* bv  = (const float*)d_in[8];
    float* out = (float*)d_out;

    (void)in_sizes; (void)n_in; (void)out_size;

    pack_w_kernel<<<C_ / 2, C_>>>(wq, wv);

    dim3 tg((HW_ + 31) / 32, C_ / 32, B_);
    transpose_x_kernel<<<tg, dim3(32, 8)>>>(x);

    cudaFuncSetAttribute(proj_kernel,
                         cudaFuncAttributeMaxDynamicSharedMemorySize, PROJ_SMEM);
    proj_kernel<<<dim3(Q_ / MP, B_), 512, PROJ_SMEM>>>(q, bq, wk, bk);

    cudaFuncSetAttribute(deform_attn_kernel,
                         cudaFuncAttributeMaxDynamicSharedMemorySize, SMEM_BYTES);
    deform_attn_kernel<<<dim3(Q_ / TQ, B_), 512, SMEM_BYTES>>>(ref);

    cudaFuncSetAttribute(out_kernel,
                         cudaFuncAttributeMaxDynamicSharedMemorySize, OUT_SMEM);
    out_kernel<<<(B_ * Q_) / MB, 512, OUT_SMEM>>>(bv, out);
}

// round 9
// speedup vs baseline: 1.0502x; 1.0502x over previous
#include <cuda_runtime.h>
#include <cuda_fp16.h>

#define B_  16
#define Q_  1000
#define N_  16
#define C_  256
#define H_  100
#define W_  100
#define HW_ 10000
#define NH_ 8
#define D_  32
#define TQ  4          // queries per fused block
#define MP  20         // queries per proj block
#define MB  16         // queries per out block
#define AP2 264        // A_sm row pitch in halves

// ---- fused kernel smem offsets (bytes) ----
#define OFF_A    0
#define SZ_A     (TQ*N_*AP2*2)          // 33792 half A[64][264]
#define OFF_T    (OFF_A + SZ_A)         // 33792 half t[4][8][256]
#define SZ_T     (TQ*NH_*C_*2)          // 16384
#define OFF_PS   (OFF_T + SZ_T)         // 50176 float ps[4][512]
#define SZ_PS    (4*512*4)              // 8192
#define OFF_SC   (OFF_PS + SZ_PS)       // 58368 float sc[4][8][16]
#define SZ_SC    (TQ*NH_*N_*4)          // 2048
#define OFF_AT   (OFF_SC + SZ_SC)       // 60416 float at[4][16][8]
#define SZ_AT    (TQ*N_*NH_*4)          // 2048
#define OFF_U    (OFF_AT + SZ_AT)       // 62464 float u[32]
#define SZ_U     (TQ*NH_*4)             // 128
#define OFF_WT   (OFF_U + SZ_U)         // 62592 float4 wt[64]
#define SZ_WT    (TQ*N_*16)             // 1024
#define OFF_OY   (OFF_WT + SZ_WT)       // 63616 int2 oy[64]
#define SZ_OY    (TQ*N_*8)              // 512
#define OFF_OX   (OFF_OY + SZ_OY)       // 64128 ushort2 ox[64]
#define SZ_OX    (TQ*N_*4)              // 256
#define SMEM_BYTES (OFF_OX + SZ_OX)     // 64384 -> 3 blocks/SM

#define PROJ_SMEM (MP*C_*4*2)           // 40960
#define OUT_SMEM  (MB*NH_*C_*2)         // 65536 (fp16 m rows)

// device scratch
__device__ __half g_xt[B_ * HW_ * C_];               // channels-last fp16 x
__device__ float2 g_wqP[(C_/2) * C_];                // wq k-pair packed [k2][c]
__device__ float  g_wvT[C_ * C_];                    // wv transposed [k][c]
__device__ __half g_t[(size_t)B_ * Q_ * NH_ * C_];   // t[b,q,h,k] fp16
__device__ __half g_m[(size_t)B_ * Q_ * NH_ * C_];   // m[b,q,h,k] fp16
__device__ float  g_u[(size_t)B_ * Q_ * NH_];        // u[b,q,h]

// ---- f32x2 helpers ----
__device__ __forceinline__ void fma2(unsigned long long &d,
                                     unsigned long long a, unsigned long long b) {
    asm volatile("fma.rn.f32x2 %0, %1, %2, %0;" : "+l"(d) : "l"(a), "l"(b));
}
__device__ __forceinline__ void lds_v2b64(unsigned int addr,
                                          unsigned long long &a, unsigned long long &b) {
    asm volatile("ld.shared.v2.u64 {%0, %1}, [%2];" : "=l"(a), "=l"(b) : "r"(addr));
}

// ---------------------------------------------------------------------------
// Prologue A: pack wq -> [k2][c] float2 ; transpose wv -> [k][c]
// ---------------------------------------------------------------------------
__global__ void pack_w_kernel(const float* __restrict__ wq,
                              const float* __restrict__ wv) {
    int k2 = blockIdx.x;          // 0..127
    int c  = threadIdx.x;         // 0..255
    float2 a;
    a.x = wq[(size_t)c * C_ + 2 * k2];
    a.y = wq[(size_t)c * C_ + 2 * k2 + 1];
    g_wqP[k2 * C_ + c] = a;
    g_wvT[(size_t)(2 * k2) * C_ + c]     = wv[(size_t)c * C_ + 2 * k2];
    g_wvT[(size_t)(2 * k2 + 1) * C_ + c] = wv[(size_t)c * C_ + 2 * k2 + 1];
}

// ---------------------------------------------------------------------------
// Prologue B: transpose x [B,C,HW] -> g_xt [B,HW,C] (fp16)
// ---------------------------------------------------------------------------
__global__ void transpose_x_kernel(const float* __restrict__ x) {
    __shared__ float tile[32][33];
    int b  = blockIdx.z;
    int p0 = blockIdx.x * 32;   // HW
    int c0 = blockIdx.y * 32;   // C
    int tx = threadIdx.x, ty = threadIdx.y;   // 32x8
    #pragma unroll
    for (int dy = 0; dy < 32; dy += 8) {
        int c = c0 + ty + dy;
        int p = p0 + tx;
        float v = 0.f;
        if (p < HW_) v = x[(size_t)(b * C_ + c) * HW_ + p];
        tile[ty + dy][tx] = v;
    }
    __syncthreads();
    #pragma unroll
    for (int dy = 0; dy < 32; dy += 8) {
        int p = p0 + ty + dy;
        int c = c0 + tx;
        if (p < HW_)
            g_xt[(size_t)(b * HW_ + p) * C_ + c] = __float2half_rn(tile[tx][ty + dy]);
    }
}

// ---------------------------------------------------------------------------
// Kernel P: projections. 512 threads, MP=20 queries.
// qp phase: k-packed f32x2. t/u phases scalar fp32 (proven pattern).
// ---------------------------------------------------------------------------
__global__ __launch_bounds__(512, 2)
void proj_kernel(const float* __restrict__ q,  const float* __restrict__ bq,
                 const float* __restrict__ wk, const float* __restrict__ bk) {
    extern __shared__ float psm[];
    float* qb = psm;                 // [MP][256]
    float* qp = psm + MP * C_;       // [MP][256]

    const int tid = threadIdx.x;
    const int b   = blockIdx.y;
    const int q0  = blockIdx.x * MP;
    const int lc  = tid & 255;       // channel / k lane
    const int ig  = tid >> 8;        // i-group: 0 or 1
    const int i0  = ig * (MP / 2);   // 10 queries per group

    for (int idx = tid; idx < MP * C_; idx += 512)
        qb[idx] = q[(size_t)(b * Q_ + q0 + idx / C_) * C_ + (idx % C_)];
    __syncthreads();

    unsigned int qb_s = (unsigned int)__cvta_generic_to_shared(qb);

    // ---- qp phase: (c, i-group); k-packed f32x2; 2 FFMA2 per v2 LDS ----
    {
        unsigned long long acc2[MP / 2];
        #pragma unroll
        for (int i = 0; i < MP / 2; i++) acc2[i] = 0ull;
        const unsigned long long* wp = (const unsigned long long*)g_wqP;
        #pragma unroll 2
        for (int k4 = 0; k4 < C_ / 4; k4++) {
            unsigned long long w01 = __ldg(wp + (size_t)(2 * k4) * C_ + lc);
            unsigned long long w23 = __ldg(wp + (size_t)(2 * k4 + 1) * C_ + lc);
            #pragma unroll
            for (int i = 0; i < MP / 2; i++) {
                unsigned long long q01, q23;
                lds_v2b64(qb_s + ((i0 + i) * C_ + k4 * 4) * 4, q01, q23);
                fma2(acc2[i], q01, w01);
                fma2(acc2[i], q23, w23);
            }
        }
        float bb = __ldg(bq + lc);
        #pragma unroll
        for (int i = 0; i < MP / 2; i++) {
            float lo = __uint_as_float((unsigned)acc2[i]);
            float hi = __uint_as_float((unsigned)(acc2[i] >> 32));
            qp[(i0 + i) * C_ + lc] = lo + hi + bb;
        }
    }
    __syncthreads();

    // ---- t phase: (k, i-group); coalesced wk; fp16 out ----
    {
        for (int h = 0; h < NH_; h++) {
            float acc[MP / 2];
            #pragma unroll
            for (int i = 0; i < MP / 2; i++) acc[i] = 0.f;
            #pragma unroll 2
            for (int d4 = 0; d4 < D_ / 4; d4++) {
                const float* wp = wk + (size_t)(h * D_ + d4 * 4) * C_ + lc;
                float w0 = __ldg(wp);
                float w1 = __ldg(wp + C_);
                float w2 = __ldg(wp + 2 * C_);
                float w3 = __ldg(wp + 3 * C_);
                #pragma unroll
                for (int i = 0; i < MP / 2; i++) {
                    float4 qv = *(const float4*)(qp + (i0 + i) * C_ + h * D_ + d4 * 4);
                    acc[i] += qv.x * w0 + qv.y * w1 + qv.z * w2 + qv.w * w3;
                }
            }
            #pragma unroll
            for (int i = 0; i < MP / 2; i++)
                g_t[((size_t)(b * Q_ + q0 + i0 + i) * NH_ + h) * C_ + lc] =
                    __float2half_rn(acc[i]);
        }
    }

    // ---- u phase ----
    if (tid < MP * NH_) {
        int i = tid / NH_, h = tid % NH_;
        float s = 0.f;
        #pragma unroll
        for (int dd = 0; dd < D_; dd++)
            s += qp[i * C_ + h * D_ + dd] * __ldg(bk + h * D_ + dd);
        g_u[(size_t)(b * Q_ + q0 + i) * NH_ + h] = s;
    }
}

// ---------------------------------------------------------------------------
// Kernel F: gather + scores + softmax + m (fp16 to global).
// TQ=4, 512 thr, 3 blocks/SM. (R7 proven version.)
// ---------------------------------------------------------------------------
__global__ __launch_bounds__(512, 3)
void deform_attn_kernel(const float* __restrict__ ref) {
    extern __shared__ char smc[];
    __half*  A_sm  = (__half*)(smc + OFF_A);
    __half*  t_sm  = (__half*)(smc + OFF_T);
    float*   ps_sm = (float*)(smc + OFF_PS);
    float*   sc_sm = (float*)(smc + OFF_SC);
    float*   at_sm = (float*)(smc + OFF_AT);
    float*   u_sm  = (float*)(smc + OFF_U);
    float4*  wt_sm = (float4*)(smc + OFF_WT);
    int2*    oy_sm = (int2*)(smc + OFF_OY);
    ushort2* ox_sm = (ushort2*)(smc + OFF_OX);

    const int tid = threadIdx.x;
    const int b   = blockIdx.y;
    const int gq0 = blockIdx.x * TQ;

    // ---- phase 0: ref precompute (64 thr) + t/u load ----
    if (tid < TQ * N_) {
        int i  = tid >> 4, j = tid & 15;
        int rr = (gq0 + i) * N_ + j;
        int n  = rr / Q_;
        int qq = rr - n * Q_;
        float2 g = __ldg((const float2*)(ref + (size_t)((b * Q_ + qq) * N_ + n) * 2));
        float gx = ((g.x + 1.0f) * (float)W_ - 1.0f) * 0.5f;
        float gy = ((g.y + 1.0f) * (float)H_ - 1.0f) * 0.5f;
        float x0f = floorf(gx), y0f = floorf(gy);
        float fx = gx - x0f, fy = gy - y0f;
        int x0 = (int)x0f, y0 = (int)y0f;
        int x1 = x0 + 1,   y1 = y0 + 1;
        bool vx0 = (x0 >= 0) & (x0 < W_);
        bool vx1 = (x1 >= 0) & (x1 < W_);
        bool vy0 = (y0 >= 0) & (y0 < H_);
        bool vy1 = (y1 >= 0) & (y1 < H_);
        float4 w;
        w.x = (vx0 && vy0) ? (1.f - fx) * (1.f - fy) : 0.f;
        w.y = (vx1 && vy0) ? fx * (1.f - fy)         : 0.f;
        w.z = (vx0 && vy1) ? (1.f - fx) * fy         : 0.f;
        w.w = (vx1 && vy1) ? fx * fy                 : 0.f;
        int x0c = min(max(x0, 0), W_ - 1);
        int x1c = min(max(x1, 0), W_ - 1);
        int y0c = min(max(y0, 0), H_ - 1);
        int y1c = min(max(y1, 0), H_ - 1);
        wt_sm[tid] = w;
        oy_sm[tid] = make_int2(y0c * W_ * C_, y1c * W_ * C_);
        ox_sm[tid] = make_ushort2((unsigned short)(x0c * C_),
                                  (unsigned short)(x1c * C_));
    }
    {
        const uint4* ts = (const uint4*)(g_t + (size_t)(b * Q_ + gq0) * NH_ * C_);
        uint4* td = (uint4*)t_sm;
        td[tid] = __ldg(ts + tid);
        td[tid + 512] = __ldg(ts + tid + 512);
    }
    if (tid < TQ * NH_)
        u_sm[tid] = __ldg(g_u + (size_t)(b * Q_ + gq0) * NH_ + tid);
    __syncthreads();

    // ---- gather: thread owns k-pair; 16 rows each ----
    {
        const int k2 = tid & 127;
        const int rg = tid >> 7;
        const __half* xb = g_xt + (size_t)b * HW_ * C_;
        #pragma unroll 4
        for (int row = rg; row < TQ * N_; row += 4) {
            float4  w  = wt_sm[row];
            int2    oy = oy_sm[row];
            ushort2 ox = ox_sm[row];
            float2 v00 = __half22float2(__ldg((const __half2*)(xb + oy.x + ox.x) + k2));
            float2 v01 = __half22float2(__ldg((const __half2*)(xb + oy.x + ox.y) + k2));
            float2 v10 = __half22float2(__ldg((const __half2*)(xb + oy.y + ox.x) + k2));
            float2 v11 = __half22float2(__ldg((const __half2*)(xb + oy.y + ox.y) + k2));
            float rx = w.x * v00.x + w.y * v01.x + w.z * v10.x + w.w * v11.x;
            float ry = w.x * v00.y + w.y * v01.y + w.z * v10.y + w.w * v11.y;
            *(__half2*)(A_sm + row * AP2 + 2 * k2) = __floats2half2_rn(rx, ry);
        }
    }
    __syncthreads();

    // ---- scores: 2x2 tile, 4-way k-split. tid = (kh, i, jp, hp) ----
    {
        const int kh = tid >> 7;            // k quarter (64 k's)
        const int r  = tid & 127;
        const int i  = r >> 5;
        const int jp = (r >> 2) & 7;        // j = 2jp, 2jp+1
        const int hp = r & 3;               // h = 2hp, 2hp+1
        const uint4* a0 = (const uint4*)(A_sm + (i * N_ + 2 * jp) * AP2) + kh * 8;
        const uint4* a1 = (const uint4*)(A_sm + (i * N_ + 2 * jp + 1) * AP2) + kh * 8;
        const uint4* t0 = (const uint4*)(t_sm + (i * NH_ + 2 * hp) * C_) + kh * 8;
        const uint4* t1 = (const uint4*)(t_sm + (i * NH_ + 2 * hp + 1) * C_) + kh * 8;
        float acc00 = 0.f, acc01 = 0.f, acc10 = 0.f, acc11 = 0.f;
        #pragma unroll
        for (int c8 = 0; c8 < 8; c8++) {
            uint4 av0 = a0[c8], av1 = a1[c8], tv0 = t0[c8], tv1 = t1[c8];
            const __half2* ah0 = (const __half2*)&av0;
            const __half2* ah1 = (const __half2*)&av1;
            const __half2* th0 = (const __half2*)&tv0;
            const __half2* th1 = (const __half2*)&tv1;
            #pragma unroll
            for (int p = 0; p < 4; p++) {
                float2 f0 = __half22float2(ah0[p]);
                float2 f1 = __half22float2(ah1[p]);
                float2 g0 = __half22float2(th0[p]);
                float2 g1 = __half22float2(th1[p]);
                acc00 += f0.x * g0.x + f0.y * g0.y;
                acc01 += f0.x * g1.x + f0.y * g1.y;
                acc10 += f1.x * g0.x + f1.y * g0.y;
                acc11 += f1.x * g1.x + f1.y * g1.y;
            }
        }
        float* ps = ps_sm + kh * 512 + i * 128;
        ps[(2 * jp) * 8 + 2 * hp]         = acc00;
        ps[(2 * jp) * 8 + 2 * hp + 1]     = acc01;
        ps[(2 * jp + 1) * 8 + 2 * hp]     = acc10;
        ps[(2 * jp + 1) * 8 + 2 * hp + 1] = acc11;
    }
    __syncthreads();

    // ---- reduce partials -> sc ----
    {
        const int i = tid >> 7;
        const int j = (tid >> 3) & 15;
        const int h = tid & 7;
        const int idx = i * 128 + j * 8 + h;
        float s = ps_sm[idx] + ps_sm[512 + idx] + ps_sm[1024 + idx] + ps_sm[1536 + idx];
        const float scale = 0.17677669529663687f; // 1/sqrt(32)
        sc_sm[(i * NH_ + h) * N_ + j] = (s + u_sm[i * NH_ + h]) * scale;
    }
    __syncthreads();

    // ---- softmax over j per (i,h): 32 threads; attn transposed fp32 ----
    if (tid < TQ * NH_) {
        int i = tid >> 3, h = tid & 7;
        float s[N_];
        float mx = -1e30f;
        #pragma unroll
        for (int j = 0; j < N_; j++) {
            s[j] = sc_sm[(i * NH_ + h) * N_ + j];
            mx = fmaxf(mx, s[j]);
        }
        float sum = 0.f;
        #pragma unroll
        for (int j = 0; j < N_; j++) { s[j] = expf(s[j] - mx); sum += s[j]; }
        float inv = 1.f / sum;
        #pragma unroll
        for (int j = 0; j < N_; j++)
            at_sm[(i * N_ + j) * NH_ + h] = s[j] * inv;
    }
    __syncthreads();

    // ---- m[i][h][k] = sum_j attn*A : thread owns (k-pair, i); fp16 out ----
    {
        const int k2 = tid & 127;
        const int i  = tid >> 7;
        float accx[NH_], accy[NH_];
        #pragma unroll
        for (int h = 0; h < NH_; h++) { accx[h] = 0.f; accy[h] = 0.f; }
        #pragma unroll
        for (int j = 0; j < N_; j++) {
            float2 a = __half22float2(*(const __half2*)(A_sm + (i * N_ + j) * AP2 + 2 * k2));
            float4 p0 = *(const float4*)(at_sm + (i * N_ + j) * NH_);
            float4 p1 = *(const float4*)(at_sm + (i * N_ + j) * NH_ + 4);
            accx[0] += a.x * p0.x; accy[0] += a.y * p0.x;
            accx[1] += a.x * p0.y; accy[1] += a.y * p0.y;
            accx[2] += a.x * p0.z; accy[2] += a.y * p0.z;
            accx[3] += a.x * p0.w; accy[3] += a.y * p0.w;
            accx[4] += a.x * p1.x; accy[4] += a.y * p1.x;
            accx[5] += a.x * p1.y; accy[5] += a.y * p1.y;
            accx[6] += a.x * p1.z; accy[6] += a.y * p1.z;
            accx[7] += a.x * p1.w; accy[7] += a.y * p1.w;
        }
        __half* mb = g_m + (size_t)(b * Q_ + gq0 + i) * NH_ * C_;
        #pragma unroll
        for (int h = 0; h < NH_; h++)
            *(__half2*)(mb + h * C_ + 2 * k2) = __floats2half2_rn(accx[h], accy[h]);
    }
}

// ---------------------------------------------------------------------------
// Kernel O: out[r][c] = sum_k m[r][h(c)][k] * wvT[k][c] + bv[c].
// MB=16 queries/block, 512 threads. (R7 proven version.)
// ---------------------------------------------------------------------------
__global__ __launch_bounds__(512, 2)
void out_kernel(const float* __restrict__ bv, float* __restrict__ out) {
    extern __shared__ char osm[];
    __half* m_sm = (__half*)osm;     // [MB][8][256]

    const int tid = threadIdx.x;
    const int r0  = blockIdx.x * MB;

    // load m: MB*8*256 halves = 4096 uint4
    {
        const uint4* ms = (const uint4*)(g_m + (size_t)r0 * NH_ * C_);
        uint4* md = (uint4*)m_sm;
        #pragma unroll
        for (int rep = 0; rep < (MB * NH_ * C_ / 8) / 512; rep++)
            md[tid + rep * 512] = __ldg(ms + tid + rep * 512);
    }
    __syncthreads();

    const int c  = tid & 255;
    const int ig = tid >> 8;            // 2 groups of 8 queries
    const int h  = c >> 5;
    float bb = __ldg(bv + c);
    float acc[MB / 2];
    #pragma unroll
    for (int ii = 0; ii < MB / 2; ii++) acc[ii] = bb;
    #pragma unroll 2
    for (int k4 = 0; k4 < C_ / 4; k4++) {
        const float* wp = g_wvT + (size_t)(k4 * 4) * C_ + c;
        float w0 = __ldg(wp);
        float w1 = __ldg(wp + C_);
        float w2 = __ldg(wp + 2 * C_);
        float w3 = __ldg(wp + 3 * C_);
        #pragma unroll
        for (int ii = 0; ii < MB / 2; ii++) {
            int i = ig * (MB / 2) + ii;
            const __half2* mp = (const __half2*)(m_sm + (i * NH_ + h) * C_ + k4 * 4);
            float2 m01 = __half22float2(mp[0]);
            float2 m23 = __half22float2(mp[1]);
            acc[ii] += m01.x * w0 + m01.y * w1 + m23.x * w2 + m23.y * w3;
        }
    }
    #pragma unroll
    for (int ii = 0; ii < MB / 2; ii++) {
        int i = ig * (MB / 2) + ii;
        out[(size_t)(r0 + i) * C_ + c] = acc[ii];
    }
}

// ---------------------------------------------------------------------------
extern "C" void kernel_launch(void* const* d_in, const int* in_sizes, int n_in,
                              void* d_out, int out_size) {
    const float* x   = (const float*)d_in[0];
    const float* q   = (const float*)d_in[1];
    const float* ref = (const float*)d_in[2];
    const float* wq  = (const float*)d_in[3];
    const float* bq  = (const float*)d_in[4];
    const float* wk  = (const float*)d_in[5];
    const float* bk  = (const float*)d_in[6];
    const float* wv  = (const float*)d_in[7];
    const float* bv  = (const float*)d_in[8];
    float* out = (float*)d_out;

    (void)in_sizes; (void)n_in; (void)out_size;

    pack_w_kernel<<<C_ / 2, C_>>>(wq, wv);

    dim3 tg((HW_ + 31) / 32, C_ / 32, B_);
    transpose_x_kernel<<<tg, dim3(32, 8)>>>(x);

    cudaFuncSetAttribute(proj_kernel,
                         cudaFuncAttributeMaxDynamicSharedMemorySize, PROJ_SMEM);
    proj_kernel<<<dim3(Q_ / MP, B_), 512, PROJ_SMEM>>>(q, bq, wk, bk);

    cudaFuncSetAttribute(deform_attn_kernel,
                         cudaFuncAttributeMaxDynamicSharedMemorySize, SMEM_BYTES);
    deform_attn_kernel<<<dim3(Q_ / TQ, B_), 512, SMEM_BYTES>>>(ref);

    cudaFuncSetAttribute(out_kernel,
                         cudaFuncAttributeMaxDynamicSharedMemorySize, OUT_SMEM);
    out_kernel<<<(B_ * Q_) / MB, 512, OUT_SMEM>>>(bv, out);
}

// round 11
// speedup vs baseline: 1.0523x; 1.0019x over previous
#include <cuda_runtime.h>
#include <cuda_fp16.h>

#define B_  16
#define Q_  1000
#define N_  16
#define C_  256
#define H_  100
#define W_  100
#define HW_ 10000
#define NH_ 8
#define D_  32
#define TQ  4          // queries per fused block
#define MP  20         // queries per proj block
#define MB  16         // queries per out block
#define AP2 264        // A_sm row pitch in halves

// ---- fused kernel smem offsets (bytes) ----
#define OFF_A    0
#define SZ_A     (TQ*N_*AP2*2)          // 33792 half A[64][264]
#define OFF_T    (OFF_A + SZ_A)         // 33792 half t[4][8][256]
#define SZ_T     (TQ*NH_*C_*2)          // 16384
#define OFF_PS   (OFF_T + SZ_T)         // 50176 float ps[4][512]
#define SZ_PS    (4*512*4)              // 8192
#define OFF_SC   (OFF_PS + SZ_PS)       // 58368 float sc[4][8][16]
#define SZ_SC    (TQ*NH_*N_*4)          // 2048
#define OFF_AT   (OFF_SC + SZ_SC)       // 60416 float at[4][16][8]
#define SZ_AT    (TQ*N_*NH_*4)          // 2048
#define OFF_U    (OFF_AT + SZ_AT)       // 62464 float u[32]
#define SZ_U     (TQ*NH_*4)             // 128
#define OFF_WT   (OFF_U + SZ_U)         // 62592 float4 wt[64]
#define SZ_WT    (TQ*N_*16)             // 1024
#define OFF_OY   (OFF_WT + SZ_WT)       // 63616 int2 oy[64]
#define SZ_OY    (TQ*N_*8)              // 512
#define OFF_OX   (OFF_OY + SZ_OY)       // 64128 ushort2 ox[64]
#define SZ_OX    (TQ*N_*4)              // 256
#define SMEM_BYTES (OFF_OX + SZ_OX)     // 64384 -> 3 blocks/SM

#define PROJ_SMEM (MP*C_*4*2)           // 40960
#define OUT_SMEM  (MB*NH_*64*8)         // 65536 (fp32 k-pair m, one k-half)

// role-split prologue grid: proj blocks + transpose tile-pair blocks
#define PRJ_BLOCKS ((Q_/MP)*B_)         // 800
#define TRP_PAIRS  157                  // ceil(313/2) tile-pairs along HW
#define TRP_BLOCKS (TRP_PAIRS*8*B_)     // 20096
#define GRID1 (PRJ_BLOCKS + TRP_BLOCKS)

// device scratch
__device__ __half g_xt[B_ * HW_ * C_];               // channels-last fp16 x
__device__ float2 g_wqP[(C_/2) * C_];                // wq k-pair packed [k2][c]
__device__ float2 g_wvP[(C_/2) * C_];                // wv k-pair packed [k2][c]
__device__ __half g_t[(size_t)B_ * Q_ * NH_ * C_];   // t[b,q,h,k] fp16
__device__ __half g_m[(size_t)B_ * Q_ * NH_ * C_];   // m[b,q,h,k] fp16
__device__ float  g_u[(size_t)B_ * Q_ * NH_];        // u[b,q,h]

// ---- f32x2 helpers ----
__device__ __forceinline__ void fma2(unsigned long long &d,
                                     unsigned long long a, unsigned long long b) {
    asm volatile("fma.rn.f32x2 %0, %1, %2, %0;" : "+l"(d) : "l"(a), "l"(b));
}
__device__ __forceinline__ void lds_v2b64(unsigned int addr,
                                          unsigned long long &a, unsigned long long &b) {
    asm volatile("ld.shared.v2.u64 {%0, %1}, [%2];" : "=l"(a), "=l"(b) : "r"(addr));
}

// ---------------------------------------------------------------------------
// Kernel 0: pack wq, wv -> k-pair float2 [k2][c]. MUST precede prologue
// (proj role consumes g_wqP; same-grid ordering is not guaranteed).
// ---------------------------------------------------------------------------
__global__ void pack_w_kernel(const float* __restrict__ wq,
                              const float* __restrict__ wv) {
    int k2 = blockIdx.x;          // 0..127
    int c  = threadIdx.x;         // 0..255
    float2 a, v;
    a.x = wq[(size_t)c * C_ + 2 * k2];
    a.y = wq[(size_t)c * C_ + 2 * k2 + 1];
    v.x = wv[(size_t)c * C_ + 2 * k2];
    v.y = wv[(size_t)c * C_ + 2 * k2 + 1];
    g_wqP[k2 * C_ + c] = a;
    g_wvP[k2 * C_ + c] = v;
}

// ---------------------------------------------------------------------------
// Kernel 1: role-split prologue. Blocks [0,800): projections (R9-proven).
// Blocks [800, 800+20096): x-transpose tile-pairs. 512 threads, 40KB smem.
// ---------------------------------------------------------------------------
__global__ __launch_bounds__(512, 2)
void prologue_kernel(const float* __restrict__ x,
                     const float* __restrict__ q,  const float* __restrict__ bq,
                     const float* __restrict__ wk, const float* __restrict__ bk) {
    extern __shared__ float psm[];
    const int tid = threadIdx.x;
    const int bid = blockIdx.x;

    if (bid >= PRJ_BLOCKS) {
        // =============== TRANSPOSE ROLE: two 32x32 tiles ===============
        int t2  = bid - PRJ_BLOCKS;
        int pp  = t2 % TRP_PAIRS;
        int rem = t2 / TRP_PAIRS;
        int c0  = (rem & 7) * 32;
        int b   = rem >> 3;
        int half = tid >> 8;
        int t   = tid & 255;
        int tx  = t & 31;
        int ty  = t >> 5;              // 0..7
        int p0  = pp * 64 + half * 32;
        float (*tile)[33] = (float(*)[33])(psm + half * 32 * 33);

        #pragma unroll
        for (int dy = 0; dy < 32; dy += 8) {
            int c = c0 + ty + dy;
            int p = p0 + tx;
            float v = 0.f;
            if (p < HW_) v = x[(size_t)(b * C_ + c) * HW_ + p];
            tile[ty + dy][tx] = v;
        }
        __syncthreads();
        #pragma unroll
        for (int dy = 0; dy < 32; dy += 8) {
            int p = p0 + ty + dy;
            int c = c0 + tx;
            if (p < HW_)
                g_xt[(size_t)(b * HW_ + p) * C_ + c] =
                    __float2half_rn(tile[tx][ty + dy]);
        }
        return;
    }

    // =============== PROJ ROLE (R9-proven) ===============
    float* qb = psm;                 // [MP][256]
    float* qp = psm + MP * C_;       // [MP][256]
    const int b   = bid / (Q_ / MP);
    const int q0  = (bid % (Q_ / MP)) * MP;
    const int lc  = tid & 255;       // channel / k lane
    const int ig  = tid >> 8;        // i-group: 0 or 1
    const int i0  = ig * (MP / 2);   // 10 queries per group

    for (int idx = tid; idx < MP * C_; idx += 512)
        qb[idx] = q[(size_t)(b * Q_ + q0 + idx / C_) * C_ + (idx % C_)];
    __syncthreads();

    unsigned int qb_s = (unsigned int)__cvta_generic_to_shared(qb);

    // ---- qp phase: (c, i-group); k-packed f32x2 ----
    {
        unsigned long long acc2[MP / 2];
        #pragma unroll
        for (int i = 0; i < MP / 2; i++) acc2[i] = 0ull;
        const unsigned long long* wp = (const unsigned long long*)g_wqP;
        #pragma unroll 2
        for (int k4 = 0; k4 < C_ / 4; k4++) {
            unsigned long long w01 = __ldg(wp + (size_t)(2 * k4) * C_ + lc);
            unsigned long long w23 = __ldg(wp + (size_t)(2 * k4 + 1) * C_ + lc);
            #pragma unroll
            for (int i = 0; i < MP / 2; i++) {
                unsigned long long q01, q23;
                lds_v2b64(qb_s + ((i0 + i) * C_ + k4 * 4) * 4, q01, q23);
                fma2(acc2[i], q01, w01);
                fma2(acc2[i], q23, w23);
            }
        }
        float bb = __ldg(bq + lc);
        #pragma unroll
        for (int i = 0; i < MP / 2; i++) {
            float lo = __uint_as_float((unsigned)acc2[i]);
            float hi = __uint_as_float((unsigned)(acc2[i] >> 32));
            qp[(i0 + i) * C_ + lc] = lo + hi + bb;
        }
    }
    __syncthreads();

    // ---- t phase: (k, i-group); coalesced wk; fp16 out ----
    {
        for (int h = 0; h < NH_; h++) {
            float acc[MP / 2];
            #pragma unroll
            for (int i = 0; i < MP / 2; i++) acc[i] = 0.f;
            #pragma unroll 2
            for (int d4 = 0; d4 < D_ / 4; d4++) {
                const float* wp = wk + (size_t)(h * D_ + d4 * 4) * C_ + lc;
                float w0 = __ldg(wp);
                float w1 = __ldg(wp + C_);
                float w2 = __ldg(wp + 2 * C_);
                float w3 = __ldg(wp + 3 * C_);
                #pragma unroll
                for (int i = 0; i < MP / 2; i++) {
                    float4 qv = *(const float4*)(qp + (i0 + i) * C_ + h * D_ + d4 * 4);
                    acc[i] += qv.x * w0 + qv.y * w1 + qv.z * w2 + qv.w * w3;
                }
            }
            #pragma unroll
            for (int i = 0; i < MP / 2; i++)
                g_t[((size_t)(b * Q_ + q0 + i0 + i) * NH_ + h) * C_ + lc] =
                    __float2half_rn(acc[i]);
        }
    }

    // ---- u phase ----
    if (tid < MP * NH_) {
        int i = tid / NH_, h = tid % NH_;
        float s = 0.f;
        #pragma unroll
        for (int dd = 0; dd < D_; dd++)
            s += qp[i * C_ + h * D_ + dd] * __ldg(bk + h * D_ + dd);
        g_u[(size_t)(b * Q_ + q0 + i) * NH_ + h] = s;
    }
}

// ---------------------------------------------------------------------------
// Kernel F: gather + scores + softmax + m (fp16 to global).
// TQ=4, 512 thr, 3 blocks/SM. (R7/R9 proven version, unchanged.)
// ---------------------------------------------------------------------------
__global__ __launch_bounds__(512, 3)
void deform_attn_kernel(const float* __restrict__ ref) {
    extern __shared__ char smc[];
    __half*  A_sm  = (__half*)(smc + OFF_A);
    __half*  t_sm  = (__half*)(smc + OFF_T);
    float*   ps_sm = (float*)(smc + OFF_PS);
    float*   sc_sm = (float*)(smc + OFF_SC);
    float*   at_sm = (float*)(smc + OFF_AT);
    float*   u_sm  = (float*)(smc + OFF_U);
    float4*  wt_sm = (float4*)(smc + OFF_WT);
    int2*    oy_sm = (int2*)(smc + OFF_OY);
    ushort2* ox_sm = (ushort2*)(smc + OFF_OX);

    const int tid = threadIdx.x;
    const int b   = blockIdx.y;
    const int gq0 = blockIdx.x * TQ;

    // ---- phase 0: ref precompute (64 thr) + t/u load ----
    if (tid < TQ * N_) {
        int i  = tid >> 4, j = tid & 15;
        int rr = (gq0 + i) * N_ + j;
        int n  = rr / Q_;
        int qq = rr - n * Q_;
        float2 g = __ldg((const float2*)(ref + (size_t)((b * Q_ + qq) * N_ + n) * 2));
        float gx = ((g.x + 1.0f) * (float)W_ - 1.0f) * 0.5f;
        float gy = ((g.y + 1.0f) * (float)H_ - 1.0f) * 0.5f;
        float x0f = floorf(gx), y0f = floorf(gy);
        float fx = gx - x0f, fy = gy - y0f;
        int x0 = (int)x0f, y0 = (int)y0f;
        int x1 = x0 + 1,   y1 = y0 + 1;
        bool vx0 = (x0 >= 0) & (x0 < W_);
        bool vx1 = (x1 >= 0) & (x1 < W_);
        bool vy0 = (y0 >= 0) & (y0 < H_);
        bool vy1 = (y1 >= 0) & (y1 < H_);
        float4 w;
        w.x = (vx0 && vy0) ? (1.f - fx) * (1.f - fy) : 0.f;
        w.y = (vx1 && vy0) ? fx * (1.f - fy)         : 0.f;
        w.z = (vx0 && vy1) ? (1.f - fx) * fy         : 0.f;
        w.w = (vx1 && vy1) ? fx * fy                 : 0.f;
        int x0c = min(max(x0, 0), W_ - 1);
        int x1c = min(max(x1, 0), W_ - 1);
        int y0c = min(max(y0, 0), H_ - 1);
        int y1c = min(max(y1, 0), H_ - 1);
        wt_sm[tid] = w;
        oy_sm[tid] = make_int2(y0c * W_ * C_, y1c * W_ * C_);
        ox_sm[tid] = make_ushort2((unsigned short)(x0c * C_),
                                  (unsigned short)(x1c * C_));
    }
    {
        const uint4* ts = (const uint4*)(g_t + (size_t)(b * Q_ + gq0) * NH_ * C_);
        uint4* td = (uint4*)t_sm;
        td[tid] = __ldg(ts + tid);
        td[tid + 512] = __ldg(ts + tid + 512);
    }
    if (tid < TQ * NH_)
        u_sm[tid] = __ldg(g_u + (size_t)(b * Q_ + gq0) * NH_ + tid);
    __syncthreads();

    // ---- gather: thread owns k-pair; 16 rows each ----
    {
        const int k2 = tid & 127;
        const int rg = tid >> 7;
        const __half* xb = g_xt + (size_t)b * HW_ * C_;
        #pragma unroll 4
        for (int row = rg; row < TQ * N_; row += 4) {
            float4  w  = wt_sm[row];
            int2    oy = oy_sm[row];
            ushort2 ox = ox_sm[row];
            float2 v00 = __half22float2(__ldg((const __half2*)(xb + oy.x + ox.x) + k2));
            float2 v01 = __half22float2(__ldg((const __half2*)(xb + oy.x + ox.y) + k2));
            float2 v10 = __half22float2(__ldg((const __half2*)(xb + oy.y + ox.x) + k2));
            float2 v11 = __half22float2(__ldg((const __half2*)(xb + oy.y + ox.y) + k2));
            float rx = w.x * v00.x + w.y * v01.x + w.z * v10.x + w.w * v11.x;
            float ry = w.x * v00.y + w.y * v01.y + w.z * v10.y + w.w * v11.y;
            *(__half2*)(A_sm + row * AP2 + 2 * k2) = __floats2half2_rn(rx, ry);
        }
    }
    __syncthreads();

    // ---- scores: 2x2 tile, 4-way k-split. tid = (kh, i, jp, hp) ----
    {
        const int kh = tid >> 7;
        const int r  = tid & 127;
        const int i  = r >> 5;
        const int jp = (r >> 2) & 7;
        const int hp = r & 3;
        const uint4* a0 = (const uint4*)(A_sm + (i * N_ + 2 * jp) * AP2) + kh * 8;
        const uint4* a1 = (const uint4*)(A_sm + (i * N_ + 2 * jp + 1) * AP2) + kh * 8;
        const uint4* t0 = (const uint4*)(t_sm + (i * NH_ + 2 * hp) * C_) + kh * 8;
        const uint4* t1 = (const uint4*)(t_sm + (i * NH_ + 2 * hp + 1) * C_) + kh * 8;
        float acc00 = 0.f, acc01 = 0.f, acc10 = 0.f, acc11 = 0.f;
        #pragma unroll
        for (int c8 = 0; c8 < 8; c8++) {
            uint4 av0 = a0[c8], av1 = a1[c8], tv0 = t0[c8], tv1 = t1[c8];
            const __half2* ah0 = (const __half2*)&av0;
            const __half2* ah1 = (const __half2*)&av1;
            const __half2* th0 = (const __half2*)&tv0;
            const __half2* th1 = (const __half2*)&tv1;
            #pragma unroll
            for (int p = 0; p < 4; p++) {
                float2 f0 = __half22float2(ah0[p]);
                float2 f1 = __half22float2(ah1[p]);
                float2 g0 = __half22float2(th0[p]);
                float2 g1 = __half22float2(th1[p]);
                acc00 += f0.x * g0.x + f0.y * g0.y;
                acc01 += f0.x * g1.x + f0.y * g1.y;
                acc10 += f1.x * g0.x + f1.y * g0.y;
                acc11 += f1.x * g1.x + f1.y * g1.y;
            }
        }
        float* ps = ps_sm + kh * 512 + i * 128;
        ps[(2 * jp) * 8 + 2 * hp]         = acc00;
        ps[(2 * jp) * 8 + 2 * hp + 1]     = acc01;
        ps[(2 * jp + 1) * 8 + 2 * hp]     = acc10;
        ps[(2 * jp + 1) * 8 + 2 * hp + 1] = acc11;
    }
    __syncthreads();

    // ---- reduce partials -> sc ----
    {
        const int i = tid >> 7;
        const int j = (tid >> 3) & 15;
        const int h = tid & 7;
        const int idx = i * 128 + j * 8 + h;
        float s = ps_sm[idx] + ps_sm[512 + idx] + ps_sm[1024 + idx] + ps_sm[1536 + idx];
        const float scale = 0.17677669529663687f; // 1/sqrt(32)
        sc_sm[(i * NH_ + h) * N_ + j] = (s + u_sm[i * NH_ + h]) * scale;
    }
    __syncthreads();

    // ---- softmax over j per (i,h): 32 threads; attn transposed fp32 ----
    if (tid < TQ * NH_) {
        int i = tid >> 3, h = tid & 7;
        float s[N_];
        float mx = -1e30f;
        #pragma unroll
        for (int j = 0; j < N_; j++) {
            s[j] = sc_sm[(i * NH_ + h) * N_ + j];
            mx = fmaxf(mx, s[j]);
        }
        float sum = 0.f;
        #pragma unroll
        for (int j = 0; j < N_; j++) { s[j] = expf(s[j] - mx); sum += s[j]; }
        float inv = 1.f / sum;
        #pragma unroll
        for (int j = 0; j < N_; j++)
            at_sm[(i * N_ + j) * NH_ + h] = s[j] * inv;
    }
    __syncthreads();

    // ---- m[i][h][k] = sum_j attn*A : thread owns (k-pair, i); fp16 out ----
    {
        const int k2 = tid & 127;
        const int i  = tid >> 7;
        float accx[NH_], accy[NH_];
        #pragma unroll
        for (int h = 0; h < NH_; h++) { accx[h] = 0.f; accy[h] = 0.f; }
        #pragma unroll
        for (int j = 0; j < N_; j++) {
            float2 a = __half22float2(*(const __half2*)(A_sm + (i * N_ + j) * AP2 + 2 * k2));
            float4 p0 = *(const float4*)(at_sm + (i * N_ + j) * NH_);
            float4 p1 = *(const float4*)(at_sm + (i * N_ + j) * NH_ + 4);
            accx[0] += a.x * p0.x; accy[0] += a.y * p0.x;
            accx[1] += a.x * p0.y; accy[1] += a.y * p0.y;
            accx[2] += a.x * p0.z; accy[2] += a.y * p0.z;
            accx[3] += a.x * p0.w; accy[3] += a.y * p0.w;
            accx[4] += a.x * p1.x; accy[4] += a.y * p1.x;
            accx[5] += a.x * p1.y; accy[5] += a.y * p1.y;
            accx[6] += a.x * p1.z; accy[6] += a.y * p1.z;
            accx[7] += a.x * p1.w; accy[7] += a.y * p1.w;
        }
        __half* mb = g_m + (size_t)(b * Q_ + gq0 + i) * NH_ * C_;
        #pragma unroll
        for (int h = 0; h < NH_; h++)
            *(__half2*)(mb + h * C_ + 2 * k2) = __floats2half2_rn(accx[h], accy[h]);
    }
}

// ---------------------------------------------------------------------------
// Kernel O: out[r][c] = sum_k m[r][h(c)][k] * wv[c][k] + bv[c].
// m staged to fp32 k-pairs in smem (2 k-passes), packed f32x2 accumulation.
// MB=16 queries/block, 512 threads, 2 blocks/SM.
// ---------------------------------------------------------------------------
__global__ __launch_bounds__(512, 2)
void out_kernel(const float* __restrict__ bv, float* __restrict__ out) {
    extern __shared__ char osm[];
    float2* ms = (float2*)osm;   // [MB*NH_][64] fp32 k-pairs (one k-half)

    const int tid = threadIdx.x;
    const int r0  = blockIdx.x * MB;
    const int c   = tid & 255;
    const int ig  = tid >> 8;
    const int h   = c >> 5;

    unsigned int ms_s = (unsigned int)__cvta_generic_to_shared(ms);
    const unsigned long long* wp = (const unsigned long long*)g_wvP;

    unsigned long long acc2[MB / 2];
    #pragma unroll
    for (int ii = 0; ii < MB / 2; ii++) acc2[ii] = 0ull;

    #pragma unroll
    for (int kp = 0; kp < 2; kp++) {
        // ---- stage: convert fp16 m (half k-range) to fp32 pairs in smem ----
        {
            const uint4* msrc = (const uint4*)(g_m + (size_t)r0 * NH_ * C_);
            #pragma unroll
            for (int rep = 0; rep < 4; rep++) {
                int idx  = tid + rep * 512;           // 0..2047
                int rowh = idx >> 4;                  // 0..127
                int seg  = idx & 15;                  // 16B segs of 8 halves
                uint4 v = __ldg(msrc + rowh * 32 + kp * 16 + seg);
                const __half2* hv = (const __half2*)&v;
                float2 p0 = __half22float2(hv[0]);
                float2 p1 = __half22float2(hv[1]);
                float2 p2 = __half22float2(hv[2]);
                float2 p3 = __half22float2(hv[3]);
                float4* dst = (float4*)(ms + rowh * 64 + seg * 4);
                dst[0] = make_float4(p0.x, p0.y, p1.x, p1.y);
                dst[1] = make_float4(p2.x, p2.y, p3.x, p3.y);
            }
        }
        __syncthreads();

        // ---- accumulate: packed f32x2, broadcast m loads ----
        #pragma unroll 4
        for (int k2l = 0; k2l < 64; k2l += 2) {
            unsigned long long w0 = __ldg(wp + (size_t)(kp * 64 + k2l) * C_ + c);
            unsigned long long w1 = __ldg(wp + (size_t)(kp * 64 + k2l + 1) * C_ + c);
            #pragma unroll
            for (int ii = 0; ii < MB / 2; ii++) {
                int i = ig * (MB / 2) + ii;
                unsigned long long m0, m1;
                lds_v2b64(ms_s + ((i * NH_ + h) * 64 + k2l) * 8, m0, m1);
                fma2(acc2[ii], m0, w0);
                fma2(acc2[ii], m1, w1);
            }
        }
        if (kp == 0) __syncthreads();   // before restaging
    }

    float bb = __ldg(bv + c);
    #pragma unroll
    for (int ii = 0; ii < MB / 2; ii++) {
        int i = ig * (MB / 2) + ii;
        float lo = __uint_as_float((unsigned)acc2[ii]);
        float hi = __uint_as_float((unsigned)(acc2[ii] >> 32));
        out[(size_t)(r0 + i) * C_ + c] = lo + hi + bb;
    }
}

// ---------------------------------------------------------------------------
extern "C" void kernel_launch(void* const* d_in, const int* in_sizes, int n_in,
                              void* d_out, int out_size) {
    const float* x   = (const float*)d_in[0];
    const float* q   = (const float*)d_in[1];
    const float* ref = (const float*)d_in[2];
    const float* wq  = (const float*)d_in[3];
    const float* bq  = (const float*)d_in[4];
    const float* wk  = (const float*)d_in[5];
    const float* bk  = (const float*)d_in[6];
    const float* wv  = (const float*)d_in[7];
    const float* bv  = (const float*)d_in[8];
    float* out = (float*)d_out;

    (void)in_sizes; (void)n_in; (void)out_size;

    // pack first: prologue's proj role consumes g_wqP (separate launch = ordered)
    pack_w_kernel<<<C_ / 2, C_>>>(wq, wv);

    cudaFuncSetAttribute(prologue_kernel,
                         cudaFuncAttributeMaxDynamicSharedMemorySize, PROJ_SMEM);
    prologue_kernel<<<GRID1, 512, PROJ_SMEM>>>(x, q, bq, wk, bk);

    cudaFuncSetAttribute(deform_attn_kernel,
                         cudaFuncAttributeMaxDynamicSharedMemorySize, SMEM_BYTES);
    deform_attn_kernel<<<dim3(Q_ / TQ, B_), 512, SMEM_BYTES>>>(ref);

    cudaFuncSetAttribute(out_kernel,
                         cudaFuncAttributeMaxDynamicSharedMemorySize, OUT_SMEM);
    out_kernel<<<(B_ * Q_) / MB, 512, OUT_SMEM>>>(bv, out);
}

// round 12
// speedup vs baseline: 1.2061x; 1.1462x over previous
#include <cuda_runtime.h>
#include <cuda_fp16.h>

#define B_  16
#define Q_  1000
#define N_  16
#define C_  256
#define H_  100
#define W_  100
#define HW_ 10000
#define NH_ 8
#define D_  32
#define TQ  4          // queries per fused block
#define MP  20         // queries per proj block
#define MB  16         // queries per out block
#define AP2 264        // A_sm row pitch in halves

// ---- fused kernel smem offsets (bytes) ----
#define OFF_A    0
#define SZ_A     (TQ*N_*AP2*2)          // 33792 half A[64][264]
#define OFF_T    (OFF_A + SZ_A)         // 33792 half t[4][8][256]
#define SZ_T     (TQ*NH_*C_*2)          // 16384
#define OFF_PS   (OFF_T + SZ_T)         // 50176 float ps[4][512]
#define SZ_PS    (4*512*4)              // 8192
#define OFF_SC   (OFF_PS + SZ_PS)       // 58368 float sc[4][8][16]
#define SZ_SC    (TQ*NH_*N_*4)          // 2048
#define OFF_AT   (OFF_SC + SZ_SC)       // 60416 float at[4][16][8]
#define SZ_AT    (TQ*N_*NH_*4)          // 2048
#define OFF_U    (OFF_AT + SZ_AT)       // 62464 float u[32]
#define SZ_U     (TQ*NH_*4)             // 128
#define OFF_WT   (OFF_U + SZ_U)         // 62592 float4 wt[64]
#define SZ_WT    (TQ*N_*16)             // 1024
#define OFF_OY   (OFF_WT + SZ_WT)       // 63616 int2 oy[64]
#define SZ_OY    (TQ*N_*8)              // 512
#define OFF_OX   (OFF_OY + SZ_OY)       // 64128 ushort2 ox[64]
#define SZ_OX    (TQ*N_*4)              // 256
#define SMEM_BYTES (OFF_OX + SZ_OX)     // 64384 -> 3 blocks/SM

#define PROJ_SMEM (MP*C_*4*2)           // 40960

// out kernel: m staged [MB][2056] halves (pitch 2056 -> conflict-free ldmatrix)
#define MPITCH  2056
#define OUT_SMEM (MB*MPITCH*2)          // 65792

// role-split prologue grid
#define PRJ_BLOCKS ((Q_/MP)*B_)         // 800
#define TRP_PAIRS  157
#define TRP_BLOCKS (TRP_PAIRS*8*B_)     // 20096
#define GRID1 (PRJ_BLOCKS + TRP_BLOCKS)

// device scratch
__device__ __half g_xt[B_ * HW_ * C_];               // channels-last fp16 x
__device__ float2 g_wqP[(C_/2) * C_];                // wq k-pair packed [k2][c]
__device__ uint2  g_wvF[32 * 16 * 32];               // wv B-fragments [nt][kc][lane]
__device__ __half g_t[(size_t)B_ * Q_ * NH_ * C_];   // t[b,q,h,k] fp16
__device__ __half g_m[(size_t)B_ * Q_ * NH_ * C_];   // m[b,q,h,k] fp16
__device__ float  g_u[(size_t)B_ * Q_ * NH_];        // u[b,q,h]

// ---- f32x2 helpers ----
__device__ __forceinline__ void fma2(unsigned long long &d,
                                     unsigned long long a, unsigned long long b) {
    asm volatile("fma.rn.f32x2 %0, %1, %2, %0;" : "+l"(d) : "l"(a), "l"(b));
}
__device__ __forceinline__ void lds_v2b64(unsigned int addr,
                                          unsigned long long &a, unsigned long long &b) {
    asm volatile("ld.shared.v2.u64 {%0, %1}, [%2];" : "=l"(a), "=l"(b) : "r"(addr));
}

// ---------------------------------------------------------------------------
// Kernel 0a: pack wq -> k-pair float2 [k2][c]
// ---------------------------------------------------------------------------
__global__ void pack_wq_kernel(const float* __restrict__ wq) {
    int k2 = blockIdx.x;          // 0..127
    int c  = threadIdx.x;         // 0..255
    float2 a;
    a.x = wq[(size_t)c * C_ + 2 * k2];
    a.y = wq[(size_t)c * C_ + 2 * k2 + 1];
    g_wqP[k2 * C_ + c] = a;
}

// ---------------------------------------------------------------------------
// Kernel 0b: build wv B-fragments for mma.m16n8k16.row.col.
// B[k][n] = wv[c0+n][k]. Per (nt,kc,lane g|t4):
//   b0 = {wv[c0+g][k0+2t4],   wv[c0+g][k0+2t4+1]}
//   b1 = {wv[c0+g][k0+2t4+8], wv[c0+g][k0+2t4+9]}
// grid=32 (nt), block=512 (kc=tid>>5, lane=tid&31)
// ---------------------------------------------------------------------------
__global__ void pack_wvF_kernel(const float* __restrict__ wv) {
    int nt   = blockIdx.x;
    int kc   = threadIdx.x >> 5;
    int lane = threadIdx.x & 31;
    int g  = lane >> 2;
    int t4 = lane & 3;
    int c  = nt * 8 + g;
    int k0 = kc * 16 + 2 * t4;
    const float* wr = wv + (size_t)c * C_;
    __half2 b0 = __floats2half2_rn(wr[k0],     wr[k0 + 1]);
    __half2 b1 = __floats2half2_rn(wr[k0 + 8], wr[k0 + 9]);
    uint2 r;
    r.x = *(unsigned*)&b0;
    r.y = *(unsigned*)&b1;
    g_wvF[(nt * 16 + kc) * 32 + lane] = r;
}

// ---------------------------------------------------------------------------
// Kernel 1: role-split prologue (proj + x-transpose). Unchanged from R11.
// ---------------------------------------------------------------------------
__global__ __launch_bounds__(512, 2)
void prologue_kernel(const float* __restrict__ x,
                     const float* __restrict__ q,  const float* __restrict__ bq,
                     const float* __restrict__ wk, const float* __restrict__ bk) {
    extern __shared__ float psm[];
    const int tid = threadIdx.x;
    const int bid = blockIdx.x;

    if (bid >= PRJ_BLOCKS) {
        // =============== TRANSPOSE ROLE: two 32x32 tiles ===============
        int t2  = bid - PRJ_BLOCKS;
        int pp  = t2 % TRP_PAIRS;
        int rem = t2 / TRP_PAIRS;
        int c0  = (rem & 7) * 32;
        int b   = rem >> 3;
        int half = tid >> 8;
        int t   = tid & 255;
        int tx  = t & 31;
        int ty  = t >> 5;
        int p0  = pp * 64 + half * 32;
        float (*tile)[33] = (float(*)[33])(psm + half * 32 * 33);

        #pragma unroll
        for (int dy = 0; dy < 32; dy += 8) {
            int c = c0 + ty + dy;
            int p = p0 + tx;
            float v = 0.f;
            if (p < HW_) v = x[(size_t)(b * C_ + c) * HW_ + p];
            tile[ty + dy][tx] = v;
        }
        __syncthreads();
        #pragma unroll
        for (int dy = 0; dy < 32; dy += 8) {
            int p = p0 + ty + dy;
            int c = c0 + tx;
            if (p < HW_)
                g_xt[(size_t)(b * HW_ + p) * C_ + c] =
                    __float2half_rn(tile[tx][ty + dy]);
        }
        return;
    }

    // =============== PROJ ROLE ===============
    float* qb = psm;
    float* qp = psm + MP * C_;
    const int b   = bid / (Q_ / MP);
    const int q0  = (bid % (Q_ / MP)) * MP;
    const int lc  = tid & 255;
    const int ig  = tid >> 8;
    const int i0  = ig * (MP / 2);

    for (int idx = tid; idx < MP * C_; idx += 512)
        qb[idx] = q[(size_t)(b * Q_ + q0 + idx / C_) * C_ + (idx % C_)];
    __syncthreads();

    unsigned int qb_s = (unsigned int)__cvta_generic_to_shared(qb);

    // ---- qp phase: k-packed f32x2 ----
    {
        unsigned long long acc2[MP / 2];
        #pragma unroll
        for (int i = 0; i < MP / 2; i++) acc2[i] = 0ull;
        const unsigned long long* wp = (const unsigned long long*)g_wqP;
        #pragma unroll 2
        for (int k4 = 0; k4 < C_ / 4; k4++) {
            unsigned long long w01 = __ldg(wp + (size_t)(2 * k4) * C_ + lc);
            unsigned long long w23 = __ldg(wp + (size_t)(2 * k4 + 1) * C_ + lc);
            #pragma unroll
            for (int i = 0; i < MP / 2; i++) {
                unsigned long long q01, q23;
                lds_v2b64(qb_s + ((i0 + i) * C_ + k4 * 4) * 4, q01, q23);
                fma2(acc2[i], q01, w01);
                fma2(acc2[i], q23, w23);
            }
        }
        float bb = __ldg(bq + lc);
        #pragma unroll
        for (int i = 0; i < MP / 2; i++) {
            float lo = __uint_as_float((unsigned)acc2[i]);
            float hi = __uint_as_float((unsigned)(acc2[i] >> 32));
            qp[(i0 + i) * C_ + lc] = lo + hi + bb;
        }
    }
    __syncthreads();

    // ---- t phase ----
    {
        for (int h = 0; h < NH_; h++) {
            float acc[MP / 2];
            #pragma unroll
            for (int i = 0; i < MP / 2; i++) acc[i] = 0.f;
            #pragma unroll 2
            for (int d4 = 0; d4 < D_ / 4; d4++) {
                const float* wp = wk + (size_t)(h * D_ + d4 * 4) * C_ + lc;
                float w0 = __ldg(wp);
                float w1 = __ldg(wp + C_);
                float w2 = __ldg(wp + 2 * C_);
                float w3 = __ldg(wp + 3 * C_);
                #pragma unroll
                for (int i = 0; i < MP / 2; i++) {
                    float4 qv = *(const float4*)(qp + (i0 + i) * C_ + h * D_ + d4 * 4);
                    acc[i] += qv.x * w0 + qv.y * w1 + qv.z * w2 + qv.w * w3;
                }
            }
            #pragma unroll
            for (int i = 0; i < MP / 2; i++)
                g_t[((size_t)(b * Q_ + q0 + i0 + i) * NH_ + h) * C_ + lc] =
                    __float2half_rn(acc[i]);
        }
    }

    // ---- u phase ----
    if (tid < MP * NH_) {
        int i = tid / NH_, h = tid % NH_;
        float s = 0.f;
        #pragma unroll
        for (int dd = 0; dd < D_; dd++)
            s += qp[i * C_ + h * D_ + dd] * __ldg(bk + h * D_ + dd);
        g_u[(size_t)(b * Q_ + q0 + i) * NH_ + h] = s;
    }
}

// ---------------------------------------------------------------------------
// Kernel F: gather + scores + softmax + m (fp16 to global). Unchanged (R7/R9).
// ---------------------------------------------------------------------------
__global__ __launch_bounds__(512, 3)
void deform_attn_kernel(const float* __restrict__ ref) {
    extern __shared__ char smc[];
    __half*  A_sm  = (__half*)(smc + OFF_A);
    __half*  t_sm  = (__half*)(smc + OFF_T);
    float*   ps_sm = (float*)(smc + OFF_PS);
    float*   sc_sm = (float*)(smc + OFF_SC);
    float*   at_sm = (float*)(smc + OFF_AT);
    float*   u_sm  = (float*)(smc + OFF_U);
    float4*  wt_sm = (float4*)(smc + OFF_WT);
    int2*    oy_sm = (int2*)(smc + OFF_OY);
    ushort2* ox_sm = (ushort2*)(smc + OFF_OX);

    const int tid = threadIdx.x;
    const int b   = blockIdx.y;
    const int gq0 = blockIdx.x * TQ;

    if (tid < TQ * N_) {
        int i  = tid >> 4, j = tid & 15;
        int rr = (gq0 + i) * N_ + j;
        int n  = rr / Q_;
        int qq = rr - n * Q_;
        float2 g = __ldg((const float2*)(ref + (size_t)((b * Q_ + qq) * N_ + n) * 2));
        float gx = ((g.x + 1.0f) * (float)W_ - 1.0f) * 0.5f;
        float gy = ((g.y + 1.0f) * (float)H_ - 1.0f) * 0.5f;
        float x0f = floorf(gx), y0f = floorf(gy);
        float fx = gx - x0f, fy = gy - y0f;
        int x0 = (int)x0f, y0 = (int)y0f;
        int x1 = x0 + 1,   y1 = y0 + 1;
        bool vx0 = (x0 >= 0) & (x0 < W_);
        bool vx1 = (x1 >= 0) & (x1 < W_);
        bool vy0 = (y0 >= 0) & (y0 < H_);
        bool vy1 = (y1 >= 0) & (y1 < H_);
        float4 w;
        w.x = (vx0 && vy0) ? (1.f - fx) * (1.f - fy) : 0.f;
        w.y = (vx1 && vy0) ? fx * (1.f - fy)         : 0.f;
        w.z = (vx0 && vy1) ? (1.f - fx) * fy         : 0.f;
        w.w = (vx1 && vy1) ? fx * fy                 : 0.f;
        int x0c = min(max(x0, 0), W_ - 1);
        int x1c = min(max(x1, 0), W_ - 1);
        int y0c = min(max(y0, 0), H_ - 1);
        int y1c = min(max(y1, 0), H_ - 1);
        wt_sm[tid] = w;
        oy_sm[tid] = make_int2(y0c * W_ * C_, y1c * W_ * C_);
        ox_sm[tid] = make_ushort2((unsigned short)(x0c * C_),
                                  (unsigned short)(x1c * C_));
    }
    {
        const uint4* ts = (const uint4*)(g_t + (size_t)(b * Q_ + gq0) * NH_ * C_);
        uint4* td = (uint4*)t_sm;
        td[tid] = __ldg(ts + tid);
        td[tid + 512] = __ldg(ts + tid + 512);
    }
    if (tid < TQ * NH_)
        u_sm[tid] = __ldg(g_u + (size_t)(b * Q_ + gq0) * NH_ + tid);
    __syncthreads();

    {
        const int k2 = tid & 127;
        const int rg = tid >> 7;
        const __half* xb = g_xt + (size_t)b * HW_ * C_;
        #pragma unroll 4
        for (int row = rg; row < TQ * N_; row += 4) {
            float4  w  = wt_sm[row];
            int2    oy = oy_sm[row];
            ushort2 ox = ox_sm[row];
            float2 v00 = __half22float2(__ldg((const __half2*)(xb + oy.x + ox.x) + k2));
            float2 v01 = __half22float2(__ldg((const __half2*)(xb + oy.x + ox.y) + k2));
            float2 v10 = __half22float2(__ldg((const __half2*)(xb + oy.y + ox.x) + k2));
            float2 v11 = __half22float2(__ldg((const __half2*)(xb + oy.y + ox.y) + k2));
            float rx = w.x * v00.x + w.y * v01.x + w.z * v10.x + w.w * v11.x;
            float ry = w.x * v00.y + w.y * v01.y + w.z * v10.y + w.w * v11.y;
            *(__half2*)(A_sm + row * AP2 + 2 * k2) = __floats2half2_rn(rx, ry);
        }
    }
    __syncthreads();

    {
        const int kh = tid >> 7;
        const int r  = tid & 127;
        const int i  = r >> 5;
        const int jp = (r >> 2) & 7;
        const int hp = r & 3;
        const uint4* a0 = (const uint4*)(A_sm + (i * N_ + 2 * jp) * AP2) + kh * 8;
        const uint4* a1 = (const uint4*)(A_sm + (i * N_ + 2 * jp + 1) * AP2) + kh * 8;
        const uint4* t0 = (const uint4*)(t_sm + (i * NH_ + 2 * hp) * C_) + kh * 8;
        const uint4* t1 = (const uint4*)(t_sm + (i * NH_ + 2 * hp + 1) * C_) + kh * 8;
        float acc00 = 0.f, acc01 = 0.f, acc10 = 0.f, acc11 = 0.f;
        #pragma unroll
        for (int c8 = 0; c8 < 8; c8++) {
            uint4 av0 = a0[c8], av1 = a1[c8], tv0 = t0[c8], tv1 = t1[c8];
            const __half2* ah0 = (const __half2*)&av0;
            const __half2* ah1 = (const __half2*)&av1;
            const __half2* th0 = (const __half2*)&tv0;
            const __half2* th1 = (const __half2*)&tv1;
            #pragma unroll
            for (int p = 0; p < 4; p++) {
                float2 f0 = __half22float2(ah0[p]);
                float2 f1 = __half22float2(ah1[p]);
                float2 g0 = __half22float2(th0[p]);
                float2 g1 = __half22float2(th1[p]);
                acc00 += f0.x * g0.x + f0.y * g0.y;
                acc01 += f0.x * g1.x + f0.y * g1.y;
                acc10 += f1.x * g0.x + f1.y * g0.y;
                acc11 += f1.x * g1.x + f1.y * g1.y;
            }
        }
        float* ps = ps_sm + kh * 512 + i * 128;
        ps[(2 * jp) * 8 + 2 * hp]         = acc00;
        ps[(2 * jp) * 8 + 2 * hp + 1]     = acc01;
        ps[(2 * jp + 1) * 8 + 2 * hp]     = acc10;
        ps[(2 * jp + 1) * 8 + 2 * hp + 1] = acc11;
    }
    __syncthreads();

    {
        const int i = tid >> 7;
        const int j = (tid >> 3) & 15;
        const int h = tid & 7;
        const int idx = i * 128 + j * 8 + h;
        float s = ps_sm[idx] + ps_sm[512 + idx] + ps_sm[1024 + idx] + ps_sm[1536 + idx];
        const float scale = 0.17677669529663687f;
        sc_sm[(i * NH_ + h) * N_ + j] = (s + u_sm[i * NH_ + h]) * scale;
    }
    __syncthreads();

    if (tid < TQ * NH_) {
        int i = tid >> 3, h = tid & 7;
        float s[N_];
        float mx = -1e30f;
        #pragma unroll
        for (int j = 0; j < N_; j++) {
            s[j] = sc_sm[(i * NH_ + h) * N_ + j];
            mx = fmaxf(mx, s[j]);
        }
        float sum = 0.f;
        #pragma unroll
        for (int j = 0; j < N_; j++) { s[j] = expf(s[j] - mx); sum += s[j]; }
        float inv = 1.f / sum;
        #pragma unroll
        for (int j = 0; j < N_; j++)
            at_sm[(i * N_ + j) * NH_ + h] = s[j] * inv;
    }
    __syncthreads();

    {
        const int k2 = tid & 127;
        const int i  = tid >> 7;
        float accx[NH_], accy[NH_];
        #pragma unroll
        for (int h = 0; h < NH_; h++) { accx[h] = 0.f; accy[h] = 0.f; }
        #pragma unroll
        for (int j = 0; j < N_; j++) {
            float2 a = __half22float2(*(const __half2*)(A_sm + (i * N_ + j) * AP2 + 2 * k2));
            float4 p0 = *(const float4*)(at_sm + (i * N_ + j) * NH_);
            float4 p1 = *(const float4*)(at_sm + (i * N_ + j) * NH_ + 4);
            accx[0] += a.x * p0.x; accy[0] += a.y * p0.x;
            accx[1] += a.x * p0.y; accy[1] += a.y * p0.y;
            accx[2] += a.x * p0.z; accy[2] += a.y * p0.z;
            accx[3] += a.x * p0.w; accy[3] += a.y * p0.w;
            accx[4] += a.x * p1.x; accy[4] += a.y * p1.x;
            accx[5] += a.x * p1.y; accy[5] += a.y * p1.y;
            accx[6] += a.x * p1.z; accy[6] += a.y * p1.z;
            accx[7] += a.x * p1.w; accy[7] += a.y * p1.w;
        }
        __half* mb = g_m + (size_t)(b * Q_ + gq0 + i) * NH_ * C_;
        #pragma unroll
        for (int h = 0; h < NH_; h++)
            *(__half2*)(mb + h * C_ + 2 * k2) = __floats2half2_rn(accx[h], accy[h]);
    }
}

// ---------------------------------------------------------------------------
// Kernel O (HMMA): out[r][c] = sum_k m[r][h(c)][k]*wv[c][k] + bv[c].
// 16 rows/block, 512 thr = 16 warps; warp w owns channels 16w..16w+15
// (h = w>>1, n-tiles 2w, 2w+1). mma.m16n8k16 over 16 k-chunks.
// ---------------------------------------------------------------------------
__global__ __launch_bounds__(512, 2)
void out_kernel(const float* __restrict__ bv, float* __restrict__ out) {
    extern __shared__ __half m_sm[];   // [MB][MPITCH]

    const int tid  = threadIdx.x;
    const int r0   = blockIdx.x * MB;
    const int warp = tid >> 5;
    const int lane = tid & 31;

    // ---- stage m: 16 rows x 2048 halves -> pitch-2056 smem ----
    {
        #pragma unroll
        for (int rep = 0; rep < 8; rep++) {
            int idx = tid + rep * 512;          // 0..4095
            int row = idx >> 8;                 // 0..15
            int seg = idx & 255;                // uint4 within row
            uint4 v = __ldg((const uint4*)(g_m + (size_t)(r0 + row) * NH_ * C_) + seg);
            *((uint4*)(m_sm + row * MPITCH) + seg) = v;
        }
    }
    __syncthreads();

    const int h   = warp >> 1;                  // head for this warp's channels
    const int g   = lane >> 2;
    const int t4  = lane & 3;
    // ldmatrix source lane address: i = (lane&7) + ((lane>>3)&1)*8, col8 = ((lane>>4)&1)*8
    const int li   = (lane & 7) + ((lane >> 3) & 1) * 8;
    const int col8 = ((lane >> 4) & 1) * 8;
    unsigned int a_base = (unsigned int)__cvta_generic_to_shared(m_sm)
                        + (li * MPITCH + h * C_ + col8) * 2;

    float d0[2][4];
    #pragma unroll
    for (int nt = 0; nt < 2; nt++)
        #pragma unroll
        for (int e = 0; e < 4; e++) d0[nt][e] = 0.f;

    const uint2* wf = g_wvF + (size_t)(warp * 2) * 16 * 32;  // nt0 = 2*warp

    #pragma unroll
    for (int kc = 0; kc < 16; kc++) {
        unsigned a0, a1, a2, a3;
        asm volatile(
            "ldmatrix.sync.aligned.m8n8.x4.shared.b16 {%0,%1,%2,%3}, [%4];"
            : "=r"(a0), "=r"(a1), "=r"(a2), "=r"(a3)
            : "r"(a_base + kc * 32));
        uint2 b0 = __ldg(wf + kc * 32 + lane);            // nt = 2*warp
        uint2 b1 = __ldg(wf + (16 + kc) * 32 + lane);     // nt = 2*warp+1
        asm volatile(
            "mma.sync.aligned.m16n8k16.row.col.f32.f16.f16.f32 "
            "{%0,%1,%2,%3}, {%4,%5,%6,%7}, {%8,%9}, {%0,%1,%2,%3};"
            : "+f"(d0[0][0]), "+f"(d0[0][1]), "+f"(d0[0][2]), "+f"(d0[0][3])
            : "r"(a0), "r"(a1), "r"(a2), "r"(a3), "r"(b0.x), "r"(b0.y));
        asm volatile(
            "mma.sync.aligned.m16n8k16.row.col.f32.f16.f16.f32 "
            "{%0,%1,%2,%3}, {%4,%5,%6,%7}, {%8,%9}, {%0,%1,%2,%3};"
            : "+f"(d0[1][0]), "+f"(d0[1][1]), "+f"(d0[1][2]), "+f"(d0[1][3])
            : "r"(a0), "r"(a1), "r"(a2), "r"(a3), "r"(b1.x), "r"(b1.y));
    }

    // ---- epilogue: D[g][2t4..] -> out, + bv ----
    #pragma unroll
    for (int nt = 0; nt < 2; nt++) {
        int c = warp * 16 + nt * 8 + 2 * t4;
        float bb0 = __ldg(bv + c);
        float bb1 = __ldg(bv + c + 1);
        float2 lo = make_float2(d0[nt][0] + bb0, d0[nt][1] + bb1);
        float2 hi = make_float2(d0[nt][2] + bb0, d0[nt][3] + bb1);
        *(float2*)(out + (size_t)(r0 + g) * C_ + c)     = lo;
        *(float2*)(out + (size_t)(r0 + g + 8) * C_ + c) = hi;
    }
}

// ---------------------------------------------------------------------------
extern "C" void kernel_launch(void* const* d_in, const int* in_sizes, int n_in,
                              void* d_out, int out_size) {
    const float* x   = (const float*)d_in[0];
    const float* q   = (const float*)d_in[1];
    const float* ref = (const float*)d_in[2];
    const float* wq  = (const float*)d_in[3];
    const float* bq  = (const float*)d_in[4];
    const float* wk  = (const float*)d_in[5];
    const float* bk  = (const float*)d_in[6];
    const float* wv  = (const float*)d_in[7];
    const float* bv  = (const float*)d_in[8];
    float* out = (float*)d_out;

    (void)in_sizes; (void)n_in; (void)out_size;

    pack_wq_kernel<<<C_ / 2, C_>>>(wq);
    pack_wvF_kernel<<<32, 512>>>(wv);

    cudaFuncSetAttribute(prologue_kernel,
                         cudaFuncAttributeMaxDynamicSharedMemorySize, PROJ_SMEM);
    prologue_kernel<<<GRID1, 512, PROJ_SMEM>>>(x, q, bq, wk, bk);

    cudaFuncSetAttribute(deform_attn_kernel,
                         cudaFuncAttributeMaxDynamicSharedMemorySize, SMEM_BYTES);
    deform_attn_kernel<<<dim3(Q_ / TQ, B_), 512, SMEM_BYTES>>>(ref);

    cudaFuncSetAttribute(out_kernel,
                         cudaFuncAttributeMaxDynamicSharedMemorySize, OUT_SMEM);
    out_kernel<<<(B_ * Q_) / MB, 512, OUT_SMEM>>>(bv, out);
}

// round 13
// speedup vs baseline: 1.7599x; 1.4592x over previous
#include <cuda_runtime.h>
#include <cuda_fp16.h>

#define B_  16
#define Q_  1000
#define N_  16
#define C_  256
#define H_  100
#define W_  100
#define HW_ 10000
#define NH_ 8
#define D_  32
#define TQ  4          // queries per fused block
#define MB  16         // rows per out/proj block
#define AP2 264        // A_sm row pitch in halves

// ---- fused kernel smem offsets (bytes) ----
#define OFF_A    0
#define SZ_A     (TQ*N_*AP2*2)          // 33792 half A[64][264]
#define OFF_T    (OFF_A + SZ_A)         // 33792 half t[4][8][256]
#define SZ_T     (TQ*NH_*C_*2)          // 16384
#define OFF_PS   (OFF_T + SZ_T)         // 50176 float ps[4][512]
#define SZ_PS    (4*512*4)              // 8192
#define OFF_SC   (OFF_PS + SZ_PS)       // 58368 float sc[4][8][16]
#define SZ_SC    (TQ*NH_*N_*4)          // 2048
#define OFF_AT   (OFF_SC + SZ_SC)       // 60416 float at[4][16][8]
#define SZ_AT    (TQ*N_*NH_*4)          // 2048
#define OFF_U    (OFF_AT + SZ_AT)       // 62464 float u[32]
#define SZ_U     (TQ*NH_*4)             // 128
#define OFF_WT   (OFF_U + SZ_U)         // 62592 float4 wt[64]
#define SZ_WT    (TQ*N_*16)             // 1024
#define OFF_OY   (OFF_WT + SZ_WT)       // 63616 int2 oy[64]
#define SZ_OY    (TQ*N_*8)              // 512
#define OFF_OX   (OFF_OY + SZ_OY)       // 64128 ushort2 ox[64]
#define SZ_OX    (TQ*N_*4)              // 256
#define SMEM_BYTES (OFF_OX + SZ_OX)     // 64384 -> 3 blocks/SM

// out kernel: m staged [MB][2056] halves
#define MPITCH  2056
#define OUT_SMEM (MB*MPITCH*2)          // 65792

// proj role smem: q fp16 [16][264] + qp fp16 [16][264]
#define QPITCH  264
#define PROJ_SMEM (2*MB*QPITCH*2)       // 16896

// role-split prologue grid: 1000 proj blocks + transpose tile-pairs
#define PRJ_BLOCKS ((B_*Q_)/MB)         // 1000
#define TRP_PAIRS  157
#define TRP_BLOCKS (TRP_PAIRS*8*B_)     // 20096
#define GRID1 (PRJ_BLOCKS + TRP_BLOCKS)

// device scratch
__device__ __half g_xt[B_ * HW_ * C_];               // channels-last fp16 x
__device__ uint2  g_wqF[32 * 16 * 32];               // wq B-frags [nt][kc][lane]
__device__ uint2  g_wvF[32 * 16 * 32];               // wv B-frags [nt][kc][lane]
__device__ uint2  g_wkF[NH_ * 32 * 2 * 32];          // wk B-frags [h][nt][kc2][lane]
__device__ __half g_t[(size_t)B_ * Q_ * NH_ * C_];   // t[r,h,k] fp16
__device__ __half g_m[(size_t)B_ * Q_ * NH_ * C_];   // m[r,h,k] fp16
__device__ float  g_u[(size_t)B_ * Q_ * NH_];        // u[r,h]

// ---------------------------------------------------------------------------
// Kernel 0a: build B-fragments for qp / out GEMMs (B[k][n] = w[c0+n][k]).
// grid.x=32 (nt), grid.y=2 (0: wq, 1: wv), block 512 (kc=tid>>5, lane)
// ---------------------------------------------------------------------------
__global__ void pack_wF_kernel(const float* __restrict__ wq,
                               const float* __restrict__ wv) {
    const float* src = blockIdx.y == 0 ? wq : wv;
    uint2* dst = blockIdx.y == 0 ? g_wqF : g_wvF;
    int nt   = blockIdx.x;
    int kc   = threadIdx.x >> 5;
    int lane = threadIdx.x & 31;
    int g  = lane >> 2;
    int t4 = lane & 3;
    int c  = nt * 8 + g;
    int k0 = kc * 16 + 2 * t4;
    const float* wr = src + (size_t)c * C_;
    __half2 b0 = __floats2half2_rn(wr[k0],     wr[k0 + 1]);
    __half2 b1 = __floats2half2_rn(wr[k0 + 8], wr[k0 + 9]);
    uint2 r;
    r.x = *(unsigned*)&b0;
    r.y = *(unsigned*)&b1;
    dst[(nt * 16 + kc) * 32 + lane] = r;
}

// ---------------------------------------------------------------------------
// Kernel 0b: wk B-fragments for t GEMM: B[kk][n] = wk[h*32+kk][n0+n].
// grid = 256 (h = bid>>5, nt = bid&31), block 64 (kc2 = tid>>5, lane)
// ---------------------------------------------------------------------------
__global__ void pack_wkF_kernel(const float* __restrict__ wk) {
    int h    = blockIdx.x >> 5;
    int nt   = blockIdx.x & 31;
    int kc2  = threadIdx.x >> 5;
    int lane = threadIdx.x & 31;
    int g  = lane >> 2;
    int t4 = lane & 3;
    int row0 = h * D_ + kc2 * 16 + 2 * t4;
    int col  = nt * 8 + g;
    __half2 b0 = __floats2half2_rn(wk[(size_t)row0 * C_ + col],
                                   wk[(size_t)(row0 + 1) * C_ + col]);
    __half2 b1 = __floats2half2_rn(wk[(size_t)(row0 + 8) * C_ + col],
                                   wk[(size_t)(row0 + 9) * C_ + col]);
    uint2 r;
    r.x = *(unsigned*)&b0;
    r.y = *(unsigned*)&b1;
    g_wkF[((h * 32 + nt) * 2 + kc2) * 32 + lane] = r;
}

// ---------------------------------------------------------------------------
// Kernel 1: role-split prologue.
// Blocks [0,1000): HMMA projections (qp -> t, u). Rest: x-transpose.
// ---------------------------------------------------------------------------
__global__ __launch_bounds__(512)
void prologue_kernel(const float* __restrict__ x,
                     const float* __restrict__ q,  const float* __restrict__ bq,
                     const float* __restrict__ bk) {
    extern __shared__ char psc[];
    const int tid = threadIdx.x;
    const int bid = blockIdx.x;

    if (bid >= PRJ_BLOCKS) {
        // =============== TRANSPOSE ROLE: two 32x32 tiles ===============
        float* psm = (float*)psc;
        int t2  = bid - PRJ_BLOCKS;
        int pp  = t2 % TRP_PAIRS;
        int rem = t2 / TRP_PAIRS;
        int c0  = (rem & 7) * 32;
        int b   = rem >> 3;
        int half = tid >> 8;
        int t   = tid & 255;
        int tx  = t & 31;
        int ty  = t >> 5;
        int p0  = pp * 64 + half * 32;
        float (*tile)[33] = (float(*)[33])(psm + half * 32 * 33);

        #pragma unroll
        for (int dy = 0; dy < 32; dy += 8) {
            int c = c0 + ty + dy;
            int p = p0 + tx;
            float v = 0.f;
            if (p < HW_) v = x[(size_t)(b * C_ + c) * HW_ + p];
            tile[ty + dy][tx] = v;
        }
        __syncthreads();
        #pragma unroll
        for (int dy = 0; dy < 32; dy += 8) {
            int p = p0 + ty + dy;
            int c = c0 + tx;
            if (p < HW_)
                g_xt[(size_t)(b * HW_ + p) * C_ + c] =
                    __float2half_rn(tile[tx][ty + dy]);
        }
        return;
    }

    // =============== PROJ ROLE (HMMA) ===============
    __half* q_sm  = (__half*)psc;                    // [16][QPITCH]
    __half* qp_sm = (__half*)psc + MB * QPITCH;      // [16][QPITCH]
    const int r0   = bid * MB;                       // flat row (b*Q+q)
    const int warp = tid >> 5;
    const int lane = tid & 31;
    const int g    = lane >> 2;
    const int t4   = lane & 3;
    const int li   = (lane & 7) + ((lane >> 3) & 1) * 8;
    const int col8 = ((lane >> 4) & 1) * 8;

    // ---- stage q rows fp32 -> fp16 smem ----
    #pragma unroll
    for (int rep = 0; rep < 4; rep++) {
        int idx  = tid + rep * 512;          // 0..2047 float2
        int row  = idx >> 7;
        int col2 = idx & 127;
        float2 v = __ldg((const float2*)(q + (size_t)(r0 + row) * C_) + col2);
        *(__half2*)(q_sm + row * QPITCH + col2 * 2) = __floats2half2_rn(v.x, v.y);
    }
    __syncthreads();

    unsigned int qs_s  = (unsigned int)__cvta_generic_to_shared(q_sm);
    unsigned int qps_s = (unsigned int)__cvta_generic_to_shared(qp_sm);

    // ---- qp = q @ wq^T + bq : warp owns 16 channels (2 n-tiles) ----
    {
        float d0[2][4];
        #pragma unroll
        for (int nt = 0; nt < 2; nt++)
            #pragma unroll
            for (int e = 0; e < 4; e++) d0[nt][e] = 0.f;
        unsigned int a_base = qs_s + (li * QPITCH + col8) * 2;
        const uint2* wf = g_wqF + (size_t)(warp * 2) * 16 * 32;
        #pragma unroll
        for (int kc = 0; kc < 16; kc++) {
            unsigned a0, a1, a2, a3;
            asm volatile(
                "ldmatrix.sync.aligned.m8n8.x4.shared.b16 {%0,%1,%2,%3}, [%4];"
                : "=r"(a0), "=r"(a1), "=r"(a2), "=r"(a3)
                : "r"(a_base + kc * 32));
            uint2 b0 = __ldg(wf + kc * 32 + lane);
            uint2 b1 = __ldg(wf + (16 + kc) * 32 + lane);
            asm volatile(
                "mma.sync.aligned.m16n8k16.row.col.f32.f16.f16.f32 "
                "{%0,%1,%2,%3}, {%4,%5,%6,%7}, {%8,%9}, {%0,%1,%2,%3};"
                : "+f"(d0[0][0]), "+f"(d0[0][1]), "+f"(d0[0][2]), "+f"(d0[0][3])
                : "r"(a0), "r"(a1), "r"(a2), "r"(a3), "r"(b0.x), "r"(b0.y));
            asm volatile(
                "mma.sync.aligned.m16n8k16.row.col.f32.f16.f16.f32 "
                "{%0,%1,%2,%3}, {%4,%5,%6,%7}, {%8,%9}, {%0,%1,%2,%3};"
                : "+f"(d0[1][0]), "+f"(d0[1][1]), "+f"(d0[1][2]), "+f"(d0[1][3])
                : "r"(a0), "r"(a1), "r"(a2), "r"(a3), "r"(b1.x), "r"(b1.y));
        }
        #pragma unroll
        for (int nt = 0; nt < 2; nt++) {
            int c = warp * 16 + nt * 8 + 2 * t4;
            float bb0 = __ldg(bq + c);
            float bb1 = __ldg(bq + c + 1);
            *(__half2*)(qp_sm + g * QPITCH + c) =
                __floats2half2_rn(d0[nt][0] + bb0, d0[nt][1] + bb1);
            *(__half2*)(qp_sm + (g + 8) * QPITCH + c) =
                __floats2half2_rn(d0[nt][2] + bb0, d0[nt][3] + bb1);
        }
    }
    __syncthreads();

    // ---- u[r][h] = qp_head . bk_head : 128 threads ----
    if (tid < MB * NH_) {
        int r = tid >> 3, h = tid & 7;
        float s = 0.f;
        #pragma unroll
        for (int dd = 0; dd < D_; dd++)
            s += __half2float(qp_sm[r * QPITCH + h * D_ + dd]) * __ldg(bk + h * D_ + dd);
        g_u[(size_t)(r0 + r) * NH_ + h] = s;
    }

    // ---- t = per-head qp @ wk : warp owns (h = w>>1, 16 n-tiles) ----
    {
        const int h   = warp >> 1;
        const int nt0 = (warp & 1) * 16;
        unsigned int a_base = qps_s + (li * QPITCH + h * D_ + col8) * 2;
        unsigned aa[2][4];
        #pragma unroll
        for (int kc2 = 0; kc2 < 2; kc2++)
            asm volatile(
                "ldmatrix.sync.aligned.m8n8.x4.shared.b16 {%0,%1,%2,%3}, [%4];"
                : "=r"(aa[kc2][0]), "=r"(aa[kc2][1]),
                  "=r"(aa[kc2][2]), "=r"(aa[kc2][3])
                : "r"(a_base + kc2 * 32));
        #pragma unroll
        for (int nn = 0; nn < 16; nn++) {
            int ntile = nt0 + nn;
            const uint2* wf = g_wkF + (size_t)((h * 32 + ntile) * 2) * 32;
            uint2 b0 = __ldg(wf + lane);
            uint2 b1 = __ldg(wf + 32 + lane);
            float d0[4] = {0.f, 0.f, 0.f, 0.f};
            asm volatile(
                "mma.sync.aligned.m16n8k16.row.col.f32.f16.f16.f32 "
                "{%0,%1,%2,%3}, {%4,%5,%6,%7}, {%8,%9}, {%0,%1,%2,%3};"
                : "+f"(d0[0]), "+f"(d0[1]), "+f"(d0[2]), "+f"(d0[3])
                : "r"(aa[0][0]), "r"(aa[0][1]), "r"(aa[0][2]), "r"(aa[0][3]),
                  "r"(b0.x), "r"(b0.y));
            asm volatile(
                "mma.sync.aligned.m16n8k16.row.col.f32.f16.f16.f32 "
                "{%0,%1,%2,%3}, {%4,%5,%6,%7}, {%8,%9}, {%0,%1,%2,%3};"
                : "+f"(d0[0]), "+f"(d0[1]), "+f"(d0[2]), "+f"(d0[3])
                : "r"(aa[1][0]), "r"(aa[1][1]), "r"(aa[1][2]), "r"(aa[1][3]),
                  "r"(b1.x), "r"(b1.y));
            int col = ntile * 8 + 2 * t4;
            __half* tb = g_t + (size_t)(r0 + g) * NH_ * C_ + h * C_ + col;
            *(__half2*)tb = __floats2half2_rn(d0[0], d0[1]);
            *(__half2*)(tb + (size_t)8 * NH_ * C_) = __floats2half2_rn(d0[2], d0[3]);
        }
    }
}

// ---------------------------------------------------------------------------
// Kernel F: gather + scores + softmax + m (fp16 to global). Unchanged (R7/R9).
// ---------------------------------------------------------------------------
__global__ __launch_bounds__(512, 3)
void deform_attn_kernel(const float* __restrict__ ref) {
    extern __shared__ char smc[];
    __half*  A_sm  = (__half*)(smc + OFF_A);
    __half*  t_sm  = (__half*)(smc + OFF_T);
    float*   ps_sm = (float*)(smc + OFF_PS);
    float*   sc_sm = (float*)(smc + OFF_SC);
    float*   at_sm = (float*)(smc + OFF_AT);
    float*   u_sm  = (float*)(smc + OFF_U);
    float4*  wt_sm = (float4*)(smc + OFF_WT);
    int2*    oy_sm = (int2*)(smc + OFF_OY);
    ushort2* ox_sm = (ushort2*)(smc + OFF_OX);

    const int tid = threadIdx.x;
    const int b   = blockIdx.y;
    const int gq0 = blockIdx.x * TQ;

    if (tid < TQ * N_) {
        int i  = tid >> 4, j = tid & 15;
        int rr = (gq0 + i) * N_ + j;
        int n  = rr / Q_;
        int qq = rr - n * Q_;
        float2 g = __ldg((const float2*)(ref + (size_t)((b * Q_ + qq) * N_ + n) * 2));
        float gx = ((g.x + 1.0f) * (float)W_ - 1.0f) * 0.5f;
        float gy = ((g.y + 1.0f) * (float)H_ - 1.0f) * 0.5f;
        float x0f = floorf(gx), y0f = floorf(gy);
        float fx = gx - x0f, fy = gy - y0f;
        int x0 = (int)x0f, y0 = (int)y0f;
        int x1 = x0 + 1,   y1 = y0 + 1;
        bool vx0 = (x0 >= 0) & (x0 < W_);
        bool vx1 = (x1 >= 0) & (x1 < W_);
        bool vy0 = (y0 >= 0) & (y0 < H_);
        bool vy1 = (y1 >= 0) & (y1 < H_);
        float4 w;
        w.x = (vx0 && vy0) ? (1.f - fx) * (1.f - fy) : 0.f;
        w.y = (vx1 && vy0) ? fx * (1.f - fy)         : 0.f;
        w.z = (vx0 && vy1) ? (1.f - fx) * fy         : 0.f;
        w.w = (vx1 && vy1) ? fx * fy                 : 0.f;
        int x0c = min(max(x0, 0), W_ - 1);
        int x1c = min(max(x1, 0), W_ - 1);
        int y0c = min(max(y0, 0), H_ - 1);
        int y1c = min(max(y1, 0), H_ - 1);
        wt_sm[tid] = w;
        oy_sm[tid] = make_int2(y0c * W_ * C_, y1c * W_ * C_);
        ox_sm[tid] = make_ushort2((unsigned short)(x0c * C_),
                                  (unsigned short)(x1c * C_));
    }
    {
        const uint4* ts = (const uint4*)(g_t + (size_t)(b * Q_ + gq0) * NH_ * C_);
        uint4* td = (uint4*)t_sm;
        td[tid] = __ldg(ts + tid);
        td[tid + 512] = __ldg(ts + tid + 512);
    }
    if (tid < TQ * NH_)
        u_sm[tid] = __ldg(g_u + (size_t)(b * Q_ + gq0) * NH_ + tid);
    __syncthreads();

    {
        const int k2 = tid & 127;
        const int rg = tid >> 7;
        const __half* xb = g_xt + (size_t)b * HW_ * C_;
        #pragma unroll 4
        for (int row = rg; row < TQ * N_; row += 4) {
            float4  w  = wt_sm[row];
            int2    oy = oy_sm[row];
            ushort2 ox = ox_sm[row];
            float2 v00 = __half22float2(__ldg((const __half2*)(xb + oy.x + ox.x) + k2));
            float2 v01 = __half22float2(__ldg((const __half2*)(xb + oy.x + ox.y) + k2));
            float2 v10 = __half22float2(__ldg((const __half2*)(xb + oy.y + ox.x) + k2));
            float2 v11 = __half22float2(__ldg((const __half2*)(xb + oy.y + ox.y) + k2));
            float rx = w.x * v00.x + w.y * v01.x + w.z * v10.x + w.w * v11.x;
            float ry = w.x * v00.y + w.y * v01.y + w.z * v10.y + w.w * v11.y;
            *(__half2*)(A_sm + row * AP2 + 2 * k2) = __floats2half2_rn(rx, ry);
        }
    }
    __syncthreads();

    {
        const int kh = tid >> 7;
        const int r  = tid & 127;
        const int i  = r >> 5;
        const int jp = (r >> 2) & 7;
        const int hp = r & 3;
        const uint4* a0 = (const uint4*)(A_sm + (i * N_ + 2 * jp) * AP2) + kh * 8;
        const uint4* a1 = (const uint4*)(A_sm + (i * N_ + 2 * jp + 1) * AP2) + kh * 8;
        const uint4* t0 = (const uint4*)(t_sm + (i * NH_ + 2 * hp) * C_) + kh * 8;
        const uint4* t1 = (const uint4*)(t_sm + (i * NH_ + 2 * hp + 1) * C_) + kh * 8;
        float acc00 = 0.f, acc01 = 0.f, acc10 = 0.f, acc11 = 0.f;
        #pragma unroll
        for (int c8 = 0; c8 < 8; c8++) {
            uint4 av0 = a0[c8], av1 = a1[c8], tv0 = t0[c8], tv1 = t1[c8];
            const __half2* ah0 = (const __half2*)&av0;
            const __half2* ah1 = (const __half2*)&av1;
            const __half2* th0 = (const __half2*)&tv0;
            const __half2* th1 = (const __half2*)&tv1;
            #pragma unroll
            for (int p = 0; p < 4; p++) {
                float2 f0 = __half22float2(ah0[p]);
                float2 f1 = __half22float2(ah1[p]);
                float2 g0 = __half22float2(th0[p]);
                float2 g1 = __half22float2(th1[p]);
                acc00 += f0.x * g0.x + f0.y * g0.y;
                acc01 += f0.x * g1.x + f0.y * g1.y;
                acc10 += f1.x * g0.x + f1.y * g0.y;
                acc11 += f1.x * g1.x + f1.y * g1.y;
            }
        }
        float* ps = ps_sm + kh * 512 + i * 128;
        ps[(2 * jp) * 8 + 2 * hp]         = acc00;
        ps[(2 * jp) * 8 + 2 * hp + 1]     = acc01;
        ps[(2 * jp + 1) * 8 + 2 * hp]     = acc10;
        ps[(2 * jp + 1) * 8 + 2 * hp + 1] = acc11;
    }
    __syncthreads();

    {
        const int i = tid >> 7;
        const int j = (tid >> 3) & 15;
        const int h = tid & 7;
        const int idx = i * 128 + j * 8 + h;
        float s = ps_sm[idx] + ps_sm[512 + idx] + ps_sm[1024 + idx] + ps_sm[1536 + idx];
        const float scale = 0.17677669529663687f;
        sc_sm[(i * NH_ + h) * N_ + j] = (s + u_sm[i * NH_ + h]) * scale;
    }
    __syncthreads();

    if (tid < TQ * NH_) {
        int i = tid >> 3, h = tid & 7;
        float s[N_];
        float mx = -1e30f;
        #pragma unroll
        for (int j = 0; j < N_; j++) {
            s[j] = sc_sm[(i * NH_ + h) * N_ + j];
            mx = fmaxf(mx, s[j]);
        }
        float sum = 0.f;
        #pragma unroll
        for (int j = 0; j < N_; j++) { s[j] = expf(s[j] - mx); sum += s[j]; }
        float inv = 1.f / sum;
        #pragma unroll
        for (int j = 0; j < N_; j++)
            at_sm[(i * N_ + j) * NH_ + h] = s[j] * inv;
    }
    __syncthreads();

    {
        const int k2 = tid & 127;
        const int i  = tid >> 7;
        float accx[NH_], accy[NH_];
        #pragma unroll
        for (int h = 0; h < NH_; h++) { accx[h] = 0.f; accy[h] = 0.f; }
        #pragma unroll
        for (int j = 0; j < N_; j++) {
            float2 a = __half22float2(*(const __half2*)(A_sm + (i * N_ + j) * AP2 + 2 * k2));
            float4 p0 = *(const float4*)(at_sm + (i * N_ + j) * NH_);
            float4 p1 = *(const float4*)(at_sm + (i * N_ + j) * NH_ + 4);
            accx[0] += a.x * p0.x; accy[0] += a.y * p0.x;
            accx[1] += a.x * p0.y; accy[1] += a.y * p0.y;
            accx[2] += a.x * p0.z; accy[2] += a.y * p0.z;
            accx[3] += a.x * p0.w; accy[3] += a.y * p0.w;
            accx[4] += a.x * p1.x; accy[4] += a.y * p1.x;
            accx[5] += a.x * p1.y; accy[5] += a.y * p1.y;
            accx[6] += a.x * p1.z; accy[6] += a.y * p1.z;
            accx[7] += a.x * p1.w; accy[7] += a.y * p1.w;
        }
        __half* mb = g_m + (size_t)(b * Q_ + gq0 + i) * NH_ * C_;
        #pragma unroll
        for (int h = 0; h < NH_; h++)
            *(__half2*)(mb + h * C_ + 2 * k2) = __floats2half2_rn(accx[h], accy[h]);
    }
}

// ---------------------------------------------------------------------------
// Kernel O (HMMA): out = m @ wv^T + bv. Unchanged (R12-proven).
// ---------------------------------------------------------------------------
__global__ __launch_bounds__(512, 2)
void out_kernel(const float* __restrict__ bv, float* __restrict__ out) {
    extern __shared__ __half m_sm[];   // [MB][MPITCH]

    const int tid  = threadIdx.x;
    const int r0   = blockIdx.x * MB;
    const int warp = tid >> 5;
    const int lane = tid & 31;

    {
        #pragma unroll
        for (int rep = 0; rep < 8; rep++) {
            int idx = tid + rep * 512;
            int row = idx >> 8;
            int seg = idx & 255;
            uint4 v = __ldg((const uint4*)(g_m + (size_t)(r0 + row) * NH_ * C_) + seg);
            *((uint4*)(m_sm + row * MPITCH) + seg) = v;
        }
    }
    __syncthreads();

    const int h   = warp >> 1;
    const int g   = lane >> 2;
    const int t4  = lane & 3;
    const int li   = (lane & 7) + ((lane >> 3) & 1) * 8;
    const int col8 = ((lane >> 4) & 1) * 8;
    unsigned int a_base = (unsigned int)__cvta_generic_to_shared(m_sm)
                        + (li * MPITCH + h * C_ + col8) * 2;

    float d0[2][4];
    #pragma unroll
    for (int nt = 0; nt < 2; nt++)
        #pragma unroll
        for (int e = 0; e < 4; e++) d0[nt][e] = 0.f;

    const uint2* wf = g_wvF + (size_t)(warp * 2) * 16 * 32;

    #pragma unroll
    for (int kc = 0; kc < 16; kc++) {
        unsigned a0, a1, a2, a3;
        asm volatile(
            "ldmatrix.sync.aligned.m8n8.x4.shared.b16 {%0,%1,%2,%3}, [%4];"
            : "=r"(a0), "=r"(a1), "=r"(a2), "=r"(a3)
            : "r"(a_base + kc * 32));
        uint2 b0 = __ldg(wf + kc * 32 + lane);
        uint2 b1 = __ldg(wf + (16 + kc) * 32 + lane);
        asm volatile(
            "mma.sync.aligned.m16n8k16.row.col.f32.f16.f16.f32 "
            "{%0,%1,%2,%3}, {%4,%5,%6,%7}, {%8,%9}, {%0,%1,%2,%3};"
            : "+f"(d0[0][0]), "+f"(d0[0][1]), "+f"(d0[0][2]), "+f"(d0[0][3])
            : "r"(a0), "r"(a1), "r"(a2), "r"(a3), "r"(b0.x), "r"(b0.y));
        asm volatile(
            "mma.sync.aligned.m16n8k16.row.col.f32.f16.f16.f32 "
            "{%0,%1,%2,%3}, {%4,%5,%6,%7}, {%8,%9}, {%0,%1,%2,%3};"
            : "+f"(d0[1][0]), "+f"(d0[1][1]), "+f"(d0[1][2]), "+f"(d0[1][3])
            : "r"(a0), "r"(a1), "r"(a2), "r"(a3), "r"(b1.x), "r"(b1.y));
    }

    #pragma unroll
    for (int nt = 0; nt < 2; nt++) {
        int c = warp * 16 + nt * 8 + 2 * t4;
        float bb0 = __ldg(bv + c);
        float bb1 = __ldg(bv + c + 1);
        float2 lo = make_float2(d0[nt][0] + bb0, d0[nt][1] + bb1);
        float2 hi = make_float2(d0[nt][2] + bb0, d0[nt][3] + bb1);
        *(float2*)(out + (size_t)(r0 + g) * C_ + c)     = lo;
        *(float2*)(out + (size_t)(r0 + g + 8) * C_ + c) = hi;
    }
}

// ---------------------------------------------------------------------------
extern "C" void kernel_launch(void* const* d_in, const int* in_sizes, int n_in,
                              void* d_out, int out_size) {
    const float* x   = (const float*)d_in[0];
    const float* q   = (const float*)d_in[1];
    const float* ref = (const float*)d_in[2];
    const float* wq  = (const float*)d_in[3];
    const float* bq  = (const float*)d_in[4];
    const float* wk  = (const float*)d_in[5];
    const float* bk  = (const float*)d_in[6];
    const float* wv  = (const float*)d_in[7];
    const float* bv  = (const float*)d_in[8];
    float* out = (float*)d_out;

    (void)in_sizes; (void)n_in; (void)out_size;

    pack_wF_kernel<<<dim3(32, 2), 512>>>(wq, wv);
    pack_wkF_kernel<<<256, 64>>>(wk);

    cudaFuncSetAttribute(prologue_kernel,
                         cudaFuncAttributeMaxDynamicSharedMemorySize, PROJ_SMEM);
    prologue_kernel<<<GRID1, 512, PROJ_SMEM>>>(x, q, bq, bk);

    cudaFuncSetAttribute(deform_attn_kernel,
                         cudaFuncAttributeMaxDynamicSharedMemorySize, SMEM_BYTES);
    deform_attn_kernel<<<dim3(Q_ / TQ, B_), 512, SMEM_BYTES>>>(ref);

    cudaFuncSetAttribute(out_kernel,
                         cudaFuncAttributeMaxDynamicSharedMemorySize, OUT_SMEM);
    out_kernel<<<(B_ * Q_) / MB, 512, OUT_SMEM>>>(bv, out);
}

// round 14
// speedup vs baseline: 1.9791x; 1.1246x over previous
#include <cuda_runtime.h>
#include <cuda_fp16.h>

#define B_  16
#define Q_  1000
#define N_  16
#define C_  256
#define H_  100
#define W_  100
#define HW_ 10000
#define NH_ 8
#define D_  32
#define TQ  4          // queries per fused block
#define MB  16         // rows per out/proj block
#define AP2 264        // A_sm row pitch in halves (528B, 16B-aligned)

// ---- fused kernel smem offsets (bytes) ----
#define OFF_A    0
#define SZ_A     (TQ*N_*AP2*2)          // 33792 half A[64][264]
#define OFF_T    (OFF_A + SZ_A)         // 33792 half t[4][8][256]; reused as m
#define SZ_T     (TQ*NH_*C_*2)          // 16384
#define OFF_PS   (OFF_T + SZ_T)         // 50176 float ps[4][512]
#define SZ_PS    (4*512*4)              // 8192
#define OFF_SC   (OFF_PS + SZ_PS)       // 58368 float sc[4][8][16]
#define SZ_SC    (TQ*NH_*N_*4)          // 2048
#define OFF_AT   (OFF_SC + SZ_SC)       // 60416 half at2[4][8][16] (1024B used)
#define SZ_AT    (TQ*N_*NH_*4)          // 4096 reserved
#define OFF_U    (OFF_AT + SZ_AT)       // 64512... keep layout: recompute below
#define SZ_U     (TQ*NH_*4)             // 128
#define OFF_WT   (OFF_U + SZ_U)         // float4 wt[64]
#define SZ_WT    (TQ*N_*16)             // 1024
#define OFF_OY   (OFF_WT + SZ_WT)
#define SZ_OY    (TQ*N_*8)              // 512
#define OFF_OX   (OFF_OY + SZ_OY)
#define SZ_OX    (TQ*N_*4)              // 256
#define SMEM_BYTES (OFF_OX + SZ_OX)     // 66560 -> still 3 blocks/SM (<=75.6KB)

// out kernel: m staged [MB][2056] halves
#define MPITCH  2056
#define OUT_SMEM (MB*MPITCH*2)          // 65792

// proj role smem
#define QPITCH  264
#define PROJ_SMEM (2*MB*QPITCH*2)       // 16896

// role-split prologue grid
#define PRJ_BLOCKS ((B_*Q_)/MB)         // 1000
#define TRP_PAIRS  157
#define TRP_BLOCKS (TRP_PAIRS*8*B_)     // 20096
#define GRID1 (PRJ_BLOCKS + TRP_BLOCKS)

// device scratch
__device__ __half g_xt[B_ * HW_ * C_];
__device__ uint2  g_wqF[32 * 16 * 32];
__device__ uint2  g_wvF[32 * 16 * 32];
__device__ uint2  g_wkF[NH_ * 32 * 2 * 32];
__device__ __half g_t[(size_t)B_ * Q_ * NH_ * C_];
__device__ __half g_m[(size_t)B_ * Q_ * NH_ * C_];
__device__ float  g_u[(size_t)B_ * Q_ * NH_];

// ---------------------------------------------------------------------------
// Kernel 0a: build B-fragments for qp / out GEMMs
// ---------------------------------------------------------------------------
__global__ void pack_wF_kernel(const float* __restrict__ wq,
                               const float* __restrict__ wv) {
    const float* src = blockIdx.y == 0 ? wq : wv;
    uint2* dst = blockIdx.y == 0 ? g_wqF : g_wvF;
    int nt   = blockIdx.x;
    int kc   = threadIdx.x >> 5;
    int lane = threadIdx.x & 31;
    int g  = lane >> 2;
    int t4 = lane & 3;
    int c  = nt * 8 + g;
    int k0 = kc * 16 + 2 * t4;
    const float* wr = src + (size_t)c * C_;
    __half2 b0 = __floats2half2_rn(wr[k0],     wr[k0 + 1]);
    __half2 b1 = __floats2half2_rn(wr[k0 + 8], wr[k0 + 9]);
    uint2 r;
    r.x = *(unsigned*)&b0;
    r.y = *(unsigned*)&b1;
    dst[(nt * 16 + kc) * 32 + lane] = r;
}

// ---------------------------------------------------------------------------
// Kernel 0b: wk B-fragments for t GEMM
// ---------------------------------------------------------------------------
__global__ void pack_wkF_kernel(const float* __restrict__ wk) {
    int h    = blockIdx.x >> 5;
    int nt   = blockIdx.x & 31;
    int kc2  = threadIdx.x >> 5;
    int lane = threadIdx.x & 31;
    int g  = lane >> 2;
    int t4 = lane & 3;
    int row0 = h * D_ + kc2 * 16 + 2 * t4;
    int col  = nt * 8 + g;
    __half2 b0 = __floats2half2_rn(wk[(size_t)row0 * C_ + col],
                                   wk[(size_t)(row0 + 1) * C_ + col]);
    __half2 b1 = __floats2half2_rn(wk[(size_t)(row0 + 8) * C_ + col],
                                   wk[(size_t)(row0 + 9) * C_ + col]);
    uint2 r;
    r.x = *(unsigned*)&b0;
    r.y = *(unsigned*)&b1;
    g_wkF[((h * 32 + nt) * 2 + kc2) * 32 + lane] = r;
}

// ---------------------------------------------------------------------------
// Kernel 1: role-split prologue (HMMA proj + x-transpose). Unchanged (R13).
// ---------------------------------------------------------------------------
__global__ __launch_bounds__(512)
void prologue_kernel(const float* __restrict__ x,
                     const float* __restrict__ q,  const float* __restrict__ bq,
                     const float* __restrict__ bk) {
    extern __shared__ char psc[];
    const int tid = threadIdx.x;
    const int bid = blockIdx.x;

    if (bid >= PRJ_BLOCKS) {
        float* psm = (float*)psc;
        int t2  = bid - PRJ_BLOCKS;
        int pp  = t2 % TRP_PAIRS;
        int rem = t2 / TRP_PAIRS;
        int c0  = (rem & 7) * 32;
        int b   = rem >> 3;
        int half = tid >> 8;
        int t   = tid & 255;
        int tx  = t & 31;
        int ty  = t >> 5;
        int p0  = pp * 64 + half * 32;
        float (*tile)[33] = (float(*)[33])(psm + half * 32 * 33);

        #pragma unroll
        for (int dy = 0; dy < 32; dy += 8) {
            int c = c0 + ty + dy;
            int p = p0 + tx;
            float v = 0.f;
            if (p < HW_) v = x[(size_t)(b * C_ + c) * HW_ + p];
            tile[ty + dy][tx] = v;
        }
        __syncthreads();
        #pragma unroll
        for (int dy = 0; dy < 32; dy += 8) {
            int p = p0 + ty + dy;
            int c = c0 + tx;
            if (p < HW_)
                g_xt[(size_t)(b * HW_ + p) * C_ + c] =
                    __float2half_rn(tile[tx][ty + dy]);
        }
        return;
    }

    __half* q_sm  = (__half*)psc;
    __half* qp_sm = (__half*)psc + MB * QPITCH;
    const int r0   = bid * MB;
    const int warp = tid >> 5;
    const int lane = tid & 31;
    const int g    = lane >> 2;
    const int t4   = lane & 3;
    const int li   = (lane & 7) + ((lane >> 3) & 1) * 8;
    const int col8 = ((lane >> 4) & 1) * 8;

    #pragma unroll
    for (int rep = 0; rep < 4; rep++) {
        int idx  = tid + rep * 512;
        int row  = idx >> 7;
        int col2 = idx & 127;
        float2 v = __ldg((const float2*)(q + (size_t)(r0 + row) * C_) + col2);
        *(__half2*)(q_sm + row * QPITCH + col2 * 2) = __floats2half2_rn(v.x, v.y);
    }
    __syncthreads();

    unsigned int qs_s  = (unsigned int)__cvta_generic_to_shared(q_sm);
    unsigned int qps_s = (unsigned int)__cvta_generic_to_shared(qp_sm);

    {
        float d0[2][4];
        #pragma unroll
        for (int nt = 0; nt < 2; nt++)
            #pragma unroll
            for (int e = 0; e < 4; e++) d0[nt][e] = 0.f;
        unsigned int a_base = qs_s + (li * QPITCH + col8) * 2;
        const uint2* wf = g_wqF + (size_t)(warp * 2) * 16 * 32;
        #pragma unroll
        for (int kc = 0; kc < 16; kc++) {
            unsigned a0, a1, a2, a3;
            asm volatile(
                "ldmatrix.sync.aligned.m8n8.x4.shared.b16 {%0,%1,%2,%3}, [%4];"
                : "=r"(a0), "=r"(a1), "=r"(a2), "=r"(a3)
                : "r"(a_base + kc * 32));
            uint2 b0 = __ldg(wf + kc * 32 + lane);
            uint2 b1 = __ldg(wf + (16 + kc) * 32 + lane);
            asm volatile(
                "mma.sync.aligned.m16n8k16.row.col.f32.f16.f16.f32 "
                "{%0,%1,%2,%3}, {%4,%5,%6,%7}, {%8,%9}, {%0,%1,%2,%3};"
                : "+f"(d0[0][0]), "+f"(d0[0][1]), "+f"(d0[0][2]), "+f"(d0[0][3])
                : "r"(a0), "r"(a1), "r"(a2), "r"(a3), "r"(b0.x), "r"(b0.y));
            asm volatile(
                "mma.sync.aligned.m16n8k16.row.col.f32.f16.f16.f32 "
                "{%0,%1,%2,%3}, {%4,%5,%6,%7}, {%8,%9}, {%0,%1,%2,%3};"
                : "+f"(d0[1][0]), "+f"(d0[1][1]), "+f"(d0[1][2]), "+f"(d0[1][3])
                : "r"(a0), "r"(a1), "r"(a2), "r"(a3), "r"(b1.x), "r"(b1.y));
        }
        #pragma unroll
        for (int nt = 0; nt < 2; nt++) {
            int c = warp * 16 + nt * 8 + 2 * t4;
            float bb0 = __ldg(bq + c);
            float bb1 = __ldg(bq + c + 1);
            *(__half2*)(qp_sm + g * QPITCH + c) =
                __floats2half2_rn(d0[nt][0] + bb0, d0[nt][1] + bb1);
            *(__half2*)(qp_sm + (g + 8) * QPITCH + c) =
                __floats2half2_rn(d0[nt][2] + bb0, d0[nt][3] + bb1);
        }
    }
    __syncthreads();

    if (tid < MB * NH_) {
        int r = tid >> 3, h = tid & 7;
        float s = 0.f;
        #pragma unroll
        for (int dd = 0; dd < D_; dd++)
            s += __half2float(qp_sm[r * QPITCH + h * D_ + dd]) * __ldg(bk + h * D_ + dd);
        g_u[(size_t)(r0 + r) * NH_ + h] = s;
    }

    {
        const int h   = warp >> 1;
        const int nt0 = (warp & 1) * 16;
        unsigned int a_base = qps_s + (li * QPITCH + h * D_ + col8) * 2;
        unsigned aa[2][4];
        #pragma unroll
        for (int kc2 = 0; kc2 < 2; kc2++)
            asm volatile(
                "ldmatrix.sync.aligned.m8n8.x4.shared.b16 {%0,%1,%2,%3}, [%4];"
                : "=r"(aa[kc2][0]), "=r"(aa[kc2][1]),
                  "=r"(aa[kc2][2]), "=r"(aa[kc2][3])
                : "r"(a_base + kc2 * 32));
        #pragma unroll
        for (int nn = 0; nn < 16; nn++) {
            int ntile = nt0 + nn;
            const uint2* wf = g_wkF + (size_t)((h * 32 + ntile) * 2) * 32;
            uint2 b0 = __ldg(wf + lane);
            uint2 b1 = __ldg(wf + 32 + lane);
            float d0[4] = {0.f, 0.f, 0.f, 0.f};
            asm volatile(
                "mma.sync.aligned.m16n8k16.row.col.f32.f16.f16.f32 "
                "{%0,%1,%2,%3}, {%4,%5,%6,%7}, {%8,%9}, {%0,%1,%2,%3};"
                : "+f"(d0[0]), "+f"(d0[1]), "+f"(d0[2]), "+f"(d0[3])
                : "r"(aa[0][0]), "r"(aa[0][1]), "r"(aa[0][2]), "r"(aa[0][3]),
                  "r"(b0.x), "r"(b0.y));
            asm volatile(
                "mma.sync.aligned.m16n8k16.row.col.f32.f16.f16.f32 "
                "{%0,%1,%2,%3}, {%4,%5,%6,%7}, {%8,%9}, {%0,%1,%2,%3};"
                : "+f"(d0[0]), "+f"(d0[1]), "+f"(d0[2]), "+f"(d0[3])
                : "r"(aa[1][0]), "r"(aa[1][1]), "r"(aa[1][2]), "r"(aa[1][3]),
                  "r"(b1.x), "r"(b1.y));
            int col = ntile * 8 + 2 * t4;
            __half* tb = g_t + (size_t)(r0 + g) * NH_ * C_ + h * C_ + col;
            *(__half2*)tb = __floats2half2_rn(d0[0], d0[1]);
            *(__half2*)(tb + (size_t)8 * NH_ * C_) = __floats2half2_rn(d0[2], d0[3]);
        }
    }
}

// ---------------------------------------------------------------------------
// Kernel F: gather + HMMA scores + softmax + HMMA m. TQ=4, 512 thr, 3/SM.
// ---------------------------------------------------------------------------
__global__ __launch_bounds__(512, 3)
void deform_attn_kernel(const float* __restrict__ ref) {
    extern __shared__ char smc[];
    __half*  A_sm  = (__half*)(smc + OFF_A);
    __half*  t_sm  = (__half*)(smc + OFF_T);     // t, then m
    float*   ps_sm = (float*)(smc + OFF_PS);
    float*   sc_sm = (float*)(smc + OFF_SC);
    __half*  at2_sm = (__half*)(smc + OFF_AT);   // attn fp16 [i][h][j]
    float*   u_sm  = (float*)(smc + OFF_U);
    float4*  wt_sm = (float4*)(smc + OFF_WT);
    int2*    oy_sm = (int2*)(smc + OFF_OY);
    ushort2* ox_sm = (ushort2*)(smc + OFF_OX);

    const int tid  = threadIdx.x;
    const int b    = blockIdx.y;
    const int gq0  = blockIdx.x * TQ;
    const int warp = tid >> 5;
    const int lane = tid & 31;
    const int g    = lane >> 2;
    const int t4   = lane & 3;

    unsigned int A_s  = (unsigned int)__cvta_generic_to_shared(A_sm);
    unsigned int T_s  = (unsigned int)__cvta_generic_to_shared(t_sm);
    unsigned int AT_s = (unsigned int)__cvta_generic_to_shared(at2_sm);

    // ---- phase 0: ref precompute + t/u load ----
    if (tid < TQ * N_) {
        int i  = tid >> 4, j = tid & 15;
        int rr = (gq0 + i) * N_ + j;
        int n  = rr / Q_;
        int qq = rr - n * Q_;
        float2 gr = __ldg((const float2*)(ref + (size_t)((b * Q_ + qq) * N_ + n) * 2));
        float gx = ((gr.x + 1.0f) * (float)W_ - 1.0f) * 0.5f;
        float gy = ((gr.y + 1.0f) * (float)H_ - 1.0f) * 0.5f;
        float x0f = floorf(gx), y0f = floorf(gy);
        float fx = gx - x0f, fy = gy - y0f;
        int x0 = (int)x0f, y0 = (int)y0f;
        int x1 = x0 + 1,   y1 = y0 + 1;
        bool vx0 = (x0 >= 0) & (x0 < W_);
        bool vx1 = (x1 >= 0) & (x1 < W_);
        bool vy0 = (y0 >= 0) & (y0 < H_);
        bool vy1 = (y1 >= 0) & (y1 < H_);
        float4 w;
        w.x = (vx0 && vy0) ? (1.f - fx) * (1.f - fy) : 0.f;
        w.y = (vx1 && vy0) ? fx * (1.f - fy)         : 0.f;
        w.z = (vx0 && vy1) ? (1.f - fx) * fy         : 0.f;
        w.w = (vx1 && vy1) ? fx * fy                 : 0.f;
        int x0c = min(max(x0, 0), W_ - 1);
        int x1c = min(max(x1, 0), W_ - 1);
        int y0c = min(max(y0, 0), H_ - 1);
        int y1c = min(max(y1, 0), H_ - 1);
        wt_sm[tid] = w;
        oy_sm[tid] = make_int2(y0c * W_ * C_, y1c * W_ * C_);
        ox_sm[tid] = make_ushort2((unsigned short)(x0c * C_),
                                  (unsigned short)(x1c * C_));
    }
    {
        const uint4* ts = (const uint4*)(g_t + (size_t)(b * Q_ + gq0) * NH_ * C_);
        uint4* td = (uint4*)t_sm;
        td[tid] = __ldg(ts + tid);
        td[tid + 512] = __ldg(ts + tid + 512);
    }
    if (tid < TQ * NH_)
        u_sm[tid] = __ldg(g_u + (size_t)(b * Q_ + gq0) * NH_ + tid);
    __syncthreads();

    // ---- gather: thread owns k-pair; 16 rows each ----
    {
        const int k2 = tid & 127;
        const int rg = tid >> 7;
        const __half* xb = g_xt + (size_t)b * HW_ * C_;
        #pragma unroll 4
        for (int row = rg; row < TQ * N_; row += 4) {
            float4  w  = wt_sm[row];
            int2    oy = oy_sm[row];
            ushort2 ox = ox_sm[row];
            float2 v00 = __half22float2(__ldg((const __half2*)(xb + oy.x + ox.x) + k2));
            float2 v01 = __half22float2(__ldg((const __half2*)(xb + oy.x + ox.y) + k2));
            float2 v10 = __half22float2(__ldg((const __half2*)(xb + oy.y + ox.x) + k2));
            float2 v11 = __half22float2(__ldg((const __half2*)(xb + oy.y + ox.y) + k2));
            float rx = w.x * v00.x + w.y * v01.x + w.z * v10.x + w.w * v11.x;
            float ry = w.x * v00.y + w.y * v01.y + w.z * v10.y + w.w * v11.y;
            *(__half2*)(A_sm + row * AP2 + 2 * k2) = __floats2half2_rn(rx, ry);
        }
    }
    __syncthreads();

    // ---- scores (HMMA): warp = (i = w&3, ks = w>>2); D[j16 x h8] partials ----
    {
        const int i  = warp & 3;
        const int ks = warp >> 2;
        const int li   = (lane & 7) + ((lane >> 3) & 1) * 8;
        const int col8 = ((lane >> 4) & 1) * 8;
        unsigned int a_base = A_s + ((i * N_ + li) * AP2 + col8) * 2;
        const int bl = lane & 15;
        unsigned int b_base = T_s + ((i * NH_ + (bl & 7)) * C_ + ((bl >> 3) & 1) * 8) * 2;
        float d[4] = {0.f, 0.f, 0.f, 0.f};
        #pragma unroll
        for (int kk = 0; kk < 4; kk++) {
            int kc = ks * 4 + kk;
            unsigned a0, a1, a2, a3, b0, b1;
            asm volatile(
                "ldmatrix.sync.aligned.m8n8.x4.shared.b16 {%0,%1,%2,%3}, [%4];"
                : "=r"(a0), "=r"(a1), "=r"(a2), "=r"(a3)
                : "r"(a_base + kc * 32));
            asm volatile(
                "ldmatrix.sync.aligned.m8n8.x2.shared.b16 {%0,%1}, [%2];"
                : "=r"(b0), "=r"(b1)
                : "r"(b_base + kc * 32));
            asm volatile(
                "mma.sync.aligned.m16n8k16.row.col.f32.f16.f16.f32 "
                "{%0,%1,%2,%3}, {%4,%5,%6,%7}, {%8,%9}, {%0,%1,%2,%3};"
                : "+f"(d[0]), "+f"(d[1]), "+f"(d[2]), "+f"(d[3])
                : "r"(a0), "r"(a1), "r"(a2), "r"(a3), "r"(b0), "r"(b1));
        }
        float* ps = ps_sm + ks * 512 + i * 128;
        ps[g * 8 + 2 * t4]           = d[0];
        ps[g * 8 + 2 * t4 + 1]       = d[1];
        ps[(g + 8) * 8 + 2 * t4]     = d[2];
        ps[(g + 8) * 8 + 2 * t4 + 1] = d[3];
    }
    __syncthreads();

    // ---- reduce partials -> sc ----
    {
        const int i = tid >> 7;
        const int j = (tid >> 3) & 15;
        const int h = tid & 7;
        const int idx = i * 128 + j * 8 + h;
        float s = ps_sm[idx] + ps_sm[512 + idx] + ps_sm[1024 + idx] + ps_sm[1536 + idx];
        const float scale = 0.17677669529663687f;
        sc_sm[(i * NH_ + h) * N_ + j] = (s + u_sm[i * NH_ + h]) * scale;
    }
    __syncthreads();

    // ---- softmax over j per (i,h): 32 threads; attn fp16 [i][h][j] ----
    if (tid < TQ * NH_) {
        int i = tid >> 3, h = tid & 7;
        float s[N_];
        float mx = -1e30f;
        #pragma unroll
        for (int j = 0; j < N_; j++) {
            s[j] = sc_sm[(i * NH_ + h) * N_ + j];
            mx = fmaxf(mx, s[j]);
        }
        float sum = 0.f;
        #pragma unroll
        for (int j = 0; j < N_; j++) { s[j] = expf(s[j] - mx); sum += s[j]; }
        float inv = 1.f / sum;
        __half* dst = at2_sm + i * 128 + h * 16;
        #pragma unroll
        for (int j = 0; j < N_; j += 2)
            *(__half2*)(dst + j) = __floats2half2_rn(s[j] * inv, s[j + 1] * inv);
    }
    __syncthreads();

    // ---- m (HMMA): D[k16 x h8] = A^T . attn^T; warp = (i = w&3, ks = w>>2) ----
    {
        const int i  = warp & 3;
        const int ks = warp >> 2;
        // B = attn[h][j]: ldmatrix.x2 on at2 rows
        const int bl = lane & 15;
        unsigned int b_addr = AT_s + (i * 128 + (bl & 7) * 16 + ((bl >> 3) & 1) * 8) * 2;
        unsigned b0, b1;
        asm volatile(
            "ldmatrix.sync.aligned.m8n8.x2.shared.b16 {%0,%1}, [%2];"
            : "=r"(b0), "=r"(b1) : "r"(b_addr));
        // A^T frag addressing
        const int jrow  = (lane & 7) + ((lane >> 4) & 1) * 8;
        const int kcol8 = ((lane >> 3) & 1) * 8;
        unsigned int a_base = A_s + ((i * N_ + jrow) * AP2 + kcol8) * 2;
        __half* mrow = t_sm + i * NH_ * C_;   // t dead; reuse as m[i][h][k]
        #pragma unroll
        for (int kk = 0; kk < 4; kk++) {
            int kt = ks * 4 + kk;
            unsigned a0, a1, a2, a3;
            asm volatile(
                "ldmatrix.sync.aligned.m8n8.x4.trans.shared.b16 {%0,%1,%2,%3}, [%4];"
                : "=r"(a0), "=r"(a1), "=r"(a2), "=r"(a3)
                : "r"(a_base + kt * 32));
            float d[4] = {0.f, 0.f, 0.f, 0.f};
            asm volatile(
                "mma.sync.aligned.m16n8k16.row.col.f32.f16.f16.f32 "
                "{%0,%1,%2,%3}, {%4,%5,%6,%7}, {%8,%9}, {%0,%1,%2,%3};"
                : "+f"(d[0]), "+f"(d[1]), "+f"(d[2]), "+f"(d[3])
                : "r"(a0), "r"(a1), "r"(a2), "r"(a3), "r"(b0), "r"(b1));
            int k0 = kt * 16;
            mrow[(2 * t4) * C_ + k0 + g]         = __float2half_rn(d[0]);
            mrow[(2 * t4 + 1) * C_ + k0 + g]     = __float2half_rn(d[1]);
            mrow[(2 * t4) * C_ + k0 + g + 8]     = __float2half_rn(d[2]);
            mrow[(2 * t4 + 1) * C_ + k0 + g + 8] = __float2half_rn(d[3]);
        }
    }
    __syncthreads();

    // ---- copy m -> global (coalesced) ----
    {
        const uint4* ms = (const uint4*)t_sm;
        uint4* md = (uint4*)(g_m + (size_t)(b * Q_ + gq0) * NH_ * C_);
        md[tid] = ms[tid];
        md[tid + 512] = ms[tid + 512];
    }
}

// ---------------------------------------------------------------------------
// Kernel O (HMMA): out = m @ wv^T + bv. Unchanged (R12-proven).
// ---------------------------------------------------------------------------
__global__ __launch_bounds__(512, 2)
void out_kernel(const float* __restrict__ bv, float* __restrict__ out) {
    extern __shared__ __half m_sm[];

    const int tid  = threadIdx.x;
    const int r0   = blockIdx.x * MB;
    const int warp = tid >> 5;
    const int lane = tid & 31;

    {
        #pragma unroll
        for (int rep = 0; rep < 8; rep++) {
            int idx = tid + rep * 512;
            int row = idx >> 8;
            int seg = idx & 255;
            uint4 v = __ldg((const uint4*)(g_m + (size_t)(r0 + row) * NH_ * C_) + seg);
            *((uint4*)(m_sm + row * MPITCH) + seg) = v;
        }
    }
    __syncthreads();

    const int h   = warp >> 1;
    const int g   = lane >> 2;
    const int t4  = lane & 3;
    const int li   = (lane & 7) + ((lane >> 3) & 1) * 8;
    const int col8 = ((lane >> 4) & 1) * 8;
    unsigned int a_base = (unsigned int)__cvta_generic_to_shared(m_sm)
                        + (li * MPITCH + h * C_ + col8) * 2;

    float d0[2][4];
    #pragma unroll
    for (int nt = 0; nt < 2; nt++)
        #pragma unroll
        for (int e = 0; e < 4; e++) d0[nt][e] = 0.f;

    const uint2* wf = g_wvF + (size_t)(warp * 2) * 16 * 32;

    #pragma unroll
    for (int kc = 0; kc < 16; kc++) {
        unsigned a0, a1, a2, a3;
        asm volatile(
            "ldmatrix.sync.aligned.m8n8.x4.shared.b16 {%0,%1,%2,%3}, [%4];"
            : "=r"(a0), "=r"(a1), "=r"(a2), "=r"(a3)
            : "r"(a_base + kc * 32));
        uint2 b0 = __ldg(wf + kc * 32 + lane);
        uint2 b1 = __ldg(wf + (16 + kc) * 32 + lane);
        asm volatile(
            "mma.sync.aligned.m16n8k16.row.col.f32.f16.f16.f32 "
            "{%0,%1,%2,%3}, {%4,%5,%6,%7}, {%8,%9}, {%0,%1,%2,%3};"
            : "+f"(d0[0][0]), "+f"(d0[0][1]), "+f"(d0[0][2]), "+f"(d0[0][3])
            : "r"(a0), "r"(a1), "r"(a2), "r"(a3), "r"(b0.x), "r"(b0.y));
        asm volatile(
            "mma.sync.aligned.m16n8k16.row.col.f32.f16.f16.f32 "
            "{%0,%1,%2,%3}, {%4,%5,%6,%7}, {%8,%9}, {%0,%1,%2,%3};"
            : "+f"(d0[1][0]), "+f"(d0[1][1]), "+f"(d0[1][2]), "+f"(d0[1][3])
            : "r"(a0), "r"(a1), "r"(a2), "r"(a3), "r"(b1.x), "r"(b1.y));
    }

    #pragma unroll
    for (int nt = 0; nt < 2; nt++) {
        int c = warp * 16 + nt * 8 + 2 * t4;
        float bb0 = __ldg(bv + c);
        float bb1 = __ldg(bv + c + 1);
        float2 lo = make_float2(d0[nt][0] + bb0, d0[nt][1] + bb1);
        float2 hi = make_float2(d0[nt][2] + bb0, d0[nt][3] + bb1);
        *(float2*)(out + (size_t)(r0 + g) * C_ + c)     = lo;
        *(float2*)(out + (size_t)(r0 + g + 8) * C_ + c) = hi;
    }
}

// ---------------------------------------------------------------------------
extern "C" void kernel_launch(void* const* d_in, const int* in_sizes, int n_in,
                              void* d_out, int out_size) {
    const float* x   = (const float*)d_in[0];
    const float* q   = (const float*)d_in[1];
    const float* ref = (const float*)d_in[2];
    const float* wq  = (const float*)d_in[3];
    const float* bq  = (const float*)d_in[4];
    const float* wk  = (const float*)d_in[5];
    const float* bk  = (const float*)d_in[6];
    const float* wv  = (const float*)d_in[7];
    const float* bv  = (const float*)d_in[8];
    float* out = (float*)d_out;

    (void)in_sizes; (void)n_in; (void)out_size;

    pack_wF_kernel<<<dim3(32, 2), 512>>>(wq, wv);
    pack_wkF_kernel<<<256, 64>>>(wk);

    cudaFuncSetAttribute(prologue_kernel,
                         cudaFuncAttributeMaxDynamicSharedMemorySize, PROJ_SMEM);
    prologue_kernel<<<GRID1, 512, PROJ_SMEM>>>(x, q, bq, bk);

    cudaFuncSetAttribute(deform_attn_kernel,
                         cudaFuncAttributeMaxDynamicSharedMemorySize, SMEM_BYTES);
    deform_attn_kernel<<<dim3(Q_ / TQ, B_), 512, SMEM_BYTES>>>(ref);

    cudaFuncSetAttribute(out_kernel,
                         cudaFuncAttributeMaxDynamicSharedMemorySize, OUT_SMEM);
    out_kernel<<<(B_ * Q_) / MB, 512, OUT_SMEM>>>(bv, out);
}

// round 15
// speedup vs baseline: 2.2560x; 1.1399x over previous
#include <cuda_runtime.h>
#include <cuda_fp16.h>

#define B_  16
#define Q_  1000
#define N_  16
#define C_  256
#define H_  100
#define W_  100
#define HW_ 10000
#define NH_ 8
#define D_  32
#define TQ  4          // queries per fused block
#define MB  16         // rows per out/proj block
#define AP2 264        // A_sm row pitch in halves (528B, 16B-aligned)

// ---- fused kernel smem offsets (bytes) ----
#define OFF_A    0
#define SZ_A     (TQ*N_*AP2*2)          // 33792 half A[64][264]
#define OFF_T    (OFF_A + SZ_A)         // 33792 half t[4][8][256]; reused as m
#define SZ_T     (TQ*NH_*C_*2)          // 16384
#define OFF_SC   (OFF_T + SZ_T)         // 50176 float sc[4][8][16]
#define SZ_SC    (TQ*NH_*N_*4)          // 2048
#define OFF_AT   (OFF_SC + SZ_SC)       // 52224 half at2[4][8][16]
#define SZ_AT    (TQ*NH_*N_*2)          // 1024
#define OFF_U    (OFF_AT + SZ_AT)       // 53248 float u[32]
#define SZ_U     (TQ*NH_*4)             // 128
#define OFF_WT   (OFF_U + SZ_U)         // 53376 float4 wt[64]
#define SZ_WT    (TQ*N_*16)             // 1024
#define OFF_O4   (OFF_WT + SZ_WT)       // 54400 int4 o4[64] combined tap offsets
#define SZ_O4    (TQ*N_*16)             // 1024
#define SMEM_BYTES (OFF_O4 + SZ_O4)     // 55424 -> 3 blocks/SM

// out kernel: m staged [MB][2056] halves
#define MPITCH  2056
#define OUT_SMEM (MB*MPITCH*2)          // 65792

// proj role smem
#define QPITCH  264
#define PROJ_SMEM (2*MB*QPITCH*2)       // 16896

// role-split prologue grid
#define PRJ_BLOCKS ((B_*Q_)/MB)         // 1000
#define TRP_PAIRS  157
#define TRP_BLOCKS (TRP_PAIRS*8*B_)     // 20096
#define GRID1 (PRJ_BLOCKS + TRP_BLOCKS)

// device scratch
__device__ __half g_xt[B_ * HW_ * C_];
__device__ uint2  g_wqF[32 * 16 * 32];
__device__ uint2  g_wvF[32 * 16 * 32];
__device__ uint2  g_wkF[NH_ * 32 * 2 * 32];
__device__ __half g_t[(size_t)B_ * Q_ * NH_ * C_];
__device__ __half g_m[(size_t)B_ * Q_ * NH_ * C_];
__device__ float  g_u[(size_t)B_ * Q_ * NH_];

// ---------------------------------------------------------------------------
// Kernel 0a: build B-fragments for qp / out GEMMs
// ---------------------------------------------------------------------------
__global__ void pack_wF_kernel(const float* __restrict__ wq,
                               const float* __restrict__ wv) {
    const float* src = blockIdx.y == 0 ? wq : wv;
    uint2* dst = blockIdx.y == 0 ? g_wqF : g_wvF;
    int nt   = blockIdx.x;
    int kc   = threadIdx.x >> 5;
    int lane = threadIdx.x & 31;
    int g  = lane >> 2;
    int t4 = lane & 3;
    int c  = nt * 8 + g;
    int k0 = kc * 16 + 2 * t4;
    const float* wr = src + (size_t)c * C_;
    __half2 b0 = __floats2half2_rn(wr[k0],     wr[k0 + 1]);
    __half2 b1 = __floats2half2_rn(wr[k0 + 8], wr[k0 + 9]);
    uint2 r;
    r.x = *(unsigned*)&b0;
    r.y = *(unsigned*)&b1;
    dst[(nt * 16 + kc) * 32 + lane] = r;
}

// ---------------------------------------------------------------------------
// Kernel 0b: wk B-fragments for t GEMM
// ---------------------------------------------------------------------------
__global__ void pack_wkF_kernel(const float* __restrict__ wk) {
    int h    = blockIdx.x >> 5;
    int nt   = blockIdx.x & 31;
    int kc2  = threadIdx.x >> 5;
    int lane = threadIdx.x & 31;
    int g  = lane >> 2;
    int t4 = lane & 3;
    int row0 = h * D_ + kc2 * 16 + 2 * t4;
    int col  = nt * 8 + g;
    __half2 b0 = __floats2half2_rn(wk[(size_t)row0 * C_ + col],
                                   wk[(size_t)(row0 + 1) * C_ + col]);
    __half2 b1 = __floats2half2_rn(wk[(size_t)(row0 + 8) * C_ + col],
                                   wk[(size_t)(row0 + 9) * C_ + col]);
    uint2 r;
    r.x = *(unsigned*)&b0;
    r.y = *(unsigned*)&b1;
    g_wkF[((h * 32 + nt) * 2 + kc2) * 32 + lane] = r;
}

// ---------------------------------------------------------------------------
// Kernel 1: role-split prologue (HMMA proj + x-transpose). Unchanged (R13).
// ---------------------------------------------------------------------------
__global__ __launch_bounds__(512)
void prologue_kernel(const float* __restrict__ x,
                     const float* __restrict__ q,  const float* __restrict__ bq,
                     const float* __restrict__ bk) {
    extern __shared__ char psc[];
    const int tid = threadIdx.x;
    const int bid = blockIdx.x;

    if (bid >= PRJ_BLOCKS) {
        float* psm = (float*)psc;
        int t2  = bid - PRJ_BLOCKS;
        int pp  = t2 % TRP_PAIRS;
        int rem = t2 / TRP_PAIRS;
        int c0  = (rem & 7) * 32;
        int b   = rem >> 3;
        int half = tid >> 8;
        int t   = tid & 255;
        int tx  = t & 31;
        int ty  = t >> 5;
        int p0  = pp * 64 + half * 32;
        float (*tile)[33] = (float(*)[33])(psm + half * 32 * 33);

        #pragma unroll
        for (int dy = 0; dy < 32; dy += 8) {
            int c = c0 + ty + dy;
            int p = p0 + tx;
            float v = 0.f;
            if (p < HW_) v = x[(size_t)(b * C_ + c) * HW_ + p];
            tile[ty + dy][tx] = v;
        }
        __syncthreads();
        #pragma unroll
        for (int dy = 0; dy < 32; dy += 8) {
            int p = p0 + ty + dy;
            int c = c0 + tx;
            if (p < HW_)
                g_xt[(size_t)(b * HW_ + p) * C_ + c] =
                    __float2half_rn(tile[tx][ty + dy]);
        }
        return;
    }

    __half* q_sm  = (__half*)psc;
    __half* qp_sm = (__half*)psc + MB * QPITCH;
    const int r0   = bid * MB;
    const int warp = tid >> 5;
    const int lane = tid & 31;
    const int g    = lane >> 2;
    const int t4   = lane & 3;
    const int li   = (lane & 7) + ((lane >> 3) & 1) * 8;
    const int col8 = ((lane >> 4) & 1) * 8;

    #pragma unroll
    for (int rep = 0; rep < 4; rep++) {
        int idx  = tid + rep * 512;
        int row  = idx >> 7;
        int col2 = idx & 127;
        float2 v = __ldg((const float2*)(q + (size_t)(r0 + row) * C_) + col2);
        *(__half2*)(q_sm + row * QPITCH + col2 * 2) = __floats2half2_rn(v.x, v.y);
    }
    __syncthreads();

    unsigned int qs_s  = (unsigned int)__cvta_generic_to_shared(q_sm);
    unsigned int qps_s = (unsigned int)__cvta_generic_to_shared(qp_sm);

    {
        float d0[2][4];
        #pragma unroll
        for (int nt = 0; nt < 2; nt++)
            #pragma unroll
            for (int e = 0; e < 4; e++) d0[nt][e] = 0.f;
        unsigned int a_base = qs_s + (li * QPITCH + col8) * 2;
        const uint2* wf = g_wqF + (size_t)(warp * 2) * 16 * 32;
        #pragma unroll
        for (int kc = 0; kc < 16; kc++) {
            unsigned a0, a1, a2, a3;
            asm volatile(
                "ldmatrix.sync.aligned.m8n8.x4.shared.b16 {%0,%1,%2,%3}, [%4];"
                : "=r"(a0), "=r"(a1), "=r"(a2), "=r"(a3)
                : "r"(a_base + kc * 32));
            uint2 b0 = __ldg(wf + kc * 32 + lane);
            uint2 b1 = __ldg(wf + (16 + kc) * 32 + lane);
            asm volatile(
                "mma.sync.aligned.m16n8k16.row.col.f32.f16.f16.f32 "
                "{%0,%1,%2,%3}, {%4,%5,%6,%7}, {%8,%9}, {%0,%1,%2,%3};"
                : "+f"(d0[0][0]), "+f"(d0[0][1]), "+f"(d0[0][2]), "+f"(d0[0][3])
                : "r"(a0), "r"(a1), "r"(a2), "r"(a3), "r"(b0.x), "r"(b0.y));
            asm volatile(
                "mma.sync.aligned.m16n8k16.row.col.f32.f16.f16.f32 "
                "{%0,%1,%2,%3}, {%4,%5,%6,%7}, {%8,%9}, {%0,%1,%2,%3};"
                : "+f"(d0[1][0]), "+f"(d0[1][1]), "+f"(d0[1][2]), "+f"(d0[1][3])
                : "r"(a0), "r"(a1), "r"(a2), "r"(a3), "r"(b1.x), "r"(b1.y));
        }
        #pragma unroll
        for (int nt = 0; nt < 2; nt++) {
            int c = warp * 16 + nt * 8 + 2 * t4;
            float bb0 = __ldg(bq + c);
            float bb1 = __ldg(bq + c + 1);
            *(__half2*)(qp_sm + g * QPITCH + c) =
                __floats2half2_rn(d0[nt][0] + bb0, d0[nt][1] + bb1);
            *(__half2*)(qp_sm + (g + 8) * QPITCH + c) =
                __floats2half2_rn(d0[nt][2] + bb0, d0[nt][3] + bb1);
        }
    }
    __syncthreads();

    if (tid < MB * NH_) {
        int r = tid >> 3, h = tid & 7;
        float s = 0.f;
        #pragma unroll
        for (int dd = 0; dd < D_; dd++)
            s += __half2float(qp_sm[r * QPITCH + h * D_ + dd]) * __ldg(bk + h * D_ + dd);
        g_u[(size_t)(r0 + r) * NH_ + h] = s;
    }

    {
        const int h   = warp >> 1;
        const int nt0 = (warp & 1) * 16;
        unsigned int a_base = qps_s + (li * QPITCH + h * D_ + col8) * 2;
        unsigned aa[2][4];
        #pragma unroll
        for (int kc2 = 0; kc2 < 2; kc2++)
            asm volatile(
                "ldmatrix.sync.aligned.m8n8.x4.shared.b16 {%0,%1,%2,%3}, [%4];"
                : "=r"(aa[kc2][0]), "=r"(aa[kc2][1]),
                  "=r"(aa[kc2][2]), "=r"(aa[kc2][3])
                : "r"(a_base + kc2 * 32));
        #pragma unroll
        for (int nn = 0; nn < 16; nn++) {
            int ntile = nt0 + nn;
            const uint2* wf = g_wkF + (size_t)((h * 32 + ntile) * 2) * 32;
            uint2 b0 = __ldg(wf + lane);
            uint2 b1 = __ldg(wf + 32 + lane);
            float d0[4] = {0.f, 0.f, 0.f, 0.f};
            asm volatile(
                "mma.sync.aligned.m16n8k16.row.col.f32.f16.f16.f32 "
                "{%0,%1,%2,%3}, {%4,%5,%6,%7}, {%8,%9}, {%0,%1,%2,%3};"
                : "+f"(d0[0]), "+f"(d0[1]), "+f"(d0[2]), "+f"(d0[3])
                : "r"(aa[0][0]), "r"(aa[0][1]), "r"(aa[0][2]), "r"(aa[0][3]),
                  "r"(b0.x), "r"(b0.y));
            asm volatile(
                "mma.sync.aligned.m16n8k16.row.col.f32.f16.f16.f32 "
                "{%0,%1,%2,%3}, {%4,%5,%6,%7}, {%8,%9}, {%0,%1,%2,%3};"
                : "+f"(d0[0]), "+f"(d0[1]), "+f"(d0[2]), "+f"(d0[3])
                : "r"(aa[1][0]), "r"(aa[1][1]), "r"(aa[1][2]), "r"(aa[1][3]),
                  "r"(b1.x), "r"(b1.y));
            int col = ntile * 8 + 2 * t4;
            __half* tb = g_t + (size_t)(r0 + g) * NH_ * C_ + h * C_ + col;
            *(__half2*)tb = __floats2half2_rn(d0[0], d0[1]);
            *(__half2*)(tb + (size_t)8 * NH_ * C_) = __floats2half2_rn(d0[2], d0[3]);
        }
    }
}

// ---------------------------------------------------------------------------
// Kernel F: gather + HMMA scores + softmax + HMMA m. TQ=4, 512 thr, 3/SM.
// ---------------------------------------------------------------------------
__global__ __launch_bounds__(512, 3)
void deform_attn_kernel(const float* __restrict__ ref) {
    extern __shared__ char smc[];
    __half*  A_sm   = (__half*)(smc + OFF_A);
    __half*  t_sm   = (__half*)(smc + OFF_T);     // t, then m
    float*   sc_sm  = (float*)(smc + OFF_SC);
    __half*  at2_sm = (__half*)(smc + OFF_AT);    // attn fp16 [i][h][j]
    float*   u_sm   = (float*)(smc + OFF_U);
    float4*  wt_sm  = (float4*)(smc + OFF_WT);
    int4*    o4_sm  = (int4*)(smc + OFF_O4);

    const int tid  = threadIdx.x;
    const int b    = blockIdx.y;
    const int gq0  = blockIdx.x * TQ;
    const int warp = tid >> 5;
    const int lane = tid & 31;
    const int g    = lane >> 2;
    const int t4   = lane & 3;

    unsigned int A_s  = (unsigned int)__cvta_generic_to_shared(A_sm);
    unsigned int T_s  = (unsigned int)__cvta_generic_to_shared(t_sm);
    unsigned int AT_s = (unsigned int)__cvta_generic_to_shared(at2_sm);

    // ---- phase 0: ref precompute (combined tap offsets) + t/u load ----
    if (tid < TQ * N_) {
        int i  = tid >> 4, j = tid & 15;
        int rr = (gq0 + i) * N_ + j;
        int n  = rr / Q_;
        int qq = rr - n * Q_;
        float2 gr = __ldg((const float2*)(ref + (size_t)((b * Q_ + qq) * N_ + n) * 2));
        float gx = ((gr.x + 1.0f) * (float)W_ - 1.0f) * 0.5f;
        float gy = ((gr.y + 1.0f) * (float)H_ - 1.0f) * 0.5f;
        float x0f = floorf(gx), y0f = floorf(gy);
        float fx = gx - x0f, fy = gy - y0f;
        int x0 = (int)x0f, y0 = (int)y0f;
        int x1 = x0 + 1,   y1 = y0 + 1;
        bool vx0 = (x0 >= 0) & (x0 < W_);
        bool vx1 = (x1 >= 0) & (x1 < W_);
        bool vy0 = (y0 >= 0) & (y0 < H_);
        bool vy1 = (y1 >= 0) & (y1 < H_);
        float4 w;
        w.x = (vx0 && vy0) ? (1.f - fx) * (1.f - fy) : 0.f;
        w.y = (vx1 && vy0) ? fx * (1.f - fy)         : 0.f;
        w.z = (vx0 && vy1) ? (1.f - fx) * fy         : 0.f;
        w.w = (vx1 && vy1) ? fx * fy                 : 0.f;
        int x0c = min(max(x0, 0), W_ - 1) * C_;
        int x1c = min(max(x1, 0), W_ - 1) * C_;
        int y0c = min(max(y0, 0), H_ - 1) * W_ * C_;
        int y1c = min(max(y1, 0), H_ - 1) * W_ * C_;
        wt_sm[tid] = w;
        o4_sm[tid] = make_int4(y0c + x0c, y0c + x1c, y1c + x0c, y1c + x1c);
    }
    {
        const uint4* ts = (const uint4*)(g_t + (size_t)(b * Q_ + gq0) * NH_ * C_);
        uint4* td = (uint4*)t_sm;
        td[tid] = __ldg(ts + tid);
        td[tid + 512] = __ldg(ts + tid + 512);
    }
    if (tid < TQ * NH_)
        u_sm[tid] = __ldg(g_u + (size_t)(b * Q_ + gq0) * NH_ + tid);
    __syncthreads();

    // ---- gather: thread owns k-quad (uint2 of 4 halves); 8 rows each ----
    {
        const int k4 = tid & 63;             // uint2 index within row
        const int rg = tid >> 6;             // 0..7
        const __half* xb = g_xt + (size_t)b * HW_ * C_;
        #pragma unroll 4
        for (int row = rg; row < TQ * N_; row += 8) {
            float4 w = wt_sm[row];
            int4   o = o4_sm[row];
            uint2 v00 = __ldg((const uint2*)(xb + o.x) + k4);
            uint2 v01 = __ldg((const uint2*)(xb + o.y) + k4);
            uint2 v10 = __ldg((const uint2*)(xb + o.z) + k4);
            uint2 v11 = __ldg((const uint2*)(xb + o.w) + k4);
            float2 a00 = __half22float2(*(const __half2*)&v00.x);
            float2 b00 = __half22float2(*(const __half2*)&v00.y);
            float2 a01 = __half22float2(*(const __half2*)&v01.x);
            float2 b01 = __half22float2(*(const __half2*)&v01.y);
            float2 a10 = __half22float2(*(const __half2*)&v10.x);
            float2 b10 = __half22float2(*(const __half2*)&v10.y);
            float2 a11 = __half22float2(*(const __half2*)&v11.x);
            float2 b11 = __half22float2(*(const __half2*)&v11.y);
            float r0 = w.x * a00.x + w.y * a01.x + w.z * a10.x + w.w * a11.x;
            float r1 = w.x * a00.y + w.y * a01.y + w.z * a10.y + w.w * a11.y;
            float r2 = w.x * b00.x + w.y * b01.x + w.z * b10.x + w.w * b11.x;
            float r3 = w.x * b00.y + w.y * b01.y + w.z * b10.y + w.w * b11.y;
            __half2 h0 = __floats2half2_rn(r0, r1);
            __half2 h1 = __floats2half2_rn(r2, r3);
            uint2 pkt;
            pkt.x = *(unsigned*)&h0;
            pkt.y = *(unsigned*)&h1;
            *((uint2*)(A_sm + row * AP2) + k4) = pkt;
        }
    }
    __syncthreads();

    // ---- scores (HMMA): 4 warps, warp = query i, full K; write sc direct ----
    if (warp < TQ) {
        const int i = warp;
        const int li   = (lane & 7) + ((lane >> 3) & 1) * 8;
        const int col8 = ((lane >> 4) & 1) * 8;
        unsigned int a_base = A_s + ((i * N_ + li) * AP2 + col8) * 2;
        const int bl = lane & 15;
        unsigned int b_base = T_s + ((i * NH_ + (bl & 7)) * C_ + ((bl >> 3) & 1) * 8) * 2;
        float d[4] = {0.f, 0.f, 0.f, 0.f};
        #pragma unroll
        for (int kc = 0; kc < 16; kc++) {
            unsigned a0, a1, a2, a3, b0, b1;
            asm volatile(
                "ldmatrix.sync.aligned.m8n8.x4.shared.b16 {%0,%1,%2,%3}, [%4];"
                : "=r"(a0), "=r"(a1), "=r"(a2), "=r"(a3)
                : "r"(a_base + kc * 32));
            asm volatile(
                "ldmatrix.sync.aligned.m8n8.x2.shared.b16 {%0,%1}, [%2];"
                : "=r"(b0), "=r"(b1)
                : "r"(b_base + kc * 32));
            asm volatile(
                "mma.sync.aligned.m16n8k16.row.col.f32.f16.f16.f32 "
                "{%0,%1,%2,%3}, {%4,%5,%6,%7}, {%8,%9}, {%0,%1,%2,%3};"
                : "+f"(d[0]), "+f"(d[1]), "+f"(d[2]), "+f"(d[3])
                : "r"(a0), "r"(a1), "r"(a2), "r"(a3), "r"(b0), "r"(b1));
        }
        const float scale = 0.17677669529663687f;
        float u0 = u_sm[i * NH_ + 2 * t4];
        float u1 = u_sm[i * NH_ + 2 * t4 + 1];
        sc_sm[(i * NH_ + 2 * t4) * N_ + g]           = (d[0] + u0) * scale;
        sc_sm[(i * NH_ + 2 * t4 + 1) * N_ + g]       = (d[1] + u1) * scale;
        sc_sm[(i * NH_ + 2 * t4) * N_ + g + 8]       = (d[2] + u0) * scale;
        sc_sm[(i * NH_ + 2 * t4 + 1) * N_ + g + 8]   = (d[3] + u1) * scale;
    }
    __syncthreads();

    // ---- softmax over j per (i,h): 32 threads; attn fp16 [i][h][j] ----
    if (tid < TQ * NH_) {
        int i = tid >> 3, h = tid & 7;
        float s[N_];
        float mx = -1e30f;
        #pragma unroll
        for (int j = 0; j < N_; j++) {
            s[j] = sc_sm[(i * NH_ + h) * N_ + j];
            mx = fmaxf(mx, s[j]);
        }
        float sum = 0.f;
        #pragma unroll
        for (int j = 0; j < N_; j++) { s[j] = expf(s[j] - mx); sum += s[j]; }
        float inv = 1.f / sum;
        __half* dst = at2_sm + i * 128 + h * 16;
        #pragma unroll
        for (int j = 0; j < N_; j += 2)
            *(__half2*)(dst + j) = __floats2half2_rn(s[j] * inv, s[j + 1] * inv);
    }
    __syncthreads();

    // ---- m (HMMA): D[k16 x h8] = A^T . attn^T; warp = (i = w&3, ks = w>>2) ----
    {
        const int i  = warp & 3;
        const int ks = warp >> 2;
        const int bl = lane & 15;
        unsigned int b_addr = AT_s + (i * 128 + (bl & 7) * 16 + ((bl >> 3) & 1) * 8) * 2;
        unsigned b0, b1;
        asm volatile(
            "ldmatrix.sync.aligned.m8n8.x2.shared.b16 {%0,%1}, [%2];"
            : "=r"(b0), "=r"(b1) : "r"(b_addr));
        const int jrow  = (lane & 7) + ((lane >> 4) & 1) * 8;
        const int kcol8 = ((lane >> 3) & 1) * 8;
        unsigned int a_base = A_s + ((i * N_ + jrow) * AP2 + kcol8) * 2;
        __half* mrow = t_sm + i * NH_ * C_;
        #pragma unroll
        for (int kk = 0; kk < 4; kk++) {
            int kt = ks * 4 + kk;
            unsigned a0, a1, a2, a3;
            asm volatile(
                "ldmatrix.sync.aligned.m8n8.x4.trans.shared.b16 {%0,%1,%2,%3}, [%4];"
                : "=r"(a0), "=r"(a1), "=r"(a2), "=r"(a3)
                : "r"(a_base + kt * 32));
            float d[4] = {0.f, 0.f, 0.f, 0.f};
            asm volatile(
                "mma.sync.aligned.m16n8k16.row.col.f32.f16.f16.f32 "
                "{%0,%1,%2,%3}, {%4,%5,%6,%7}, {%8,%9}, {%0,%1,%2,%3};"
                : "+f"(d[0]), "+f"(d[1]), "+f"(d[2]), "+f"(d[3])
                : "r"(a0), "r"(a1), "r"(a2), "r"(a3), "r"(b0), "r"(b1));
            int k0 = kt * 16;
            mrow[(2 * t4) * C_ + k0 + g]         = __float2half_rn(d[0]);
            mrow[(2 * t4 + 1) * C_ + k0 + g]     = __float2half_rn(d[1]);
            mrow[(2 * t4) * C_ + k0 + g + 8]     = __float2half_rn(d[2]);
            mrow[(2 * t4 + 1) * C_ + k0 + g + 8] = __float2half_rn(d[3]);
        }
    }
    __syncthreads();

    // ---- copy m -> global (coalesced) ----
    {
        const uint4* ms = (const uint4*)t_sm;
        uint4* md = (uint4*)(g_m + (size_t)(b * Q_ + gq0) * NH_ * C_);
        md[tid] = ms[tid];
        md[tid + 512] = ms[tid + 512];
    }
}

// ---------------------------------------------------------------------------
// Kernel O (HMMA): out = m @ wv^T + bv. Unchanged (R12-proven).
// ---------------------------------------------------------------------------
__global__ __launch_bounds__(512, 2)
void out_kernel(const float* __restrict__ bv, float* __restrict__ out) {
    extern __shared__ __half m_sm[];

    const int tid  = threadIdx.x;
    const int r0   = blockIdx.x * MB;
    const int warp = tid >> 5;
    const int lane = tid & 31;

    {
        #pragma unroll
        for (int rep = 0; rep < 8; rep++) {
            int idx = tid + rep * 512;
            int row = idx >> 8;
            int seg = idx & 255;
            uint4 v = __ldg((const uint4*)(g_m + (size_t)(r0 + row) * NH_ * C_) + seg);
            *((uint4*)(m_sm + row * MPITCH) + seg) = v;
        }
    }
    __syncthreads();

    const int h   = warp >> 1;
    const int g   = lane >> 2;
    const int t4  = lane & 3;
    const int li   = (lane & 7) + ((lane >> 3) & 1) * 8;
    const int col8 = ((lane >> 4) & 1) * 8;
    unsigned int a_base = (unsigned int)__cvta_generic_to_shared(m_sm)
                        + (li * MPITCH + h * C_ + col8) * 2;

    float d0[2][4];
    #pragma unroll
    for (int nt = 0; nt < 2; nt++)
        #pragma unroll
        for (int e = 0; e < 4; e++) d0[nt][e] = 0.f;

    const uint2* wf = g_wvF + (size_t)(warp * 2) * 16 * 32;

    #pragma unroll
    for (int kc = 0; kc < 16; kc++) {
        unsigned a0, a1, a2, a3;
        asm volatile(
            "ldmatrix.sync.aligned.m8n8.x4.shared.b16 {%0,%1,%2,%3}, [%4];"
            : "=r"(a0), "=r"(a1), "=r"(a2), "=r"(a3)
            : "r"(a_base + kc * 32));
        uint2 b0 = __ldg(wf + kc * 32 + lane);
        uint2 b1 = __ldg(wf + (16 + kc) * 32 + lane);
        asm volatile(
            "mma.sync.aligned.m16n8k16.row.col.f32.f16.f16.f32 "
            "{%0,%1,%2,%3}, {%4,%5,%6,%7}, {%8,%9}, {%0,%1,%2,%3};"
            : "+f"(d0[0][0]), "+f"(d0[0][1]), "+f"(d0[0][2]), "+f"(d0[0][3])
            : "r"(a0), "r"(a1), "r"(a2), "r"(a3), "r"(b0.x), "r"(b0.y));
        asm volatile(
            "mma.sync.aligned.m16n8k16.row.col.f32.f16.f16.f32 "
            "{%0,%1,%2,%3}, {%4,%5,%6,%7}, {%8,%9}, {%0,%1,%2,%3};"
            : "+f"(d0[1][0]), "+f"(d0[1][1]), "+f"(d0[1][2]), "+f"(d0[1][3])
            : "r"(a0), "r"(a1), "r"(a2), "r"(a3), "r"(b1.x), "r"(b1.y));
    }

    #pragma unroll
    for (int nt = 0; nt < 2; nt++) {
        int c = warp * 16 + nt * 8 + 2 * t4;
        float bb0 = __ldg(bv + c);
        float bb1 = __ldg(bv + c + 1);
        float2 lo = make_float2(d0[nt][0] + bb0, d0[nt][1] + bb1);
        float2 hi = make_float2(d0[nt][2] + bb0, d0[nt][3] + bb1);
        *(float2*)(out + (size_t)(r0 + g) * C_ + c)     = lo;
        *(float2*)(out + (size_t)(r0 + g + 8) * C_ + c) = hi;
    }
}

// ---------------------------------------------------------------------------
extern "C" void kernel_launch(void* const* d_in, const int* in_sizes, int n_in,
                              void* d_out, int out_size) {
    const float* x   = (const float*)d_in[0];
    const float* q   = (const float*)d_in[1];
    const float* ref = (const float*)d_in[2];
    const float* wq  = (const float*)d_in[3];
    const float* bq  = (const float*)d_in[4];
    const float* wk  = (const float*)d_in[5];
    const float* bk  = (const float*)d_in[6];
    const float* wv  = (const float*)d_in[7];
    const float* bv  = (const float*)d_in[8];
    float* out = (float*)d_out;

    (void)in_sizes; (void)n_in; (void)out_size;

    pack_wF_kernel<<<dim3(32, 2), 512>>>(wq, wv);
    pack_wkF_kernel<<<256, 64>>>(wk);

    cudaFuncSetAttribute(prologue_kernel,
                         cudaFuncAttributeMaxDynamicSharedMemorySize, PROJ_SMEM);
    prologue_kernel<<<GRID1, 512, PROJ_SMEM>>>(x, q, bq, bk);

    cudaFuncSetAttribute(deform_attn_kernel,
                         cudaFuncAttributeMaxDynamicSharedMemorySize, SMEM_BYTES);
    deform_attn_kernel<<<dim3(Q_ / TQ, B_), 512, SMEM_BYTES>>>(ref);

    cudaFuncSetAttribute(out_kernel,
                         cudaFuncAttributeMaxDynamicSharedMemorySize, OUT_SMEM);
    out_kernel<<<(B_ * Q_) / MB, 512, OUT_SMEM>>>(bv, out);
}

// round 17
// speedup vs baseline: 2.3417x; 1.0380x over previous
#include <cuda_runtime.h>
#include <cuda_fp16.h>

#define B_  16
#define Q_  1000
#define N_  16
#define C_  256
#define H_  100
#define W_  100
#define HW_ 10000
#define NH_ 8
#define D_  32
#define TQ  4          // queries per fused block
#define MB  16         // rows per out/proj block
#define AP2 264        // A_sm row pitch in halves (528B, 16B-aligned)

// ---- fused kernel smem offsets (bytes) ----
#define OFF_A    0
#define SZ_A     (TQ*N_*AP2*2)          // 33792 half A[64][264]
#define OFF_T    (OFF_A + SZ_A)         // 33792 half t[4][8][256]; reused as m
#define SZ_T     (TQ*NH_*C_*2)          // 16384
#define OFF_SC   (OFF_T + SZ_T)         // 50176 float sc[4][8][16]
#define SZ_SC    (TQ*NH_*N_*4)          // 2048
#define OFF_AT   (OFF_SC + SZ_SC)       // 52224 half at2[4][8][16]
#define SZ_AT    (TQ*NH_*N_*2)          // 1024
#define OFF_U    (OFF_AT + SZ_AT)       // 53248 float u[32]
#define SZ_U     (TQ*NH_*4)             // 128
#define OFF_WT   (OFF_U + SZ_U)         // 53376 float4 wt[64]
#define SZ_WT    (TQ*N_*16)             // 1024
#define OFF_O4   (OFF_WT + SZ_WT)       // 54400 int4 o4[64]
#define SZ_O4    (TQ*N_*16)             // 1024
#define SMEM_BYTES (OFF_O4 + SZ_O4)     // 55424 -> 3 blocks/SM

// out kernel: m staged [MB][2056] halves
#define MPITCH  2056
#define OUT_SMEM (MB*MPITCH*2)          // 65792

// proj role smem
#define QPITCH  264
#define PROJ_SMEM (2*MB*QPITCH*2)       // 16896 (>= transpose tile 8448)

// role-split prologue grid: proj + transpose (32p x 64c tiles)
#define PRJ_BLOCKS ((B_*Q_)/MB)         // 1000
#define TRP_PT     313                  // ceil(10000/32)
#define TRP_BLOCKS (TRP_PT*4*B_)        // 20032
#define GRID1 (PRJ_BLOCKS + TRP_BLOCKS)

// device scratch
__device__ __half g_xt[B_ * HW_ * C_];
__device__ uint2  g_wqF[32 * 16 * 32];
__device__ uint2  g_wvF[32 * 16 * 32];
__device__ uint2  g_wkF[NH_ * 32 * 2 * 32];
__device__ __half g_t[(size_t)B_ * Q_ * NH_ * C_];
__device__ __half g_m[(size_t)B_ * Q_ * NH_ * C_];
__device__ float  g_u[(size_t)B_ * Q_ * NH_];

// ---------------------------------------------------------------------------
// Kernel 0a: build B-fragments for qp / out GEMMs
// ---------------------------------------------------------------------------
__global__ void pack_wF_kernel(const float* __restrict__ wq,
                               const float* __restrict__ wv) {
    const float* src = blockIdx.y == 0 ? wq : wv;
    uint2* dst = blockIdx.y == 0 ? g_wqF : g_wvF;
    int nt   = blockIdx.x;
    int kc   = threadIdx.x >> 5;
    int lane = threadIdx.x & 31;
    int g  = lane >> 2;
    int t4 = lane & 3;
    int c  = nt * 8 + g;
    int k0 = kc * 16 + 2 * t4;
    const float* wr = src + (size_t)c * C_;
    __half2 b0 = __floats2half2_rn(wr[k0],     wr[k0 + 1]);
    __half2 b1 = __floats2half2_rn(wr[k0 + 8], wr[k0 + 9]);
    uint2 r;
    r.x = *(unsigned*)&b0;
    r.y = *(unsigned*)&b1;
    dst[(nt * 16 + kc) * 32 + lane] = r;
}

// ---------------------------------------------------------------------------
// Kernel 0b: wk B-fragments for t GEMM
// ---------------------------------------------------------------------------
__global__ void pack_wkF_kernel(const float* __restrict__ wk) {
    int h    = blockIdx.x >> 5;
    int nt   = blockIdx.x & 31;
    int kc2  = threadIdx.x >> 5;
    int lane = threadIdx.x & 31;
    int g  = lane >> 2;
    int t4 = lane & 3;
    int row0 = h * D_ + kc2 * 16 + 2 * t4;
    int col  = nt * 8 + g;
    __half2 b0 = __floats2half2_rn(wk[(size_t)row0 * C_ + col],
                                   wk[(size_t)(row0 + 1) * C_ + col]);
    __half2 b1 = __floats2half2_rn(wk[(size_t)(row0 + 8) * C_ + col],
                                   wk[(size_t)(row0 + 9) * C_ + col]);
    uint2 r;
    r.x = *(unsigned*)&b0;
    r.y = *(unsigned*)&b1;
    g_wkF[((h * 32 + nt) * 2 + kc2) * 32 + lane] = r;
}

// ---------------------------------------------------------------------------
// Kernel 1: role-split prologue (HMMA proj + wide-store x-transpose).
// ---------------------------------------------------------------------------
__global__ __launch_bounds__(512)
void prologue_kernel(const float* __restrict__ x,
                     const float* __restrict__ q,  const float* __restrict__ bq,
                     const float* __restrict__ bk) {
    extern __shared__ char psc[];
    const int tid = threadIdx.x;
    const int bid = blockIdx.x;

    if (bid >= PRJ_BLOCKS) {
        // ===== TRANSPOSE ROLE: tile = 32 HW-positions x 64 channels =====
        float (*tile)[33] = (float(*)[33])psc;     // [64][33] fp32
        int t2  = bid - PRJ_BLOCKS;
        int pt  = t2 % TRP_PT;
        int rem = t2 / TRP_PT;
        int ct  = rem & 3;
        int b   = rem >> 2;
        int p0  = pt * 32;
        int c0  = ct * 64;
        const int warp = tid >> 5;
        const int lane = tid & 31;

        // load: warp owns c-rows (4 iterations), 128B coalesced
        #pragma unroll
        for (int it = 0; it < 4; it++) {
            int cc = warp + 16 * it;               // 0..63
            int p  = p0 + lane;
            float v = 0.f;
            if (p < HW_) v = x[(size_t)(b * C_ + c0 + cc) * HW_ + p];
            tile[cc][lane] = v;
        }
        __syncthreads();

        // store: warp owns p-row (2 iterations), 128B half2 stores
        #pragma unroll
        for (int it = 0; it < 2; it++) {
            int pp = warp + 16 * it;               // 0..31
            int p  = p0 + pp;
            if (p < HW_) {
                float lo = tile[2 * lane][pp];
                float hi = tile[2 * lane + 1][pp];
                *(__half2*)(g_xt + (size_t)(b * HW_ + p) * C_ + c0 + 2 * lane) =
                    __floats2half2_rn(lo, hi);
            }
        }
        return;
    }

    // =============== PROJ ROLE (HMMA, R13-proven) ===============
    __half* q_sm  = (__half*)psc;
    __half* qp_sm = (__half*)psc + MB * QPITCH;
    const int r0   = bid * MB;
    const int warp = tid >> 5;
    const int lane = tid & 31;
    const int g    = lane >> 2;
    const int t4   = lane & 3;
    const int li   = (lane & 7) + ((lane >> 3) & 1) * 8;
    const int col8 = ((lane >> 4) & 1) * 8;

    #pragma unroll
    for (int rep = 0; rep < 4; rep++) {
        int idx  = tid + rep * 512;
        int row  = idx >> 7;
        int col2 = idx & 127;
        float2 v = __ldg((const float2*)(q + (size_t)(r0 + row) * C_) + col2);
        *(__half2*)(q_sm + row * QPITCH + col2 * 2) = __floats2half2_rn(v.x, v.y);
    }
    __syncthreads();

    unsigned int qs_s  = (unsigned int)__cvta_generic_to_shared(q_sm);
    unsigned int qps_s = (unsigned int)__cvta_generic_to_shared(qp_sm);

    {
        float d0[2][4];
        #pragma unroll
        for (int nt = 0; nt < 2; nt++)
            #pragma unroll
            for (int e = 0; e < 4; e++) d0[nt][e] = 0.f;
        unsigned int a_base = qs_s + (li * QPITCH + col8) * 2;
        const uint2* wf = g_wqF + (size_t)(warp * 2) * 16 * 32;
        #pragma unroll
        for (int kc = 0; kc < 16; kc++) {
            unsigned a0, a1, a2, a3;
            asm volatile(
                "ldmatrix.sync.aligned.m8n8.x4.shared.b16 {%0,%1,%2,%3}, [%4];"
                : "=r"(a0), "=r"(a1), "=r"(a2), "=r"(a3)
                : "r"(a_base + kc * 32));
            uint2 b0 = __ldg(wf + kc * 32 + lane);
            uint2 b1 = __ldg(wf + (16 + kc) * 32 + lane);
            asm volatile(
                "mma.sync.aligned.m16n8k16.row.col.f32.f16.f16.f32 "
                "{%0,%1,%2,%3}, {%4,%5,%6,%7}, {%8,%9}, {%0,%1,%2,%3};"
                : "+f"(d0[0][0]), "+f"(d0[0][1]), "+f"(d0[0][2]), "+f"(d0[0][3])
                : "r"(a0), "r"(a1), "r"(a2), "r"(a3), "r"(b0.x), "r"(b0.y));
            asm volatile(
                "mma.sync.aligned.m16n8k16.row.col.f32.f16.f16.f32 "
                "{%0,%1,%2,%3}, {%4,%5,%6,%7}, {%8,%9}, {%0,%1,%2,%3};"
                : "+f"(d0[1][0]), "+f"(d0[1][1]), "+f"(d0[1][2]), "+f"(d0[1][3])
                : "r"(a0), "r"(a1), "r"(a2), "r"(a3), "r"(b1.x), "r"(b1.y));
        }
        #pragma unroll
        for (int nt = 0; nt < 2; nt++) {
            int c = warp * 16 + nt * 8 + 2 * t4;
            float bb0 = __ldg(bq + c);
            float bb1 = __ldg(bq + c + 1);
            *(__half2*)(qp_sm + g * QPITCH + c) =
                __floats2half2_rn(d0[nt][0] + bb0, d0[nt][1] + bb1);
            *(__half2*)(qp_sm + (g + 8) * QPITCH + c) =
                __floats2half2_rn(d0[nt][2] + bb0, d0[nt][3] + bb1);
        }
    }
    __syncthreads();

    if (tid < MB * NH_) {
        int r = tid >> 3, h = tid & 7;
        float s = 0.f;
        #pragma unroll
        for (int dd = 0; dd < D_; dd++)
            s += __half2float(qp_sm[r * QPITCH + h * D_ + dd]) * __ldg(bk + h * D_ + dd);
        g_u[(size_t)(r0 + r) * NH_ + h] = s;
    }

    {
        const int h   = warp >> 1;
        const int nt0 = (warp & 1) * 16;
        unsigned int a_base = qps_s + (li * QPITCH + h * D_ + col8) * 2;
        unsigned aa[2][4];
        #pragma unroll
        for (int kc2 = 0; kc2 < 2; kc2++)
            asm volatile(
                "ldmatrix.sync.aligned.m8n8.x4.shared.b16 {%0,%1,%2,%3}, [%4];"
                : "=r"(aa[kc2][0]), "=r"(aa[kc2][1]),
                  "=r"(aa[kc2][2]), "=r"(aa[kc2][3])
                : "r"(a_base + kc2 * 32));
        #pragma unroll
        for (int nn = 0; nn < 16; nn++) {
            int ntile = nt0 + nn;
            const uint2* wf = g_wkF + (size_t)((h * 32 + ntile) * 2) * 32;
            uint2 b0 = __ldg(wf + lane);
            uint2 b1 = __ldg(wf + 32 + lane);
            float d0[4] = {0.f, 0.f, 0.f, 0.f};
            asm volatile(
                "mma.sync.aligned.m16n8k16.row.col.f32.f16.f16.f32 "
                "{%0,%1,%2,%3}, {%4,%5,%6,%7}, {%8,%9}, {%0,%1,%2,%3};"
                : "+f"(d0[0]), "+f"(d0[1]), "+f"(d0[2]), "+f"(d0[3])
                : "r"(aa[0][0]), "r"(aa[0][1]), "r"(aa[0][2]), "r"(aa[0][3]),
                  "r"(b0.x), "r"(b0.y));
            asm volatile(
                "mma.sync.aligned.m16n8k16.row.col.f32.f16.f16.f32 "
                "{%0,%1,%2,%3}, {%4,%5,%6,%7}, {%8,%9}, {%0,%1,%2,%3};"
                : "+f"(d0[0]), "+f"(d0[1]), "+f"(d0[2]), "+f"(d0[3])
                : "r"(aa[1][0]), "r"(aa[1][1]), "r"(aa[1][2]), "r"(aa[1][3]),
                  "r"(b1.x), "r"(b1.y));
            int col = ntile * 8 + 2 * t4;
            __half* tb = g_t + (size_t)(r0 + g) * NH_ * C_ + h * C_ + col;
            *(__half2*)tb = __floats2half2_rn(d0[0], d0[1]);
            *(__half2*)(tb + (size_t)8 * NH_ * C_) = __floats2half2_rn(d0[2], d0[3]);
        }
    }
}

// ---------------------------------------------------------------------------
// Kernel F: gather (LDG.128) + HMMA scores + softmax + HMMA m. 512 thr, 3/SM.
// ---------------------------------------------------------------------------
__global__ __launch_bounds__(512, 3)
void deform_attn_kernel(const float* __restrict__ ref) {
    extern __shared__ char smc[];
    __half*  A_sm   = (__half*)(smc + OFF_A);
    __half*  t_sm   = (__half*)(smc + OFF_T);     // t, then m
    float*   sc_sm  = (float*)(smc + OFF_SC);
    __half*  at2_sm = (__half*)(smc + OFF_AT);    // attn fp16 [i][h][j]
    float*   u_sm   = (float*)(smc + OFF_U);
    float4*  wt_sm  = (float4*)(smc + OFF_WT);
    int4*    o4_sm  = (int4*)(smc + OFF_O4);

    const int tid  = threadIdx.x;
    const int b    = blockIdx.y;
    const int gq0  = blockIdx.x * TQ;
    const int warp = tid >> 5;
    const int lane = tid & 31;
    const int g    = lane >> 2;
    const int t4   = lane & 3;

    unsigned int A_s  = (unsigned int)__cvta_generic_to_shared(A_sm);
    unsigned int T_s  = (unsigned int)__cvta_generic_to_shared(t_sm);
    unsigned int AT_s = (unsigned int)__cvta_generic_to_shared(at2_sm);

    // ---- phase 0: ref precompute (combined tap offsets) + t/u load ----
    if (tid < TQ * N_) {
        int i  = tid >> 4, j = tid & 15;
        int rr = (gq0 + i) * N_ + j;
        int n  = rr / Q_;
        int qq = rr - n * Q_;
        float2 gr = __ldg((const float2*)(ref + (size_t)((b * Q_ + qq) * N_ + n) * 2));
        float gx = ((gr.x + 1.0f) * (float)W_ - 1.0f) * 0.5f;
        float gy = ((gr.y + 1.0f) * (float)H_ - 1.0f) * 0.5f;
        float x0f = floorf(gx), y0f = floorf(gy);
        float fx = gx - x0f, fy = gy - y0f;
        int x0 = (int)x0f, y0 = (int)y0f;
        int x1 = x0 + 1,   y1 = y0 + 1;
        bool vx0 = (x0 >= 0) & (x0 < W_);
        bool vx1 = (x1 >= 0) & (x1 < W_);
        bool vy0 = (y0 >= 0) & (y0 < H_);
        bool vy1 = (y1 >= 0) & (y1 < H_);
        float4 w;
        w.x = (vx0 && vy0) ? (1.f - fx) * (1.f - fy) : 0.f;
        w.y = (vx1 && vy0) ? fx * (1.f - fy)         : 0.f;
        w.z = (vx0 && vy1) ? (1.f - fx) * fy         : 0.f;
        w.w = (vx1 && vy1) ? fx * fy                 : 0.f;
        int x0c = min(max(x0, 0), W_ - 1) * C_;
        int x1c = min(max(x1, 0), W_ - 1) * C_;
        int y0c = min(max(y0, 0), H_ - 1) * W_ * C_;
        int y1c = min(max(y1, 0), H_ - 1) * W_ * C_;
        wt_sm[tid] = w;
        o4_sm[tid] = make_int4(y0c + x0c, y0c + x1c, y1c + x0c, y1c + x1c);
    }
    {
        const uint4* ts = (const uint4*)(g_t + (size_t)(b * Q_ + gq0) * NH_ * C_);
        uint4* td = (uint4*)t_sm;
        td[tid] = __ldg(ts + tid);
        td[tid + 512] = __ldg(ts + tid + 512);
    }
    if (tid < TQ * NH_)
        u_sm[tid] = __ldg(g_u + (size_t)(b * Q_ + gq0) * NH_ + tid);
    __syncthreads();

    // ---- gather: thread owns k-octet (uint4 = 8 halves); 4 rows each ----
    // 64 rows x 32 uint4 = 2048 packets; 512 thr x 4 = 2048. Full coverage.
    {
        const int k8 = tid & 31;             // uint4 index within row (32/row)
        const int rg = tid >> 5;             // 0..15
        const __half* xb = g_xt + (size_t)b * HW_ * C_;
        #pragma unroll
        for (int rr = 0; rr < 4; rr++) {
            int row = rg + rr * 16;
            float4 w = wt_sm[row];
            int4   o = o4_sm[row];
            uint4 v0 = __ldg((const uint4*)(xb + o.x) + k8);
            uint4 v1 = __ldg((const uint4*)(xb + o.y) + k8);
            uint4 v2 = __ldg((const uint4*)(xb + o.z) + k8);
            uint4 v3 = __ldg((const uint4*)(xb + o.w) + k8);
            uint4 pkt;
            const unsigned* p0 = &v0.x;
            const unsigned* p1 = &v1.x;
            const unsigned* p2 = &v2.x;
            const unsigned* p3 = &v3.x;
            unsigned* po = &pkt.x;
            #pragma unroll
            for (int e = 0; e < 4; e++) {
                float2 a = __half22float2(*(const __half2*)&p0[e]);
                float2 bb = __half22float2(*(const __half2*)&p1[e]);
                float2 c = __half22float2(*(const __half2*)&p2[e]);
                float2 d = __half22float2(*(const __half2*)&p3[e]);
                float rx = w.x * a.x + w.y * bb.x + w.z * c.x + w.w * d.x;
                float ry = w.x * a.y + w.y * bb.y + w.z * c.y + w.w * d.y;
                __half2 hv = __floats2half2_rn(rx, ry);
                po[e] = *(unsigned*)&hv;
            }
            *((uint4*)(A_sm + row * AP2) + k8) = pkt;
        }
    }
    __syncthreads();

    // ---- scores (HMMA): 4 warps, warp = query i, full K; write sc direct ----
    if (warp < TQ) {
        const int i = warp;
        const int li   = (lane & 7) + ((lane >> 3) & 1) * 8;
        const int col8 = ((lane >> 4) & 1) * 8;
        unsigned int a_base = A_s + ((i * N_ + li) * AP2 + col8) * 2;
        const int bl = lane & 15;
        unsigned int b_base = T_s + ((i * NH_ + (bl & 7)) * C_ + ((bl >> 3) & 1) * 8) * 2;
        float d[4] = {0.f, 0.f, 0.f, 0.f};
        #pragma unroll
        for (int kc = 0; kc < 16; kc++) {
            unsigned a0, a1, a2, a3, b0, b1;
            asm volatile(
                "ldmatrix.sync.aligned.m8n8.x4.shared.b16 {%0,%1,%2,%3}, [%4];"
                : "=r"(a0), "=r"(a1), "=r"(a2), "=r"(a3)
                : "r"(a_base + kc * 32));
            asm volatile(
                "ldmatrix.sync.aligned.m8n8.x2.shared.b16 {%0,%1}, [%2];"
                : "=r"(b0), "=r"(b1)
                : "r"(b_base + kc * 32));
            asm volatile(
                "mma.sync.aligned.m16n8k16.row.col.f32.f16.f16.f32 "
                "{%0,%1,%2,%3}, {%4,%5,%6,%7}, {%8,%9}, {%0,%1,%2,%3};"
                : "+f"(d[0]), "+f"(d[1]), "+f"(d[2]), "+f"(d[3])
                : "r"(a0), "r"(a1), "r"(a2), "r"(a3), "r"(b0), "r"(b1));
        }
        const float scale = 0.17677669529663687f;
        float u0 = u_sm[i * NH_ + 2 * t4];
        float u1 = u_sm[i * NH_ + 2 * t4 + 1];
        sc_sm[(i * NH_ + 2 * t4) * N_ + g]           = (d[0] + u0) * scale;
        sc_sm[(i * NH_ + 2 * t4 + 1) * N_ + g]       = (d[1] + u1) * scale;
        sc_sm[(i * NH_ + 2 * t4) * N_ + g + 8]       = (d[2] + u0) * scale;
        sc_sm[(i * NH_ + 2 * t4 + 1) * N_ + g + 8]   = (d[3] + u1) * scale;
    }
    __syncthreads();

    // ---- softmax over j per (i,h): 32 threads; attn fp16 [i][h][j] ----
    if (tid < TQ * NH_) {
        int i = tid >> 3, h = tid & 7;
        float s[N_];
        float mx = -1e30f;
        #pragma unroll
        for (int j = 0; j < N_; j++) {
            s[j] = sc_sm[(i * NH_ + h) * N_ + j];
            mx = fmaxf(mx, s[j]);
        }
        float sum = 0.f;
        #pragma unroll
        for (int j = 0; j < N_; j++) { s[j] = expf(s[j] - mx); sum += s[j]; }
        float inv = 1.f / sum;
        __half* dst = at2_sm + i * 128 + h * 16;
        #pragma unroll
        for (int j = 0; j < N_; j += 2)
            *(__half2*)(dst + j) = __floats2half2_rn(s[j] * inv, s[j + 1] * inv);
    }
    __syncthreads();

    // ---- m (HMMA): D[k16 x h8] = A^T . attn^T; warp = (i = w&3, ks = w>>2) ----
    {
        const int i  = warp & 3;
        const int ks = warp >> 2;
        const int bl = lane & 15;
        unsigned int b_addr = AT_s + (i * 128 + (bl & 7) * 16 + ((bl >> 3) & 1) * 8) * 2;
        unsigned b0, b1;
        asm volatile(
            "ldmatrix.sync.aligned.m8n8.x2.shared.b16 {%0,%1}, [%2];"
            : "=r"(b0), "=r"(b1) : "r"(b_addr));
        const int jrow  = (lane & 7) + ((lane >> 4) & 1) * 8;
        const int kcol8 = ((lane >> 3) & 1) * 8;
        unsigned int a_base = A_s + ((i * N_ + jrow) * AP2 + kcol8) * 2;
        __half* mrow = t_sm + i * NH_ * C_;
        #pragma unroll
        for (int kk = 0; kk < 4; kk++) {
            int kt = ks * 4 + kk;
            unsigned a0, a1, a2, a3;
            asm volatile(
                "ldmatrix.sync.aligned.m8n8.x4.trans.shared.b16 {%0,%1,%2,%3}, [%4];"
                : "=r"(a0), "=r"(a1), "=r"(a2), "=r"(a3)
                : "r"(a_base + kt * 32));
            float d[4] = {0.f, 0.f, 0.f, 0.f};
            asm volatile(
                "mma.sync.aligned.m16n8k16.row.col.f32.f16.f16.f32 "
                "{%0,%1,%2,%3}, {%4,%5,%6,%7}, {%8,%9}, {%0,%1,%2,%3};"
                : "+f"(d[0]), "+f"(d[1]), "+f"(d[2]), "+f"(d[3])
                : "r"(a0), "r"(a1), "r"(a2), "r"(a3), "r"(b0), "r"(b1));
            int k0 = kt * 16;
            mrow[(2 * t4) * C_ + k0 + g]         = __float2half_rn(d[0]);
            mrow[(2 * t4 + 1) * C_ + k0 + g]     = __float2half_rn(d[1]);
            mrow[(2 * t4) * C_ + k0 + g + 8]     = __float2half_rn(d[2]);
            mrow[(2 * t4 + 1) * C_ + k0 + g + 8] = __float2half_rn(d[3]);
        }
    }
    __syncthreads();

    // ---- copy m -> global (coalesced) ----
    {
        const uint4* ms = (const uint4*)t_sm;
        uint4* md = (uint4*)(g_m + (size_t)(b * Q_ + gq0) * NH_ * C_);
        md[tid] = ms[tid];
        md[tid + 512] = ms[tid + 512];
    }
}

// ---------------------------------------------------------------------------
// Kernel O (HMMA): out = m @ wv^T + bv. Unchanged (R12-proven).
// ---------------------------------------------------------------------------
__global__ __launch_bounds__(512, 2)
void out_kernel(const float* __restrict__ bv, float* __restrict__ out) {
    extern __shared__ __half m_sm[];

    const int tid  = threadIdx.x;
    const int r0   = blockIdx.x * MB;
    const int warp = tid >> 5;
    const int lane = tid & 31;

    {
        #pragma unroll
        for (int rep = 0; rep < 8; rep++) {
            int idx = tid + rep * 512;
            int row = idx >> 8;
            int seg = idx & 255;
            uint4 v = __ldg((const uint4*)(g_m + (size_t)(r0 + row) * NH_ * C_) + seg);
            *((uint4*)(m_sm + row * MPITCH) + seg) = v;
        }
    }
    __syncthreads();

    const int h   = warp >> 1;
    const int g   = lane >> 2;
    const int t4  = lane & 3;
    const int li   = (lane & 7) + ((lane >> 3) & 1) * 8;
    const int col8 = ((lane >> 4) & 1) * 8;
    unsigned int a_base = (unsigned int)__cvta_generic_to_shared(m_sm)
                        + (li * MPITCH + h * C_ + col8) * 2;

    float d0[2][4];
    #pragma unroll
    for (int nt = 0; nt < 2; nt++)
        #pragma unroll
        for (int e = 0; e < 4; e++) d0[nt][e] = 0.f;

    const uint2* wf = g_wvF + (size_t)(warp * 2) * 16 * 32;

    #pragma unroll
    for (int kc = 0; kc < 16; kc++) {
        unsigned a0, a1, a2, a3;
        asm volatile(
            "ldmatrix.sync.aligned.m8n8.x4.shared.b16 {%0,%1,%2,%3}, [%4];"
            : "=r"(a0), "=r"(a1), "=r"(a2), "=r"(a3)
            : "r"(a_base + kc * 32));
        uint2 b0 = __ldg(wf + kc * 32 + lane);
        uint2 b1 = __ldg(wf + (16 + kc) * 32 + lane);
        asm volatile(
            "mma.sync.aligned.m16n8k16.row.col.f32.f16.f16.f32 "
            "{%0,%1,%2,%3}, {%4,%5,%6,%7}, {%8,%9}, {%0,%1,%2,%3};"
            : "+f"(d0[0][0]), "+f"(d0[0][1]), "+f"(d0[0][2]), "+f"(d0[0][3])
            : "r"(a0), "r"(a1), "r"(a2), "r"(a3), "r"(b0.x), "r"(b0.y));
        asm volatile(
            "mma.sync.aligned.m16n8k16.row.col.f32.f16.f16.f32 "
            "{%0,%1,%2,%3}, {%4,%5,%6,%7}, {%8,%9}, {%0,%1,%2,%3};"
            : "+f"(d0[1][0]), "+f"(d0[1][1]), "+f"(d0[1][2]), "+f"(d0[1][3])
            : "r"(a0), "r"(a1), "r"(a2), "r"(a3), "r"(b1.x), "r"(b1.y));
    }

    #pragma unroll
    for (int nt = 0; nt < 2; nt++) {
        int c = warp * 16 + nt * 8 + 2 * t4;
        float bb0 = __ldg(bv + c);
        float bb1 = __ldg(bv + c + 1);
        float2 lo = make_float2(d0[nt][0] + bb0, d0[nt][1] + bb1);
        float2 hi = make_float2(d0[nt][2] + bb0, d0[nt][3] + bb1);
        *(float2*)(out + (size_t)(r0 + g) * C_ + c)     = lo;
        *(float2*)(out + (size_t)(r0 + g + 8) * C_ + c) = hi;
    }
}

// ---------------------------------------------------------------------------
extern "C" void kernel_launch(void* const* d_in, const int* in_sizes, int n_in,
                              void* d_out, int out_size) {
    const float* x   = (const float*)d_in[0];
    const float* q   = (const float*)d_in[1];
    const float* ref = (const float*)d_in[2];
    const float* wq  = (const float*)d_in[3];
    const float* bq  = (const float*)d_in[4];
    const float* wk  = (const float*)d_in[5];
    const float* bk  = (const float*)d_in[6];
    const float* wv  = (const float*)d_in[7];
    const float* bv  = (const float*)d_in[8];
    float* out = (float*)d_out;

    (void)in_sizes; (void)n_in; (void)out_size;

    pack_wF_kernel<<<dim3(32, 2), 512>>>(wq, wv);
    pack_wkF_kernel<<<256, 64>>>(wk);

    cudaFuncSetAttribute(prologue_kernel,
                         cudaFuncAttributeMaxDynamicSharedMemorySize, PROJ_SMEM);
    prologue_kernel<<<GRID1, 512, PROJ_SMEM>>>(x, q, bq, bk);

    cudaFuncSetAttribute(deform_attn_kernel,
                         cudaFuncAttributeMaxDynamicSharedMemorySize, SMEM_BYTES);
    deform_attn_kernel<<<dim3(Q_ / TQ, B_), 512, SMEM_BYTES>>>(ref);

    cudaFuncSetAttribute(out_kernel,
                         cudaFuncAttributeMaxDynamicSharedMemorySize, OUT_SMEM);
    out_kernel<<<(B_ * Q_) / MB, 512, OUT_SMEM>>>(bv, out);
}